// round 1
// baseline (speedup 1.0000x reference)
#include <cuda_runtime.h>
#include <math.h>

// Problem constants
#define B_    4
#define H_    768
#define L_    1024
#define N_    4096          // B_*L_
#define M4_   3072          // 4*H_
#define NINP_ 512
#define KC_   1536          // stacked conv K  ([h(t-1); h(t)])
#define KI_   1024          // stacked inject K ([x(t-1); x(t)])
#define NOUT_ 256
#define NLAYER_ 10

// Scratch (device globals; no allocation allowed)
__device__ float g_us[M4_ * N_];     // pre-activation from inject conv (+ both biases)
__device__ float g_h0[H_ * N_];
__device__ float g_h1[H_ * N_];
__device__ float g_c0[H_ * N_];
__device__ float g_c1[H_ * N_];
__device__ float g_Wc[KC_ * M4_];    // repacked conv weights, [kr][o], kr = tap*768 + i
__device__ float g_Wi[KI_ * M4_];    // repacked inject weights, [kr][o], kr = tap*512 + i

// ---------------------------------------------------------------------------
// Weight repack: conv_w[o][i][k] (k innermost) -> g_Wc[(k*H + i)*M4 + o]
// ---------------------------------------------------------------------------
__global__ void repack_conv(const float* __restrict__ conv_w) {
    int idx = blockIdx.x * blockDim.x + threadIdx.x;
    if (idx >= KC_ * M4_) return;
    int kr = idx / M4_;
    int o  = idx - kr * M4_;
    int tap = (kr >= H_) ? 1 : 0;
    int i = kr - tap * H_;
    g_Wc[idx] = conv_w[o * (H_ * 2) + i * 2 + tap];
}

__global__ void repack_inj(const float* __restrict__ inject_w) {
    int idx = blockIdx.x * blockDim.x + threadIdx.x;
    if (idx >= KI_ * M4_) return;
    int kr = idx / M4_;
    int o  = idx - kr * M4_;
    int tap = (kr >= NINP_) ? 1 : 0;
    int i = kr - tap * NINP_;
    g_Wi[idx] = inject_w[o * (NINP_ * 2) + i * 2 + tap];
}

__global__ void zero_hc() {
    int idx = blockIdx.x * blockDim.x + threadIdx.x;
    if (idx < H_ * N_) { g_h0[idx] = 0.0f; g_c0[idx] = 0.0f; }
}

// ---------------------------------------------------------------------------
// Inject GEMM: g_us[o][n] = inject_b[o] + conv_b[o]
//                         + sum_i  w[o,i,0]*X[b,i,t-1] + w[o,i,1]*X[b,i,t]
// Tile: 4 gates x 32 rows x 128 cols, BK=16, 256 threads (16x16), 2x8/thr/gate
// ---------------------------------------------------------------------------
__global__ __launch_bounds__(256, 2)
void inject_gemm(const float* __restrict__ X,
                 const float* __restrict__ inject_b,
                 const float* __restrict__ conv_b) {
    const int n0 = blockIdx.x * 128;
    const int m0 = blockIdx.y * 32;
    const int tid = threadIdx.x;
    const int tn = tid & 15;
    const int tm = tid >> 4;

    __shared__ float Wsh[4][16][32];
    __shared__ float Bsh[16][128];

    float acc[4][2][8];
#pragma unroll
    for (int g = 0; g < 4; g++)
#pragma unroll
        for (int a = 0; a < 2; a++)
#pragma unroll
            for (int x = 0; x < 8; x++) acc[g][a][x] = 0.0f;

    for (int k0 = 0; k0 < KI_; k0 += 16) {
#pragma unroll
        for (int j = 0; j < 8; j++) {
            int idx = tid + j * 256;          // 0..2047
            int g  = idx >> 9;
            int r  = idx & 511;
            int kk = r >> 5;
            int m  = r & 31;
            Wsh[g][kk][m] = g_Wi[(k0 + kk) * M4_ + g * H_ + m0 + m];
        }
#pragma unroll
        for (int j = 0; j < 8; j++) {
            int idx = tid + j * 256;
            int kk = idx >> 7;
            int nn = idx & 127;
            int kr = k0 + kk;
            int n  = n0 + nn;
            int t  = n & (L_ - 1);
            int b  = n >> 10;
            float v;
            if (kr < NINP_) {                 // tap 0: x[t-1], zero-padded
                v = (t == 0) ? 0.0f : X[(b * NINP_ + kr) * L_ + t - 1];
            } else {                          // tap 1: x[t]
                v = X[(b * NINP_ + (kr - NINP_)) * L_ + t];
            }
            Bsh[kk][nn] = v;
        }
        __syncthreads();
#pragma unroll
        for (int kk = 0; kk < 16; kk++) {
            float wv0[4], wv1[4], bv[8];
#pragma unroll
            for (int g = 0; g < 4; g++) {
                wv0[g] = Wsh[g][kk][tm * 2];
                wv1[g] = Wsh[g][kk][tm * 2 + 1];
            }
#pragma unroll
            for (int x = 0; x < 8; x++) bv[x] = Bsh[kk][tn * 8 + x];
#pragma unroll
            for (int g = 0; g < 4; g++)
#pragma unroll
                for (int x = 0; x < 8; x++) {
                    acc[g][0][x] += wv0[g] * bv[x];
                    acc[g][1][x] += wv1[g] * bv[x];
                }
        }
        __syncthreads();
    }

#pragma unroll
    for (int g = 0; g < 4; g++)
#pragma unroll
        for (int mi = 0; mi < 2; mi++) {
            int row = g * H_ + m0 + tm * 2 + mi;
            float bias = inject_b[row] + conv_b[row];
#pragma unroll
            for (int x = 0; x < 8; x++)
                g_us[row * N_ + n0 + tn * 8 + x] = acc[g][mi][x] + bias;
        }
}

// ---------------------------------------------------------------------------
// Layer: pre[g*H+m][n] = us[...] + sum_i W0*h[i][n-1] + W1*h[i][n]   (z0h at t==0)
// then LSTM-ish gating with c_prev[m][n-1] (z0c at t==0). Fused epilogue.
// ---------------------------------------------------------------------------
__global__ __launch_bounds__(256, 2)
void layer_kernel(const float* __restrict__ z0, int rd) {
    const float* __restrict__ hp = rd ? g_h1 : g_h0;
    const float* __restrict__ cp = rd ? g_c1 : g_c0;
    float* __restrict__ hn = rd ? g_h0 : g_h1;
    float* __restrict__ cn = rd ? g_c0 : g_c1;

    const int n0 = blockIdx.x * 128;
    const int m0 = blockIdx.y * 32;
    const int tid = threadIdx.x;
    const int tn = tid & 15;
    const int tm = tid >> 4;

    __shared__ float Wsh[4][16][32];
    __shared__ float Bsh[16][128];

    float acc[4][2][8];
#pragma unroll
    for (int g = 0; g < 4; g++)
#pragma unroll
        for (int a = 0; a < 2; a++)
#pragma unroll
            for (int x = 0; x < 8; x++) acc[g][a][x] = 0.0f;

    for (int k0 = 0; k0 < KC_; k0 += 16) {
#pragma unroll
        for (int j = 0; j < 8; j++) {
            int idx = tid + j * 256;
            int g  = idx >> 9;
            int r  = idx & 511;
            int kk = r >> 5;
            int m  = r & 31;
            Wsh[g][kk][m] = g_Wc[(k0 + kk) * M4_ + g * H_ + m0 + m];
        }
#pragma unroll
        for (int j = 0; j < 8; j++) {
            int idx = tid + j * 256;
            int kk = idx >> 7;
            int nn = idx & 127;
            int kr = k0 + kk;
            int n  = n0 + nn;
            int t  = n & (L_ - 1);
            float v;
            if (kr < H_) {                    // tap 0: h[t-1], z0h at t==0
                if (t == 0) v = z0[(n >> 10) * (2 * H_) + kr];
                else        v = hp[kr * N_ + n - 1];
            } else {                          // tap 1: h[t]
                v = hp[(kr - H_) * N_ + n];
            }
            Bsh[kk][nn] = v;
        }
        __syncthreads();
#pragma unroll
        for (int kk = 0; kk < 16; kk++) {
            float wv0[4], wv1[4], bv[8];
#pragma unroll
            for (int g = 0; g < 4; g++) {
                wv0[g] = Wsh[g][kk][tm * 2];
                wv1[g] = Wsh[g][kk][tm * 2 + 1];
            }
#pragma unroll
            for (int x = 0; x < 8; x++) bv[x] = Bsh[kk][tn * 8 + x];
#pragma unroll
            for (int g = 0; g < 4; g++)
#pragma unroll
                for (int x = 0; x < 8; x++) {
                    acc[g][0][x] += wv0[g] * bv[x];
                    acc[g][1][x] += wv1[g] * bv[x];
                }
        }
        __syncthreads();
    }

    // Epilogue: gate + write new h, c. Gate order from split: i, o, g, f.
#pragma unroll
    for (int mi = 0; mi < 2; mi++) {
        int row = m0 + tm * 2 + mi;           // channel in [0, H)
#pragma unroll
        for (int x = 0; x < 8; x++) {
            int n = n0 + tn * 8 + x;
            int t = n & (L_ - 1);
            int b = n >> 10;
            float pi = acc[0][mi][x] + g_us[(0 * H_ + row) * N_ + n];
            float po = acc[1][mi][x] + g_us[(1 * H_ + row) * N_ + n];
            float pg = acc[2][mi][x] + g_us[(2 * H_ + row) * N_ + n];
            float pf = acc[3][mi][x] + g_us[(3 * H_ + row) * N_ + n];
            float si = 1.0f / (1.0f + __expf(-pi));
            float so = 1.0f / (1.0f + __expf(-po));
            float sf = 1.0f / (1.0f + __expf(-pf));
            float tg = tanhf(pg);
            float cprev = (t == 0) ? z0[b * (2 * H_) + H_ + row]
                                   : cp[row * N_ + n - 1];
            float c = sf * cprev + si * tg;
            float h = so * tanhf(c);
            hn[row * N_ + n] = h;
            cn[row * N_ + n] = c;
        }
    }
}

// ---------------------------------------------------------------------------
// Outputs: out (B, L, NOUT) = h[H-NOUT:H] transposed; then z0_out (B, 2H, 1).
// Final state lives in buffers 0 (10 layers -> even parity).
// ---------------------------------------------------------------------------
__global__ void write_out(float* __restrict__ out) {
    int idx = blockIdx.x * blockDim.x + threadIdx.x;
    const int total = B_ * L_ * NOUT_;
    if (idx < total) {
        int j = idx & (NOUT_ - 1);
        int t = (idx >> 8) & (L_ - 1);
        int b = idx >> 18;
        out[idx] = g_h0[(H_ - NOUT_ + j) * N_ + b * L_ + t];
    }
    if (idx < B_ * 2 * H_) {
        int ch = idx % (2 * H_);
        int b  = idx / (2 * H_);
        float v = (ch < H_) ? g_h0[ch * N_ + b * L_ + (L_ - 1)]
                            : g_c0[(ch - H_) * N_ + b * L_ + (L_ - 1)];
        out[total + idx] = v;
    }
}

// ---------------------------------------------------------------------------
extern "C" void kernel_launch(void* const* d_in, const int* in_sizes, int n_in,
                              void* d_out, int out_size) {
    const float* X        = (const float*)d_in[0];
    const float* z0       = (const float*)d_in[1];
    const float* inject_w = (const float*)d_in[2];
    const float* inject_b = (const float*)d_in[3];
    const float* conv_w   = (const float*)d_in[4];
    const float* conv_b   = (const float*)d_in[5];
    float* out = (float*)d_out;

    repack_conv<<<(KC_ * M4_ + 255) / 256, 256>>>(conv_w);
    repack_inj<<<(KI_ * M4_ + 255) / 256, 256>>>(inject_w);
    zero_hc<<<(H_ * N_ + 255) / 256, 256>>>();

    inject_gemm<<<dim3(N_ / 128, H_ / 32), 256>>>(X, inject_b, conv_b);

    for (int l = 0; l < NLAYER_; l++)
        layer_kernel<<<dim3(N_ / 128, H_ / 32), 256>>>(z0, l & 1);

    write_out<<<(B_ * L_ * NOUT_ + 255) / 256, 256>>>(out);
}

// round 3
// speedup vs baseline: 3.2486x; 3.2486x over previous
#include <cuda_runtime.h>
#include <math.h>
#include <cstdint>

// Problem constants
#define B_    4
#define H_    768
#define L_    1024
#define N_    4096          // B_*L_
#define M4_   3072          // 4*H_
#define NINP_ 512
#define KC_   1536          // stacked conv K  ([h(t-1); h(t)])
#define KI_   1024          // stacked inject K ([x(t-1); x(t)])
#define NOUT_ 256
#define NLAYER_ 10

// Scratch (device globals; no allocation allowed)
__device__ float g_us[N_ * M4_];     // us_T[n][m]  (time-major pre-activation + biases)
__device__ float g_pre[N_ * M4_];    // conv GEMM output, pre[n][m]
__device__ float g_h0[N_ * H_];      // h[n][c] time-major
__device__ float g_h1[N_ * H_];
__device__ float g_c0[N_ * H_];
__device__ float g_c1[N_ * H_];
__device__ float g_Wc[M4_ * KC_];    // conv weights [m][k], k = tap*768 + i  (K contiguous)
__device__ float g_Wi[KI_ * M4_];    // inject weights [kr][o]

// ===========================================================================
// Small helpers
// ===========================================================================
__device__ __forceinline__ uint32_t smem_u32(const void* p) {
    uint32_t a;
    asm("{ .reg .u64 t; cvta.to.shared.u64 t, %1; cvt.u32.u64 %0, t; }"
        : "=r"(a) : "l"(p));
    return a;
}

__device__ __forceinline__ void cp_async16(uint32_t dst, const void* src) {
    asm volatile("cp.async.cg.shared.global [%0], [%1], 16;" :: "r"(dst), "l"(src));
}
__device__ __forceinline__ void cp_commit() {
    asm volatile("cp.async.commit_group;");
}
template <int Npend>
__device__ __forceinline__ void cp_wait() {
    asm volatile("cp.async.wait_group %0;" :: "n"(Npend));
}

__device__ __forceinline__ uint32_t f2tf32(float f) {
    uint32_t r;
    asm("cvt.rna.tf32.f32 %0, %1;" : "=r"(r) : "f"(f));
    return r;
}

__device__ __forceinline__ void mma_tf32(float& c0, float& c1, float& c2, float& c3,
                                         uint32_t a0, uint32_t a1, uint32_t a2, uint32_t a3,
                                         uint32_t b0, uint32_t b1) {
    asm volatile(
        "mma.sync.aligned.m16n8k8.row.col.f32.tf32.tf32.f32 "
        "{%0,%1,%2,%3}, {%4,%5,%6,%7}, {%8,%9}, {%0,%1,%2,%3};"
        : "+f"(c0), "+f"(c1), "+f"(c2), "+f"(c3)
        : "r"(a0), "r"(a1), "r"(a2), "r"(a3), "r"(b0), "r"(b1));
}

// ===========================================================================
// Weight repacks
// ===========================================================================
__global__ void repack_conv(const float* __restrict__ conv_w) {
    int idx = blockIdx.x * blockDim.x + threadIdx.x;
    if (idx >= M4_ * KC_) return;
    int m = idx / KC_;
    int k = idx - m * KC_;
    int tap = (k >= H_) ? 1 : 0;
    int i = k - tap * H_;
    g_Wc[idx] = conv_w[m * (H_ * 2) + i * 2 + tap];
}

__global__ void repack_inj(const float* __restrict__ inject_w) {
    int idx = blockIdx.x * blockDim.x + threadIdx.x;
    if (idx >= KI_ * M4_) return;
    int kr = idx / M4_;
    int o  = idx - kr * M4_;
    int tap = (kr >= NINP_) ? 1 : 0;
    int i = kr - tap * NINP_;
    g_Wi[idx] = inject_w[o * (NINP_ * 2) + i * 2 + tap];
}

__global__ void zero_hc() {
    int idx = blockIdx.x * blockDim.x + threadIdx.x;
    if (idx < H_ * N_) { g_h0[idx] = 0.0f; g_c0[idx] = 0.0f; }
}

// ===========================================================================
// Inject GEMM (fp32 CUDA cores, verified math) -> writes us_T[n][m]
// ===========================================================================
__global__ __launch_bounds__(256, 2)
void inject_gemm(const float* __restrict__ X,
                 const float* __restrict__ inject_b,
                 const float* __restrict__ conv_b) {
    const int n0 = blockIdx.x * 128;
    const int m0 = blockIdx.y * 32;
    const int tid = threadIdx.x;
    const int tn = tid & 15;
    const int tm = tid >> 4;

    __shared__ float Wsh[4][16][32];
    __shared__ float Bsh[16][128];

    float acc[4][2][8];
#pragma unroll
    for (int g = 0; g < 4; g++)
#pragma unroll
        for (int a = 0; a < 2; a++)
#pragma unroll
            for (int x = 0; x < 8; x++) acc[g][a][x] = 0.0f;

    for (int k0 = 0; k0 < KI_; k0 += 16) {
#pragma unroll
        for (int j = 0; j < 8; j++) {
            int idx = tid + j * 256;
            int g  = idx >> 9;
            int r  = idx & 511;
            int kk = r >> 5;
            int m  = r & 31;
            Wsh[g][kk][m] = g_Wi[(k0 + kk) * M4_ + g * H_ + m0 + m];
        }
#pragma unroll
        for (int j = 0; j < 8; j++) {
            int idx = tid + j * 256;
            int kk = idx >> 7;
            int nn = idx & 127;
            int kr = k0 + kk;
            int n  = n0 + nn;
            int t  = n & (L_ - 1);
            int b  = n >> 10;
            float v;
            if (kr < NINP_) {
                v = (t == 0) ? 0.0f : X[(b * NINP_ + kr) * L_ + t - 1];
            } else {
                v = X[(b * NINP_ + (kr - NINP_)) * L_ + t];
            }
            Bsh[kk][nn] = v;
        }
        __syncthreads();
#pragma unroll
        for (int kk = 0; kk < 16; kk++) {
            float wv0[4], wv1[4], bv[8];
#pragma unroll
            for (int g = 0; g < 4; g++) {
                wv0[g] = Wsh[g][kk][tm * 2];
                wv1[g] = Wsh[g][kk][tm * 2 + 1];
            }
#pragma unroll
            for (int x = 0; x < 8; x++) bv[x] = Bsh[kk][tn * 8 + x];
#pragma unroll
            for (int g = 0; g < 4; g++)
#pragma unroll
                for (int x = 0; x < 8; x++) {
                    acc[g][0][x] += wv0[g] * bv[x];
                    acc[g][1][x] += wv1[g] * bv[x];
                }
        }
        __syncthreads();
    }

#pragma unroll
    for (int g = 0; g < 4; g++)
#pragma unroll
        for (int mi = 0; mi < 2; mi++) {
            int row = g * H_ + m0 + tm * 2 + mi;
            float bias = inject_b[row] + conv_b[row];
#pragma unroll
            for (int x = 0; x < 8; x++)
                g_us[(size_t)(n0 + tn * 8 + x) * M4_ + row] = acc[g][mi][x] + bias;
        }
}

// ===========================================================================
// Layer conv GEMM via mma.sync tf32:
//   pre[n][m] = sum_k A[n,k] * Wc[m,k]
//   A[n, k<768]  = h_prev[n-1][k]   (z0h at t==0)
//   A[n, k>=768] = h_prev[n][k-768]
// Block tile 128(n) x 128(m), BK=16, 4-stage cp.async pipeline.
// 8 warps as 2(n) x 4(m); warp tile 64x32.
// ===========================================================================
#define BK      16
#define KSTRIDE 20                      // padded row stride in floats
#define STG_A   (128 * KSTRIDE)         // floats per A stage
#define STG_SZ  (2 * 128 * KSTRIDE)     // floats per stage (A+B)
#define NSTAGE  4
#define NKT     (KC_ / BK)              // 96

__global__ __launch_bounds__(256, 1)
void layer_gemm(const float* __restrict__ z0, int rd) {
    extern __shared__ float smf[];
    const float* __restrict__ hp = rd ? g_h1 : g_h0;

    const int tid  = threadIdx.x;
    const int wid  = tid >> 5;
    const int lane = tid & 31;
    const int grp  = lane >> 2;
    const int qid  = lane & 3;
    const int n0   = blockIdx.x * 128;
    const int m0   = blockIdx.y * 128;

    const int wn = (wid >> 2) * 64;     // warp n offset in tile
    const int wm = (wid & 3) * 32;      // warp m offset in tile

    const uint32_t sbase = smem_u32(smf);

    // per-thread load slots: A tile is 512 float4 (2 per thread), B same
    const int arow = (tid * 2) >> 2;        // unused helper form; compute inline below

    // -------- pipeline prologue: issue stages 0..2 --------
#pragma unroll 1
    for (int s = 0; s < NSTAGE - 1; s++) {
        const int k0 = s * BK;
        float* Abuf = smf + (s % NSTAGE) * STG_SZ;
        float* Bbuf = Abuf + STG_A;
#pragma unroll
        for (int j = 0; j < 2; j++) {
            int idx = tid + j * 256;        // 0..511
            int r  = idx >> 2;
            int c4 = idx & 3;
            // A
            {
                int n = n0 + r;
                int t = n & (L_ - 1);
                int b = n >> 10;
                const float* src;
                if (k0 < H_) {
                    src = (t == 0) ? (z0 + b * (2 * H_) + k0 + c4 * 4)
                                   : (hp + (size_t)(n - 1) * H_ + k0 + c4 * 4);
                } else {
                    src = hp + (size_t)n * H_ + (k0 - H_) + c4 * 4;
                }
                cp_async16(sbase + (uint32_t)((Abuf - smf) + r * KSTRIDE + c4 * 4) * 4, src);
            }
            // B
            {
                const float* src = g_Wc + (size_t)(m0 + r) * KC_ + k0 + c4 * 4;
                cp_async16(sbase + (uint32_t)((Bbuf - smf) + r * KSTRIDE + c4 * 4) * 4, src);
            }
        }
        cp_commit();
    }

    float acc[4][4][4];                 // [n-frag][m-frag][c0..c3]
#pragma unroll
    for (int i = 0; i < 4; i++)
#pragma unroll
        for (int j = 0; j < 4; j++)
#pragma unroll
            for (int e = 0; e < 4; e++) acc[i][j][e] = 0.0f;

    // -------- main loop --------
#pragma unroll 1
    for (int kt = 0; kt < NKT; kt++) {
        cp_wait<NSTAGE - 2>();
        __syncthreads();

        // issue stage kt + NSTAGE-1
        const int sf = kt + NSTAGE - 1;
        if (sf < NKT) {
            const int k0 = sf * BK;
            float* Abuf = smf + (sf % NSTAGE) * STG_SZ;
            float* Bbuf = Abuf + STG_A;
#pragma unroll
            for (int j = 0; j < 2; j++) {
                int idx = tid + j * 256;
                int r  = idx >> 2;
                int c4 = idx & 3;
                {
                    int n = n0 + r;
                    int t = n & (L_ - 1);
                    int b = n >> 10;
                    const float* src;
                    if (k0 < H_) {
                        src = (t == 0) ? (z0 + b * (2 * H_) + k0 + c4 * 4)
                                       : (hp + (size_t)(n - 1) * H_ + k0 + c4 * 4);
                    } else {
                        src = hp + (size_t)n * H_ + (k0 - H_) + c4 * 4;
                    }
                    cp_async16(sbase + (uint32_t)((Abuf - smf) + r * KSTRIDE + c4 * 4) * 4, src);
                }
                {
                    const float* src = g_Wc + (size_t)(m0 + r) * KC_ + k0 + c4 * 4;
                    cp_async16(sbase + (uint32_t)((Bbuf - smf) + r * KSTRIDE + c4 * 4) * 4, src);
                }
            }
        }
        cp_commit();

        // compute on buffer kt%NSTAGE
        const float* As = smf + (kt % NSTAGE) * STG_SZ;
        const float* Bs = As + STG_A;
#pragma unroll
        for (int ks = 0; ks < BK; ks += 8) {
            uint32_t af[4][4];
            uint32_t bf[4][2];
#pragma unroll
            for (int fi = 0; fi < 4; fi++) {
                int nr = wn + fi * 16 + grp;
                af[fi][0] = f2tf32(As[nr * KSTRIDE + ks + qid]);
                af[fi][1] = f2tf32(As[(nr + 8) * KSTRIDE + ks + qid]);
                af[fi][2] = f2tf32(As[nr * KSTRIDE + ks + 4 + qid]);
                af[fi][3] = f2tf32(As[(nr + 8) * KSTRIDE + ks + 4 + qid]);
            }
#pragma unroll
            for (int fj = 0; fj < 4; fj++) {
                int mr = wm + fj * 8 + grp;
                bf[fj][0] = f2tf32(Bs[mr * KSTRIDE + ks + qid]);
                bf[fj][1] = f2tf32(Bs[mr * KSTRIDE + ks + 4 + qid]);
            }
#pragma unroll
            for (int fi = 0; fi < 4; fi++)
#pragma unroll
                for (int fj = 0; fj < 4; fj++)
                    mma_tf32(acc[fi][fj][0], acc[fi][fj][1], acc[fi][fj][2], acc[fi][fj][3],
                             af[fi][0], af[fi][1], af[fi][2], af[fi][3],
                             bf[fj][0], bf[fj][1]);
        }
    }

    // -------- epilogue: store pre[n][m] --------
#pragma unroll
    for (int fi = 0; fi < 4; fi++) {
#pragma unroll
        for (int fj = 0; fj < 4; fj++) {
            int n1 = n0 + wn + fi * 16 + grp;
            int m  = m0 + wm + fj * 8 + qid * 2;
            float2 v0 = make_float2(acc[fi][fj][0], acc[fi][fj][1]);
            float2 v1 = make_float2(acc[fi][fj][2], acc[fi][fj][3]);
            *(float2*)(g_pre + (size_t)n1 * M4_ + m)       = v0;
            *(float2*)(g_pre + (size_t)(n1 + 8) * M4_ + m) = v1;
        }
    }
}

// ===========================================================================
// Gating: per (n, ch float4): pre + us -> LSTM update, write h, c
// ===========================================================================
__global__ __launch_bounds__(256)
void gating(const float* __restrict__ z0, int rd) {
    const float* __restrict__ cp = rd ? g_c1 : g_c0;
    float* __restrict__ hn = rd ? g_h0 : g_h1;
    float* __restrict__ cn = rd ? g_c0 : g_c1;

    int idx = blockIdx.x * blockDim.x + threadIdx.x;   // over N_ * H_/4
    if (idx >= N_ * (H_ / 4)) return;
    int n  = idx / (H_ / 4);
    int c4 = (idx - n * (H_ / 4)) * 4;
    int t = n & (L_ - 1);
    int b = n >> 10;

    const size_t base = (size_t)n * M4_;
    float4 pi4 = *(const float4*)(g_pre + base + 0 * H_ + c4);
    float4 po4 = *(const float4*)(g_pre + base + 1 * H_ + c4);
    float4 pg4 = *(const float4*)(g_pre + base + 2 * H_ + c4);
    float4 pf4 = *(const float4*)(g_pre + base + 3 * H_ + c4);
    float4 ui4 = *(const float4*)(g_us + base + 0 * H_ + c4);
    float4 uo4 = *(const float4*)(g_us + base + 1 * H_ + c4);
    float4 ug4 = *(const float4*)(g_us + base + 2 * H_ + c4);
    float4 uf4 = *(const float4*)(g_us + base + 3 * H_ + c4);
    float4 cpv;
    if (t == 0) cpv = *(const float4*)(z0 + b * (2 * H_) + H_ + c4);
    else        cpv = *(const float4*)(cp + (size_t)(n - 1) * H_ + c4);

    const float* pip = (const float*)&pi4;
    const float* pop = (const float*)&po4;
    const float* pgp = (const float*)&pg4;
    const float* pfp = (const float*)&pf4;
    const float* uip = (const float*)&ui4;
    const float* uop = (const float*)&uo4;
    const float* ugp = (const float*)&ug4;
    const float* ufp = (const float*)&uf4;
    const float* cpl = (const float*)&cpv;

    float4 hv, cv;
    float* hvp = (float*)&hv;
    float* cvp = (float*)&cv;
#pragma unroll
    for (int e = 0; e < 4; e++) {
        float pi = pip[e] + uip[e];
        float po = pop[e] + uop[e];
        float pg = pgp[e] + ugp[e];
        float pf = pfp[e] + ufp[e];
        float si = 1.0f / (1.0f + __expf(-pi));
        float so = 1.0f / (1.0f + __expf(-po));
        float sf = 1.0f / (1.0f + __expf(-pf));
        float tg = tanhf(pg);
        float c = sf * cpl[e] + si * tg;
        float h = so * tanhf(c);
        hvp[e] = h;
        cvp[e] = c;
    }
    *(float4*)(hn + (size_t)n * H_ + c4) = hv;
    *(float4*)(cn + (size_t)n * H_ + c4) = cv;
}

// ===========================================================================
// Outputs: out (B, L, NOUT) then z0_out (B, 2H, 1). Final state in buffers 0.
// ===========================================================================
__global__ void write_out(float* __restrict__ out) {
    int idx = blockIdx.x * blockDim.x + threadIdx.x;
    const int total = B_ * L_ * NOUT_;
    if (idx < total) {
        int j = idx & (NOUT_ - 1);
        int n = idx >> 8;
        out[idx] = g_h0[(size_t)n * H_ + (H_ - NOUT_) + j];
    }
    if (idx < B_ * 2 * H_) {
        int ch = idx % (2 * H_);
        int b  = idx / (2 * H_);
        int n  = b * L_ + (L_ - 1);
        float v = (ch < H_) ? g_h0[(size_t)n * H_ + ch]
                            : g_c0[(size_t)n * H_ + (ch - H_)];
        out[total + idx] = v;
    }
}

// ===========================================================================
extern "C" void kernel_launch(void* const* d_in, const int* in_sizes, int n_in,
                              void* d_out, int out_size) {
    const float* X        = (const float*)d_in[0];
    const float* z0       = (const float*)d_in[1];
    const float* inject_w = (const float*)d_in[2];
    const float* inject_b = (const float*)d_in[3];
    const float* conv_w   = (const float*)d_in[4];
    const float* conv_b   = (const float*)d_in[5];
    float* out = (float*)d_out;

    const int smem_bytes = NSTAGE * STG_SZ * sizeof(float);   // 4*5120*4 = 81920
    static int configured = 0;
    cudaFuncSetAttribute(layer_gemm, cudaFuncAttributeMaxDynamicSharedMemorySize, smem_bytes);

    repack_conv<<<(M4_ * KC_ + 255) / 256, 256>>>(conv_w);
    repack_inj<<<(KI_ * M4_ + 255) / 256, 256>>>(inject_w);
    zero_hc<<<(H_ * N_ + 255) / 256, 256>>>();

    inject_gemm<<<dim3(N_ / 128, H_ / 32), 256>>>(X, inject_b, conv_b);

    for (int l = 0; l < NLAYER_; l++) {
        layer_gemm<<<dim3(N_ / 128, M4_ / 128), 256, smem_bytes>>>(z0, l & 1);
        gating<<<(N_ * (H_ / 4) + 255) / 256, 256>>>(z0, l & 1);
    }

    write_out<<<(B_ * L_ * NOUT_ + 255) / 256, 256>>>(out);
}

// round 4
// speedup vs baseline: 3.6707x; 1.1299x over previous
#include <cuda_runtime.h>
#include <math.h>
#include <cstdint>

// Problem constants
#define B_    4
#define H_    768
#define L_    1024
#define N_    4096          // B_*L_
#define M4_   3072          // 4*H_
#define NINP_ 512
#define KC_   1536          // conv K  ([h(t-1); h(t)])
#define KI_   1024          // inject K ([x(t-1); x(t)])
#define NOUT_ 256
#define NLAYER_ 10

// Scratch (device globals; no allocation allowed)
__device__ float g_us[(size_t)N_ * M4_]; // us[n][m] plain order (gate*H + ch), biases folded
__device__ float g_h0[(size_t)N_ * H_];  // h[n][c] time-major
__device__ float g_h1[(size_t)N_ * H_];
__device__ float g_c0[(size_t)N_ * H_];
__device__ float g_c1[(size_t)N_ * H_];
__device__ float g_Wc2[(size_t)M4_ * KC_]; // conv W, gate-interleaved rows, K-contig
__device__ float g_Wi2[(size_t)M4_ * KI_]; // inject W, plain rows, K-contig
__device__ float g_Xt[(size_t)N_ * NINP_]; // X transposed to [n][i]
__device__ float g_bias[M4_];              // inject_b + conv_b

// ===========================================================================
// Helpers
// ===========================================================================
__device__ __forceinline__ uint32_t smem_u32(const void* p) {
    uint32_t a;
    asm("{ .reg .u64 t; cvta.to.shared.u64 t, %1; cvt.u32.u64 %0, t; }"
        : "=r"(a) : "l"(p));
    return a;
}
__device__ __forceinline__ void cp_async16(uint32_t dst, const void* src) {
    asm volatile("cp.async.cg.shared.global [%0], [%1], 16;" :: "r"(dst), "l"(src));
}
__device__ __forceinline__ void cp_async16_zero(uint32_t dst, const void* src) {
    // src-size = 0 -> full 16B zero-fill
    asm volatile("cp.async.cg.shared.global [%0], [%1], 16, 0;" :: "r"(dst), "l"(src));
}
__device__ __forceinline__ void cp_commit() {
    asm volatile("cp.async.commit_group;");
}
template <int Npend>
__device__ __forceinline__ void cp_wait() {
    asm volatile("cp.async.wait_group %0;" :: "n"(Npend));
}
__device__ __forceinline__ uint32_t f2tf32(float f) {
    uint32_t r;
    asm("cvt.rna.tf32.f32 %0, %1;" : "=r"(r) : "f"(f));
    return r;
}
__device__ __forceinline__ void mma_tf32(float& c0, float& c1, float& c2, float& c3,
                                         uint32_t a0, uint32_t a1, uint32_t a2, uint32_t a3,
                                         uint32_t b0, uint32_t b1) {
    asm volatile(
        "mma.sync.aligned.m16n8k8.row.col.f32.tf32.tf32.f32 "
        "{%0,%1,%2,%3}, {%4,%5,%6,%7}, {%8,%9}, {%0,%1,%2,%3};"
        : "+f"(c0), "+f"(c1), "+f"(c2), "+f"(c3)
        : "r"(a0), "r"(a1), "r"(a2), "r"(a3), "r"(b0), "r"(b1));
}

// ===========================================================================
// Repacks / transpose / init
// ===========================================================================
// conv weights: row m' = y*128 + g*32 + cl  <->  channel c = y*32+cl, gate g
__global__ void repack_conv2(const float* __restrict__ conv_w) {
    int idx = blockIdx.x * blockDim.x + threadIdx.x;
    if (idx >= M4_ * KC_) return;
    int mp = idx / KC_;
    int k  = idx - mp * KC_;
    int y  = mp >> 7;
    int rr = mp & 127;
    int g  = rr >> 5;
    int cl = rr & 31;
    int m  = g * H_ + y * 32 + cl;
    int tap = (k >= H_) ? 1 : 0;
    int i = k - tap * H_;
    g_Wc2[idx] = conv_w[m * (H_ * 2) + i * 2 + tap];
}

__global__ void repack_inj2(const float* __restrict__ inject_w,
                            const float* __restrict__ inject_b,
                            const float* __restrict__ conv_b) {
    int idx = blockIdx.x * blockDim.x + threadIdx.x;
    if (idx >= M4_ * KI_) return;
    int m = idx / KI_;
    int k = idx - m * KI_;
    int tap = (k >= NINP_) ? 1 : 0;
    int i = k - tap * NINP_;
    g_Wi2[idx] = inject_w[m * (NINP_ * 2) + i * 2 + tap];
    if (k == 0) g_bias[m] = inject_b[m] + conv_b[m];
}

__global__ void transpose_x(const float* __restrict__ X) {
    __shared__ float tile[32][33];
    int b  = blockIdx.z;
    int i0 = blockIdx.y * 32;
    int t0 = blockIdx.x * 32;
    int tx = threadIdx.x, ty = threadIdx.y;
#pragma unroll
    for (int j = 0; j < 32; j += 8)
        tile[ty + j][tx] = X[(size_t)(b * NINP_ + i0 + ty + j) * L_ + t0 + tx];
    __syncthreads();
#pragma unroll
    for (int j = 0; j < 32; j += 8)
        g_Xt[(size_t)(b * L_ + t0 + ty + j) * NINP_ + i0 + tx] = tile[tx][ty + j];
}

__global__ void zero_hc() {
    int idx = blockIdx.x * blockDim.x + threadIdx.x;
    if (idx < H_ * N_) { g_h0[idx] = 0.0f; g_c0[idx] = 0.0f; }
}

// ===========================================================================
// Fused GEMM (tf32 mma.sync, 4-stage cp.async), 128(n) x 128(m) x BK=16.
// INJECT=true : A = stacked X taps, B = g_Wi2 (plain rows) -> g_us + bias
// INJECT=false: A = stacked h taps, B = g_Wc2 (gate-interleaved) -> fused gating
// ===========================================================================
#define BK      16
#define KSTRIDE 20
#define STG_A   (128 * KSTRIDE)
#define STG_SZ  (2 * 128 * KSTRIDE)
#define NSTAGE  4
#define PS      132                      // pre_s row stride (floats)

template <int KTOT, bool INJECT>
__global__ __launch_bounds__(256, 1)
void gemm_fused(const float* __restrict__ z0, int rd) {
    extern __shared__ float smf[];
    constexpr int KHALF = KTOT / 2;
    constexpr int NKT = KTOT / BK;

    const float* __restrict__ Asrc = INJECT ? g_Xt : (rd ? g_h1 : g_h0);
    const float* __restrict__ Bw   = INJECT ? g_Wi2 : g_Wc2;

    const int tid  = threadIdx.x;
    const int wid  = tid >> 5;
    const int lane = tid & 31;
    const int grp  = lane >> 2;
    const int qid  = lane & 3;
    const int n0   = blockIdx.x * 128;
    const int m0   = blockIdx.y * 128;

    const int wn = (wid >> 2) * 64;
    const int wm = (wid & 3) * 32;

    const uint32_t sbase = smem_u32(smf);

#define LOAD_STAGE(S, K0)                                                        \
    do {                                                                         \
        const int _k0 = (K0);                                                    \
        const uint32_t aoff = ((S) % NSTAGE) * STG_SZ;                           \
        const uint32_t boff = aoff + STG_A;                                      \
        _Pragma("unroll")                                                        \
        for (int j = 0; j < 2; j++) {                                            \
            int idx = tid + j * 256;                                             \
            int r  = idx >> 2;                                                   \
            int c4 = idx & 3;                                                    \
            {                                                                    \
                int n = n0 + r;                                                  \
                int t = n & (L_ - 1);                                            \
                int b = n >> 10;                                                 \
                uint32_t dst = sbase + (aoff + r * KSTRIDE + c4 * 4) * 4;        \
                if (_k0 < KHALF) {                                               \
                    if (t == 0) {                                                \
                        if (INJECT) cp_async16_zero(dst, Asrc);                  \
                        else cp_async16(dst, z0 + b * (2 * H_) + _k0 + c4 * 4);  \
                    } else {                                                     \
                        cp_async16(dst, Asrc + (size_t)(n - 1) * KHALF + _k0 + c4 * 4); \
                    }                                                            \
                } else {                                                         \
                    cp_async16(dst, Asrc + (size_t)n * KHALF + (_k0 - KHALF) + c4 * 4); \
                }                                                                \
            }                                                                    \
            {                                                                    \
                uint32_t dst = sbase + (boff + r * KSTRIDE + c4 * 4) * 4;        \
                cp_async16(dst, Bw + (size_t)(m0 + r) * KTOT + _k0 + c4 * 4);    \
            }                                                                    \
        }                                                                        \
        cp_commit();                                                             \
    } while (0)

    // prologue
#pragma unroll
    for (int s = 0; s < NSTAGE - 1; s++) LOAD_STAGE(s, s * BK);

    float acc[4][4][4];
#pragma unroll
    for (int i = 0; i < 4; i++)
#pragma unroll
        for (int j = 0; j < 4; j++)
#pragma unroll
            for (int e = 0; e < 4; e++) acc[i][j][e] = 0.0f;

#pragma unroll 1
    for (int kt = 0; kt < NKT; kt++) {
        cp_wait<NSTAGE - 2>();
        __syncthreads();

        const int sf = kt + NSTAGE - 1;
        if (sf < NKT) LOAD_STAGE(sf, sf * BK);
        else cp_commit();

        const float* As = smf + (kt % NSTAGE) * STG_SZ;
        const float* Bs = As + STG_A;
#pragma unroll
        for (int ks = 0; ks < BK; ks += 8) {
            uint32_t af[4][4];
            uint32_t bf[4][2];
#pragma unroll
            for (int fi = 0; fi < 4; fi++) {
                int nr = wn + fi * 16 + grp;
                af[fi][0] = f2tf32(As[nr * KSTRIDE + ks + qid]);
                af[fi][1] = f2tf32(As[(nr + 8) * KSTRIDE + ks + qid]);
                af[fi][2] = f2tf32(As[nr * KSTRIDE + ks + 4 + qid]);
                af[fi][3] = f2tf32(As[(nr + 8) * KSTRIDE + ks + 4 + qid]);
            }
#pragma unroll
            for (int fj = 0; fj < 4; fj++) {
                int mr = wm + fj * 8 + grp;
                bf[fj][0] = f2tf32(Bs[mr * KSTRIDE + ks + qid]);
                bf[fj][1] = f2tf32(Bs[mr * KSTRIDE + ks + 4 + qid]);
            }
#pragma unroll
            for (int fi = 0; fi < 4; fi++)
#pragma unroll
                for (int fj = 0; fj < 4; fj++)
                    mma_tf32(acc[fi][fj][0], acc[fi][fj][1], acc[fi][fj][2], acc[fi][fj][3],
                             af[fi][0], af[fi][1], af[fi][2], af[fi][3],
                             bf[fj][0], bf[fj][1]);
        }
    }

    if (INJECT) {
        // store us = acc + bias, plain layout
#pragma unroll
        for (int fi = 0; fi < 4; fi++) {
#pragma unroll
            for (int fj = 0; fj < 4; fj++) {
                int n1 = n0 + wn + fi * 16 + grp;
                int m  = m0 + wm + fj * 8 + qid * 2;
                float b0 = g_bias[m], b1 = g_bias[m + 1];
                *(float2*)(g_us + (size_t)n1 * M4_ + m) =
                    make_float2(acc[fi][fj][0] + b0, acc[fi][fj][1] + b1);
                *(float2*)(g_us + (size_t)(n1 + 8) * M4_ + m) =
                    make_float2(acc[fi][fj][2] + b0, acc[fi][fj][3] + b1);
            }
        }
        return;
    }

    // ---------------- fused gating epilogue (layers only) ----------------
    // stage accumulators in smem: pre_s[n_local][g*32 + cl]
    __syncthreads();                 // all warps done reading stage buffers
    float* pre_s = smf;
#pragma unroll
    for (int fi = 0; fi < 4; fi++) {
#pragma unroll
        for (int fj = 0; fj < 4; fj++) {
            int r0   = wn + fi * 16 + grp;
            int cidx = wm + fj * 8 + qid * 2;
            *(float2*)&pre_s[r0 * PS + cidx] =
                make_float2(acc[fi][fj][0], acc[fi][fj][1]);
            *(float2*)&pre_s[(r0 + 8) * PS + cidx] =
                make_float2(acc[fi][fj][2], acc[fi][fj][3]);
        }
    }
    __syncthreads();

    const float* __restrict__ cpb = rd ? g_c1 : g_c0;
    float* __restrict__ hn = rd ? g_h0 : g_h1;
    float* __restrict__ cn = rd ? g_c0 : g_c1;
    const int chbase = blockIdx.y * 32;
    const int q  = tid & 7;          // float4 group within 32 channels
    const int nl = tid >> 3;         // 0..31

#pragma unroll
    for (int it = 0; it < 4; it++) {
        int n_local = nl + it * 32;
        int n = n0 + n_local;
        int t = n & (L_ - 1);
        int b = n >> 10;
        int ch = chbase + q * 4;

        float4 pi4 = *(const float4*)&pre_s[n_local * PS + 0 * 32 + q * 4];
        float4 po4 = *(const float4*)&pre_s[n_local * PS + 1 * 32 + q * 4];
        float4 pg4 = *(const float4*)&pre_s[n_local * PS + 2 * 32 + q * 4];
        float4 pf4 = *(const float4*)&pre_s[n_local * PS + 3 * 32 + q * 4];
        const size_t ub = (size_t)n * M4_;
        float4 ui4 = *(const float4*)(g_us + ub + 0 * H_ + ch);
        float4 uo4 = *(const float4*)(g_us + ub + 1 * H_ + ch);
        float4 ug4 = *(const float4*)(g_us + ub + 2 * H_ + ch);
        float4 uf4 = *(const float4*)(g_us + ub + 3 * H_ + ch);
        float4 cpv;
        if (t == 0) cpv = *(const float4*)(z0 + b * (2 * H_) + H_ + ch);
        else        cpv = *(const float4*)(cpb + (size_t)(n - 1) * H_ + ch);

        const float* pip = (const float*)&pi4;
        const float* pop = (const float*)&po4;
        const float* pgp = (const float*)&pg4;
        const float* pfp = (const float*)&pf4;
        const float* uip = (const float*)&ui4;
        const float* uop = (const float*)&uo4;
        const float* ugp = (const float*)&ug4;
        const float* ufp = (const float*)&uf4;
        const float* cpl = (const float*)&cpv;

        float4 hv, cv;
        float* hvp = (float*)&hv;
        float* cvp = (float*)&cv;
#pragma unroll
        for (int e = 0; e < 4; e++) {
            float pi = pip[e] + uip[e];
            float po = pop[e] + uop[e];
            float pg = pgp[e] + ugp[e];
            float pf = pfp[e] + ufp[e];
            float si = 1.0f / (1.0f + __expf(-pi));
            float so = 1.0f / (1.0f + __expf(-po));
            float sf = 1.0f / (1.0f + __expf(-pf));
            float tg = tanhf(pg);
            float c = sf * cpl[e] + si * tg;
            float h = so * tanhf(c);
            hvp[e] = h;
            cvp[e] = c;
        }
        *(float4*)(hn + (size_t)n * H_ + ch) = hv;
        *(float4*)(cn + (size_t)n * H_ + ch) = cv;
    }
#undef LOAD_STAGE
}

// ===========================================================================
// Outputs
// ===========================================================================
__global__ void write_out(float* __restrict__ out) {
    int idx = blockIdx.x * blockDim.x + threadIdx.x;
    const int total = B_ * L_ * NOUT_;
    if (idx < total) {
        int j = idx & (NOUT_ - 1);
        int n = idx >> 8;
        out[idx] = g_h0[(size_t)n * H_ + (H_ - NOUT_) + j];
    }
    if (idx < B_ * 2 * H_) {
        int ch = idx % (2 * H_);
        int b  = idx / (2 * H_);
        int n  = b * L_ + (L_ - 1);
        float v = (ch < H_) ? g_h0[(size_t)n * H_ + ch]
                            : g_c0[(size_t)n * H_ + (ch - H_)];
        out[total + idx] = v;
    }
}

// ===========================================================================
extern "C" void kernel_launch(void* const* d_in, const int* in_sizes, int n_in,
                              void* d_out, int out_size) {
    const float* X        = (const float*)d_in[0];
    const float* z0       = (const float*)d_in[1];
    const float* inject_w = (const float*)d_in[2];
    const float* inject_b = (const float*)d_in[3];
    const float* conv_w   = (const float*)d_in[4];
    const float* conv_b   = (const float*)d_in[5];
    float* out = (float*)d_out;

    const int smem_bytes = NSTAGE * STG_SZ * sizeof(float);   // 81920
    cudaFuncSetAttribute(gemm_fused<KI_, true>,
                         cudaFuncAttributeMaxDynamicSharedMemorySize, smem_bytes);
    cudaFuncSetAttribute(gemm_fused<KC_, false>,
                         cudaFuncAttributeMaxDynamicSharedMemorySize, smem_bytes);

    repack_conv2<<<(M4_ * KC_ + 255) / 256, 256>>>(conv_w);
    repack_inj2<<<(M4_ * KI_ + 255) / 256, 256>>>(inject_w, inject_b, conv_b);
    transpose_x<<<dim3(L_ / 32, NINP_ / 32, B_), dim3(32, 8)>>>(X);
    zero_hc<<<(H_ * N_ + 255) / 256, 256>>>();

    gemm_fused<KI_, true><<<dim3(N_ / 128, M4_ / 128), 256, smem_bytes>>>(z0, 0);

    for (int l = 0; l < NLAYER_; l++)
        gemm_fused<KC_, false><<<dim3(N_ / 128, M4_ / 128), 256, smem_bytes>>>(z0, l & 1);

    write_out<<<(B_ * L_ * NOUT_ + 255) / 256, 256>>>(out);
}

// round 5
// speedup vs baseline: 5.4430x; 1.4828x over previous
#include <cuda_runtime.h>
#include <cuda_fp16.h>
#include <math.h>
#include <cstdint>

// Problem constants
#define B_    4
#define H_    768
#define L_    1024
#define N_    4096          // B_*L_
#define M4_   3072          // 4*H_
#define NINP_ 512
#define KC_   1536          // conv K  ([h(t-1); h(t)])
#define KI_   1024          // inject K ([x(t-1); x(t)])
#define NOUT_ 256
#define NLAYER_ 10

// Scratch (device globals; no allocation allowed)
__device__ float g_us[(size_t)N_ * M4_]; // us[n][m] plain order (gate*H + ch), biases folded
__device__ float g_h0[(size_t)N_ * H_];  // h fp32 (outputs / reference path)
__device__ float g_c0[(size_t)N_ * H_];
__device__ float g_c1[(size_t)N_ * H_];
__device__ __half g_hh0[(size_t)N_ * H_]; // h fp16 mirror (GEMM A input)
__device__ __half g_hh1[(size_t)N_ * H_];
__device__ __half g_Wc2[(size_t)M4_ * KC_]; // conv W fp16, gate-interleaved rows, K-contig
__device__ __half g_Wi2[(size_t)M4_ * KI_]; // inject W fp16, plain rows, K-contig
__device__ __half g_Xt[(size_t)N_ * NINP_]; // X fp16, time-major [n][i]
__device__ __half g_z0h[B_ * H_];           // z0 h-part fp16
__device__ float  g_bias[M4_];              // inject_b + conv_b

// ===========================================================================
// Helpers
// ===========================================================================
__device__ __forceinline__ uint32_t smem_u32(const void* p) {
    uint32_t a;
    asm("{ .reg .u64 t; cvta.to.shared.u64 t, %1; cvt.u32.u64 %0, t; }"
        : "=r"(a) : "l"(p));
    return a;
}
__device__ __forceinline__ void cp_async16(uint32_t dst, const void* src) {
    asm volatile("cp.async.cg.shared.global [%0], [%1], 16;" :: "r"(dst), "l"(src));
}
__device__ __forceinline__ void cp_async16_zero(uint32_t dst, const void* src) {
    asm volatile("cp.async.cg.shared.global [%0], [%1], 16, 0;" :: "r"(dst), "l"(src));
}
__device__ __forceinline__ void cp_commit() {
    asm volatile("cp.async.commit_group;");
}
template <int Npend>
__device__ __forceinline__ void cp_wait() {
    asm volatile("cp.async.wait_group %0;" :: "n"(Npend));
}
// fp16 mma: D[16x8] += A[16x16] * B[16x8], fp32 accum
__device__ __forceinline__ void mma_f16(float& c0, float& c1, float& c2, float& c3,
                                        uint32_t a0, uint32_t a1, uint32_t a2, uint32_t a3,
                                        uint32_t b0, uint32_t b1) {
    asm volatile(
        "mma.sync.aligned.m16n8k16.row.col.f32.f16.f16.f32 "
        "{%0,%1,%2,%3}, {%4,%5,%6,%7}, {%8,%9}, {%0,%1,%2,%3};"
        : "+f"(c0), "+f"(c1), "+f"(c2), "+f"(c3)
        : "r"(a0), "r"(a1), "r"(a2), "r"(a3), "r"(b0), "r"(b1));
}

// ===========================================================================
// Repacks / transpose / init (fp16 conversions)
// ===========================================================================
__global__ void repack_conv2(const float* __restrict__ conv_w) {
    int idx = blockIdx.x * blockDim.x + threadIdx.x;
    if (idx >= M4_ * KC_) return;
    int mp = idx / KC_;
    int k  = idx - mp * KC_;
    int y  = mp >> 7;
    int rr = mp & 127;
    int g  = rr >> 5;
    int cl = rr & 31;
    int m  = g * H_ + y * 32 + cl;
    int tap = (k >= H_) ? 1 : 0;
    int i = k - tap * H_;
    g_Wc2[idx] = __float2half_rn(conv_w[m * (H_ * 2) + i * 2 + tap]);
}

__global__ void repack_inj2(const float* __restrict__ inject_w,
                            const float* __restrict__ inject_b,
                            const float* __restrict__ conv_b) {
    int idx = blockIdx.x * blockDim.x + threadIdx.x;
    if (idx >= M4_ * KI_) return;
    int m = idx / KI_;
    int k = idx - m * KI_;
    int tap = (k >= NINP_) ? 1 : 0;
    int i = k - tap * NINP_;
    g_Wi2[idx] = __float2half_rn(inject_w[m * (NINP_ * 2) + i * 2 + tap]);
    if (k == 0) g_bias[m] = inject_b[m] + conv_b[m];
}

__global__ void transpose_x(const float* __restrict__ X) {
    __shared__ float tile[32][33];
    int b  = blockIdx.z;
    int i0 = blockIdx.y * 32;
    int t0 = blockIdx.x * 32;
    int tx = threadIdx.x, ty = threadIdx.y;
#pragma unroll
    for (int j = 0; j < 32; j += 8)
        tile[ty + j][tx] = X[(size_t)(b * NINP_ + i0 + ty + j) * L_ + t0 + tx];
    __syncthreads();
#pragma unroll
    for (int j = 0; j < 32; j += 8)
        g_Xt[(size_t)(b * L_ + t0 + ty + j) * NINP_ + i0 + tx] =
            __float2half_rn(tile[tx][ty + j]);
}

__global__ void init_state(const float* __restrict__ z0) {
    int idx = blockIdx.x * blockDim.x + threadIdx.x;
    if (idx < H_ * N_) { g_hh0[idx] = __half(0.0f); g_c0[idx] = 0.0f; }
    if (idx < B_ * H_) {
        int b = idx / H_, ch = idx - b * H_;
        g_z0h[idx] = __float2half_rn(z0[b * (2 * H_) + ch]);
    }
}

// ===========================================================================
// Fused GEMM (fp16 mma.sync m16n8k16, 4-stage cp.async), 128(n)x128(m), BK=32.
// INJECT=true : A = stacked X taps (fp16), B = g_Wi2 -> g_us + bias (fp32)
// INJECT=false: A = stacked h taps (fp16), B = g_Wc2 (gate-interleaved) -> fused gating
// ===========================================================================
#define BK      32
#define KS      40                       // padded row stride (halfs), 80B
#define STG_A   (128 * KS)               // halfs per A stage
#define STG_SZ  (2 * 128 * KS)           // halfs per stage (A+B)
#define NSTAGE  4
#define PS      132                      // pre_s row stride (floats)

template <int KTOT, bool INJECT>
__global__ __launch_bounds__(256, 1)
void gemm_fused(const float* __restrict__ z0, int rd) {
    extern __shared__ __half smh[];
    constexpr int KHALF = KTOT / 2;
    constexpr int NKT = KTOT / BK;

    const __half* __restrict__ Asrc = INJECT ? g_Xt : (rd ? g_hh1 : g_hh0);
    const __half* __restrict__ Bw   = INJECT ? g_Wi2 : g_Wc2;

    const int tid  = threadIdx.x;
    const int wid  = tid >> 5;
    const int lane = tid & 31;
    const int grp  = lane >> 2;
    const int qid  = lane & 3;
    const int n0   = blockIdx.x * 128;
    const int m0   = blockIdx.y * 128;

    const int wn = (wid >> 2) * 64;
    const int wm = (wid & 3) * 32;

    const uint32_t sbase = smem_u32(smh);

#define LOAD_STAGE(S, K0)                                                        \
    do {                                                                         \
        const int _k0 = (K0);                                                    \
        const uint32_t aoff = ((S) % NSTAGE) * STG_SZ;                           \
        const uint32_t boff = aoff + STG_A;                                      \
        _Pragma("unroll")                                                        \
        for (int j = 0; j < 2; j++) {                                            \
            int idx = tid + j * 256;                                             \
            int r  = idx >> 2;                                                   \
            int c8 = idx & 3;                                                    \
            int kk = _k0 + c8 * 8;                                               \
            {                                                                    \
                int n = n0 + r;                                                  \
                int t = n & (L_ - 1);                                            \
                int b = n >> 10;                                                 \
                uint32_t dst = sbase + (aoff + r * KS + c8 * 8) * 2;             \
                if (kk < KHALF) {                                                \
                    if (t == 0) {                                                \
                        if (INJECT) cp_async16_zero(dst, Asrc);                  \
                        else cp_async16(dst, g_z0h + b * H_ + kk);               \
                    } else {                                                     \
                        cp_async16(dst, Asrc + (size_t)(n - 1) * KHALF + kk);    \
                    }                                                            \
                } else {                                                         \
                    cp_async16(dst, Asrc + (size_t)n * KHALF + (kk - KHALF));    \
                }                                                                \
            }                                                                    \
            {                                                                    \
                uint32_t dst = sbase + (boff + r * KS + c8 * 8) * 2;             \
                cp_async16(dst, Bw + (size_t)(m0 + r) * KTOT + kk);              \
            }                                                                    \
        }                                                                        \
        cp_commit();                                                             \
    } while (0)

    // prologue
#pragma unroll
    for (int s = 0; s < NSTAGE - 1; s++) LOAD_STAGE(s, s * BK);

    float acc[4][4][4];
#pragma unroll
    for (int i = 0; i < 4; i++)
#pragma unroll
        for (int j = 0; j < 4; j++)
#pragma unroll
            for (int e = 0; e < 4; e++) acc[i][j][e] = 0.0f;

#pragma unroll 1
    for (int kt = 0; kt < NKT; kt++) {
        cp_wait<NSTAGE - 2>();
        __syncthreads();

        const int sf = kt + NSTAGE - 1;
        if (sf < NKT) LOAD_STAGE(sf, sf * BK);
        else cp_commit();

        const __half* As = smh + (kt % NSTAGE) * STG_SZ;
        const __half* Bs = As + STG_A;
#pragma unroll
        for (int ks = 0; ks < BK; ks += 16) {
            uint32_t af[4][4];
            uint32_t bf[4][2];
#pragma unroll
            for (int fi = 0; fi < 4; fi++) {
                int nr = wn + fi * 16 + grp;
                af[fi][0] = *(const uint32_t*)(As + nr * KS + ks + 2 * qid);
                af[fi][1] = *(const uint32_t*)(As + (nr + 8) * KS + ks + 2 * qid);
                af[fi][2] = *(const uint32_t*)(As + nr * KS + ks + 8 + 2 * qid);
                af[fi][3] = *(const uint32_t*)(As + (nr + 8) * KS + ks + 8 + 2 * qid);
            }
#pragma unroll
            for (int fj = 0; fj < 4; fj++) {
                int mr = wm + fj * 8 + grp;
                bf[fj][0] = *(const uint32_t*)(Bs + mr * KS + ks + 2 * qid);
                bf[fj][1] = *(const uint32_t*)(Bs + mr * KS + ks + 8 + 2 * qid);
            }
#pragma unroll
            for (int fi = 0; fi < 4; fi++)
#pragma unroll
                for (int fj = 0; fj < 4; fj++)
                    mma_f16(acc[fi][fj][0], acc[fi][fj][1], acc[fi][fj][2], acc[fi][fj][3],
                            af[fi][0], af[fi][1], af[fi][2], af[fi][3],
                            bf[fj][0], bf[fj][1]);
        }
    }

    if (INJECT) {
#pragma unroll
        for (int fi = 0; fi < 4; fi++) {
#pragma unroll
            for (int fj = 0; fj < 4; fj++) {
                int n1 = n0 + wn + fi * 16 + grp;
                int m  = m0 + wm + fj * 8 + qid * 2;
                float b0 = g_bias[m], b1 = g_bias[m + 1];
                *(float2*)(g_us + (size_t)n1 * M4_ + m) =
                    make_float2(acc[fi][fj][0] + b0, acc[fi][fj][1] + b1);
                *(float2*)(g_us + (size_t)(n1 + 8) * M4_ + m) =
                    make_float2(acc[fi][fj][2] + b0, acc[fi][fj][3] + b1);
            }
        }
        return;
    }

    // ---------------- fused gating epilogue (layers only) ----------------
    __syncthreads();                 // all warps done with stage buffers
    float* pre_s = (float*)smh;      // 128 x PS floats = 67.6 KB, fits in 80 KB
#pragma unroll
    for (int fi = 0; fi < 4; fi++) {
#pragma unroll
        for (int fj = 0; fj < 4; fj++) {
            int r0   = wn + fi * 16 + grp;
            int cidx = wm + fj * 8 + qid * 2;
            *(float2*)&pre_s[r0 * PS + cidx] =
                make_float2(acc[fi][fj][0], acc[fi][fj][1]);
            *(float2*)&pre_s[(r0 + 8) * PS + cidx] =
                make_float2(acc[fi][fj][2], acc[fi][fj][3]);
        }
    }
    __syncthreads();

    const float* __restrict__ cpb = rd ? g_c1 : g_c0;
    float* __restrict__ cn = rd ? g_c0 : g_c1;
    __half* __restrict__ hhn = rd ? g_hh0 : g_hh1;
    const int chbase = blockIdx.y * 32;
    const int q  = tid & 7;          // float4 group within 32 channels
    const int nl = tid >> 3;         // 0..31

#pragma unroll
    for (int it = 0; it < 4; it++) {
        int n_local = nl + it * 32;
        int n = n0 + n_local;
        int t = n & (L_ - 1);
        int b = n >> 10;
        int ch = chbase + q * 4;

        float4 pi4 = *(const float4*)&pre_s[n_local * PS + 0 * 32 + q * 4];
        float4 po4 = *(const float4*)&pre_s[n_local * PS + 1 * 32 + q * 4];
        float4 pg4 = *(const float4*)&pre_s[n_local * PS + 2 * 32 + q * 4];
        float4 pf4 = *(const float4*)&pre_s[n_local * PS + 3 * 32 + q * 4];
        const size_t ub = (size_t)n * M4_;
        float4 ui4 = *(const float4*)(g_us + ub + 0 * H_ + ch);
        float4 uo4 = *(const float4*)(g_us + ub + 1 * H_ + ch);
        float4 ug4 = *(const float4*)(g_us + ub + 2 * H_ + ch);
        float4 uf4 = *(const float4*)(g_us + ub + 3 * H_ + ch);
        float4 cpv;
        if (t == 0) cpv = *(const float4*)(z0 + b * (2 * H_) + H_ + ch);
        else        cpv = *(const float4*)(cpb + (size_t)(n - 1) * H_ + ch);

        const float* pip = (const float*)&pi4;
        const float* pop = (const float*)&po4;
        const float* pgp = (const float*)&pg4;
        const float* pfp = (const float*)&pf4;
        const float* uip = (const float*)&ui4;
        const float* uop = (const float*)&uo4;
        const float* ugp = (const float*)&ug4;
        const float* ufp = (const float*)&uf4;
        const float* cpl = (const float*)&cpv;

        float4 hv, cv;
        float* hvp = (float*)&hv;
        float* cvp = (float*)&cv;
#pragma unroll
        for (int e = 0; e < 4; e++) {
            float pi = pip[e] + uip[e];
            float po = pop[e] + uop[e];
            float pg = pgp[e] + ugp[e];
            float pf = pfp[e] + ufp[e];
            float si = 1.0f / (1.0f + __expf(-pi));
            float so = 1.0f / (1.0f + __expf(-po));
            float sf = 1.0f / (1.0f + __expf(-pf));
            float tg = tanhf(pg);
            float c = sf * cpl[e] + si * tg;
            float h = so * tanhf(c);
            hvp[e] = h;
            cvp[e] = c;
        }
        // fp32 h (for outputs), fp16 h (next layer GEMM input), fp32 c
        *(float4*)(g_h0 + (size_t)n * H_ + ch) = hv;   // overwritten each layer; last wins
        *(float4*)(cn + (size_t)n * H_ + ch) = cv;
        __half2 h01 = __floats2half2_rn(hvp[0], hvp[1]);
        __half2 h23 = __floats2half2_rn(hvp[2], hvp[3]);
        *(__half2*)(hhn + (size_t)n * H_ + ch)     = h01;
        *(__half2*)(hhn + (size_t)n * H_ + ch + 2) = h23;
    }
#undef LOAD_STAGE
}

// ===========================================================================
// Outputs: out (B, L, NOUT) then z0_out (B, 2H, 1).
// g_h0 holds last layer's fp32 h; g_c0 holds last layer's c (10 layers, rd=1 ends in c0).
// ===========================================================================
__global__ void write_out(float* __restrict__ out) {
    int idx = blockIdx.x * blockDim.x + threadIdx.x;
    const int total = B_ * L_ * NOUT_;
    if (idx < total) {
        int j = idx & (NOUT_ - 1);
        int n = idx >> 8;
        out[idx] = g_h0[(size_t)n * H_ + (H_ - NOUT_) + j];
    }
    if (idx < B_ * 2 * H_) {
        int ch = idx % (2 * H_);
        int b  = idx / (2 * H_);
        int n  = b * L_ + (L_ - 1);
        float v = (ch < H_) ? g_h0[(size_t)n * H_ + ch]
                            : g_c0[(size_t)n * H_ + (ch - H_)];
        out[total + idx] = v;
    }
}

// ===========================================================================
extern "C" void kernel_launch(void* const* d_in, const int* in_sizes, int n_in,
                              void* d_out, int out_size) {
    const float* X        = (const float*)d_in[0];
    const float* z0       = (const float*)d_in[1];
    const float* inject_w = (const float*)d_in[2];
    const float* inject_b = (const float*)d_in[3];
    const float* conv_w   = (const float*)d_in[4];
    const float* conv_b   = (const float*)d_in[5];
    float* out = (float*)d_out;

    const int smem_bytes = NSTAGE * STG_SZ * sizeof(__half);   // 81920
    cudaFuncSetAttribute(gemm_fused<KI_, true>,
                         cudaFuncAttributeMaxDynamicSharedMemorySize, smem_bytes);
    cudaFuncSetAttribute(gemm_fused<KC_, false>,
                         cudaFuncAttributeMaxDynamicSharedMemorySize, smem_bytes);

    repack_conv2<<<(M4_ * KC_ + 255) / 256, 256>>>(conv_w);
    repack_inj2<<<(M4_ * KI_ + 255) / 256, 256>>>(inject_w, inject_b, conv_b);
    transpose_x<<<dim3(L_ / 32, NINP_ / 32, B_), dim3(32, 8)>>>(X);
    init_state<<<(H_ * N_ + 255) / 256, 256>>>(z0);

    gemm_fused<KI_, true><<<dim3(N_ / 128, M4_ / 128), 256, smem_bytes>>>(z0, 0);

    for (int l = 0; l < NLAYER_; l++)
        gemm_fused<KC_, false><<<dim3(N_ / 128, M4_ / 128), 256, smem_bytes>>>(z0, l & 1);

    write_out<<<(B_ * L_ * NOUT_ + 255) / 256, 256>>>(out);
}

// round 6
// speedup vs baseline: 6.1071x; 1.1220x over previous
#include <cuda_runtime.h>
#include <cuda_fp16.h>
#include <math.h>
#include <cstdint>

// Problem constants
#define B_    4
#define H_    768
#define L_    1024
#define N_    4096          // B_*L_
#define M4_   3072          // 4*H_
#define NINP_ 512
#define KC_   1536          // conv K  ([h(t-1); h(t)])
#define KI_   1024          // inject K ([x(t-1); x(t)])
#define NOUT_ 256
#define NLAYER_ 10

// Scratch (device globals; no allocation allowed)
__device__ float g_us[(size_t)N_ * M4_]; // us[n][m] plain order (gate*H + ch), biases folded
__device__ float g_h0[(size_t)N_ * H_];  // h fp32 (outputs)
__device__ float g_c0[(size_t)N_ * H_];
__device__ float g_c1[(size_t)N_ * H_];
__device__ __half g_hh0[(size_t)N_ * H_]; // h fp16 mirror (GEMM A input)
__device__ __half g_hh1[(size_t)N_ * H_];
__device__ __half g_Wc2[(size_t)M4_ * KC_]; // conv W fp16, gate-interleaved rows, K-contig
__device__ __half g_Wi2[(size_t)M4_ * KI_]; // inject W fp16, plain rows, K-contig
__device__ __half g_Xt[(size_t)N_ * NINP_]; // X fp16, time-major [n][i]
__device__ __half g_z0h[B_ * H_];           // z0 h-part fp16
__device__ float  g_bias[M4_];              // inject_b + conv_b

// ===========================================================================
// Helpers
// ===========================================================================
__device__ __forceinline__ uint32_t smem_u32(const void* p) {
    uint32_t a;
    asm("{ .reg .u64 t; cvta.to.shared.u64 t, %1; cvt.u32.u64 %0, t; }"
        : "=r"(a) : "l"(p));
    return a;
}
__device__ __forceinline__ void cp_async16(uint32_t dst, const void* src) {
    asm volatile("cp.async.cg.shared.global [%0], [%1], 16;" :: "r"(dst), "l"(src));
}
__device__ __forceinline__ void cp_async16_zero(uint32_t dst, const void* src) {
    asm volatile("cp.async.cg.shared.global [%0], [%1], 16, 0;" :: "r"(dst), "l"(src));
}
__device__ __forceinline__ void cp_commit() {
    asm volatile("cp.async.commit_group;");
}
template <int Npend>
__device__ __forceinline__ void cp_wait() {
    asm volatile("cp.async.wait_group %0;" :: "n"(Npend));
}
__device__ __forceinline__ void ldmatrix_x4(uint32_t* r, uint32_t addr) {
    asm volatile("ldmatrix.sync.aligned.m8n8.x4.shared.b16 {%0,%1,%2,%3}, [%4];"
        : "=r"(r[0]), "=r"(r[1]), "=r"(r[2]), "=r"(r[3]) : "r"(addr));
}
// fp16 mma: D[16x8] += A[16x16] * B[16x8], fp32 accum
__device__ __forceinline__ void mma_f16(float& c0, float& c1, float& c2, float& c3,
                                        uint32_t a0, uint32_t a1, uint32_t a2, uint32_t a3,
                                        uint32_t b0, uint32_t b1) {
    asm volatile(
        "mma.sync.aligned.m16n8k16.row.col.f32.f16.f16.f32 "
        "{%0,%1,%2,%3}, {%4,%5,%6,%7}, {%8,%9}, {%0,%1,%2,%3};"
        : "+f"(c0), "+f"(c1), "+f"(c2), "+f"(c3)
        : "r"(a0), "r"(a1), "r"(a2), "r"(a3), "r"(b0), "r"(b1));
}

// ===========================================================================
// Repacks / transpose / init
// ===========================================================================
__global__ void repack_conv2(const float* __restrict__ conv_w) {
    int idx = blockIdx.x * blockDim.x + threadIdx.x;
    if (idx >= M4_ * KC_) return;
    int mp = idx / KC_;
    int k  = idx - mp * KC_;
    int y  = mp >> 7;
    int rr = mp & 127;
    int g  = rr >> 5;
    int cl = rr & 31;
    int m  = g * H_ + y * 32 + cl;
    int tap = (k >= H_) ? 1 : 0;
    int i = k - tap * H_;
    g_Wc2[idx] = __float2half_rn(conv_w[m * (H_ * 2) + i * 2 + tap]);
}

__global__ void repack_inj2(const float* __restrict__ inject_w,
                            const float* __restrict__ inject_b,
                            const float* __restrict__ conv_b) {
    int idx = blockIdx.x * blockDim.x + threadIdx.x;
    if (idx >= M4_ * KI_) return;
    int m = idx / KI_;
    int k = idx - m * KI_;
    int tap = (k >= NINP_) ? 1 : 0;
    int i = k - tap * NINP_;
    g_Wi2[idx] = __float2half_rn(inject_w[m * (NINP_ * 2) + i * 2 + tap]);
    if (k == 0) g_bias[m] = inject_b[m] + conv_b[m];
}

__global__ void transpose_x(const float* __restrict__ X) {
    __shared__ float tile[32][33];
    int b  = blockIdx.z;
    int i0 = blockIdx.y * 32;
    int t0 = blockIdx.x * 32;
    int tx = threadIdx.x, ty = threadIdx.y;
#pragma unroll
    for (int j = 0; j < 32; j += 8)
        tile[ty + j][tx] = X[(size_t)(b * NINP_ + i0 + ty + j) * L_ + t0 + tx];
    __syncthreads();
#pragma unroll
    for (int j = 0; j < 32; j += 8)
        g_Xt[(size_t)(b * L_ + t0 + ty + j) * NINP_ + i0 + tx] =
            __float2half_rn(tile[tx][ty + j]);
}

__global__ void init_state(const float* __restrict__ z0) {
    int idx = blockIdx.x * blockDim.x + threadIdx.x;
    if (idx < H_ * N_) { g_hh0[idx] = __half(0.0f); g_c0[idx] = 0.0f; }
    if (idx < B_ * H_) {
        int b = idx / H_, ch = idx - b * H_;
        g_z0h[idx] = __float2half_rn(z0[b * (2 * H_) + ch]);
    }
}

// ===========================================================================
// Fused GEMM (fp16 mma.sync m16n8k16 + ldmatrix), 128(n)x128(m), BK=64, 3 stages.
// ===========================================================================
#define BK      64
#define KS      72                       // padded row stride (halfs), 144B
#define STG_A   (128 * KS)               // halfs per A stage
#define STG_SZ  (2 * 128 * KS)           // halfs per stage (A+B)
#define NSTAGE  3
#define PS      132                      // pre_s row stride (floats)
#define SMEM_BYTES (NSTAGE * STG_SZ * 2) // 110592

template <int KTOT, bool INJECT>
__global__ __launch_bounds__(256, 1)
void gemm_fused(const float* __restrict__ z0, int rd) {
    extern __shared__ __half smh[];
    constexpr int KHALF = KTOT / 2;
    constexpr int NKT = KTOT / BK;

    const __half* __restrict__ Asrc = INJECT ? g_Xt : (rd ? g_hh1 : g_hh0);
    const __half* __restrict__ Bw   = INJECT ? g_Wi2 : g_Wc2;

    const int tid  = threadIdx.x;
    const int wid  = tid >> 5;
    const int lane = tid & 31;
    const int grp  = lane >> 2;
    const int qid  = lane & 3;
    const int n0   = blockIdx.x * 128;
    const int m0   = blockIdx.y * 128;

    const int wn = (wid >> 2) * 64;
    const int wm = (wid & 3) * 32;

    const uint32_t sbase = smem_u32(smh);
    // ldmatrix per-lane row/col offsets
    const int lrow = lane & 15;              // row within 16-row group
    const int lcol = (lane >> 4) << 3;       // 0 or 8 (k offset)

#define LOAD_STAGE(S, K0)                                                        \
    do {                                                                         \
        const int _k0 = (K0);                                                    \
        const uint32_t aoff = ((S) % NSTAGE) * STG_SZ;                           \
        const uint32_t boff = aoff + STG_A;                                      \
        _Pragma("unroll")                                                        \
        for (int j = 0; j < 4; j++) {                                            \
            int idx = tid + j * 256;         /* 0..1023 */                       \
            int r  = idx >> 3;                                                   \
            int c8 = idx & 7;                                                    \
            int kk = _k0 + c8 * 8;                                               \
            {                                                                    \
                int n = n0 + r;                                                  \
                int t = n & (L_ - 1);                                            \
                int b = n >> 10;                                                 \
                uint32_t dst = sbase + (aoff + r * KS + c8 * 8) * 2;             \
                if (kk < KHALF) {                                                \
                    if (t == 0) {                                                \
                        if (INJECT) cp_async16_zero(dst, Asrc);                  \
                        else cp_async16(dst, g_z0h + b * H_ + kk);               \
                    } else {                                                     \
                        cp_async16(dst, Asrc + (size_t)(n - 1) * KHALF + kk);    \
                    }                                                            \
                } else {                                                         \
                    cp_async16(dst, Asrc + (size_t)n * KHALF + (kk - KHALF));    \
                }                                                                \
            }                                                                    \
            {                                                                    \
                uint32_t dst = sbase + (boff + r * KS + c8 * 8) * 2;             \
                cp_async16(dst, Bw + (size_t)(m0 + r) * KTOT + kk);              \
            }                                                                    \
        }                                                                        \
        cp_commit();                                                             \
    } while (0)

    // prologue: issue NSTAGE-1 stages
#pragma unroll
    for (int s = 0; s < NSTAGE - 1; s++) LOAD_STAGE(s, s * BK);

    float acc[4][4][4];
#pragma unroll
    for (int i = 0; i < 4; i++)
#pragma unroll
        for (int j = 0; j < 4; j++)
#pragma unroll
            for (int e = 0; e < 4; e++) acc[i][j][e] = 0.0f;

#pragma unroll 1
    for (int kt = 0; kt < NKT; kt++) {
        cp_wait<NSTAGE - 2>();
        __syncthreads();

        const int sf = kt + NSTAGE - 1;
        if (sf < NKT) LOAD_STAGE(sf, sf * BK);
        else cp_commit();

        const uint32_t a_base = sbase + (uint32_t)((kt % NSTAGE) * STG_SZ) * 2;
        const uint32_t b_base = a_base + STG_A * 2;

#pragma unroll
        for (int ks = 0; ks < BK; ks += 16) {
            uint32_t af[4][4];
            uint32_t bf[2][4];
#pragma unroll
            for (int fi = 0; fi < 4; fi++) {
                uint32_t addr = a_base +
                    (uint32_t)((wn + fi * 16 + lrow) * KS + ks + lcol) * 2;
                ldmatrix_x4(af[fi], addr);
            }
#pragma unroll
            for (int fh = 0; fh < 2; fh++) {
                uint32_t addr = b_base +
                    (uint32_t)((wm + fh * 16 + lrow) * KS + ks + lcol) * 2;
                ldmatrix_x4(bf[fh], addr);
            }
            // bf[fh] = {fj(2fh).b0, fj(2fh+1).b0, fj(2fh).b1, fj(2fh+1).b1}
#pragma unroll
            for (int fi = 0; fi < 4; fi++) {
#pragma unroll
                for (int fh = 0; fh < 2; fh++) {
#pragma unroll
                    for (int s2 = 0; s2 < 2; s2++) {
                        int fj = fh * 2 + s2;
                        mma_f16(acc[fi][fj][0], acc[fi][fj][1],
                                acc[fi][fj][2], acc[fi][fj][3],
                                af[fi][0], af[fi][1], af[fi][2], af[fi][3],
                                bf[fh][s2], bf[fh][s2 + 2]);
                    }
                }
            }
        }
    }

    if (INJECT) {
#pragma unroll
        for (int fi = 0; fi < 4; fi++) {
#pragma unroll
            for (int fj = 0; fj < 4; fj++) {
                int n1 = n0 + wn + fi * 16 + grp;
                int m  = m0 + wm + fj * 8 + qid * 2;
                float b0 = g_bias[m], b1 = g_bias[m + 1];
                *(float2*)(g_us + (size_t)n1 * M4_ + m) =
                    make_float2(acc[fi][fj][0] + b0, acc[fi][fj][1] + b1);
                *(float2*)(g_us + (size_t)(n1 + 8) * M4_ + m) =
                    make_float2(acc[fi][fj][2] + b0, acc[fi][fj][3] + b1);
            }
        }
        return;
    }

    // ---------------- fused gating epilogue ----------------
    __syncthreads();
    float* pre_s = (float*)smh;      // 128 x PS floats = 67.6 KB <= 108 KB
#pragma unroll
    for (int fi = 0; fi < 4; fi++) {
#pragma unroll
        for (int fj = 0; fj < 4; fj++) {
            int r0   = wn + fi * 16 + grp;
            int cidx = wm + fj * 8 + qid * 2;
            *(float2*)&pre_s[r0 * PS + cidx] =
                make_float2(acc[fi][fj][0], acc[fi][fj][1]);
            *(float2*)&pre_s[(r0 + 8) * PS + cidx] =
                make_float2(acc[fi][fj][2], acc[fi][fj][3]);
        }
    }
    __syncthreads();

    const float* __restrict__ cpb = rd ? g_c1 : g_c0;
    float* __restrict__ cn = rd ? g_c0 : g_c1;
    __half* __restrict__ hhn = rd ? g_hh0 : g_hh1;
    const int chbase = blockIdx.y * 32;
    const int q  = tid & 7;
    const int nl = tid >> 3;

#pragma unroll
    for (int it = 0; it < 4; it++) {
        int n_local = nl + it * 32;
        int n = n0 + n_local;
        int t = n & (L_ - 1);
        int b = n >> 10;
        int ch = chbase + q * 4;

        float4 pi4 = *(const float4*)&pre_s[n_local * PS + 0 * 32 + q * 4];
        float4 po4 = *(const float4*)&pre_s[n_local * PS + 1 * 32 + q * 4];
        float4 pg4 = *(const float4*)&pre_s[n_local * PS + 2 * 32 + q * 4];
        float4 pf4 = *(const float4*)&pre_s[n_local * PS + 3 * 32 + q * 4];
        const size_t ub = (size_t)n * M4_;
        float4 ui4 = *(const float4*)(g_us + ub + 0 * H_ + ch);
        float4 uo4 = *(const float4*)(g_us + ub + 1 * H_ + ch);
        float4 ug4 = *(const float4*)(g_us + ub + 2 * H_ + ch);
        float4 uf4 = *(const float4*)(g_us + ub + 3 * H_ + ch);
        float4 cpv;
        if (t == 0) cpv = *(const float4*)(z0 + b * (2 * H_) + H_ + ch);
        else        cpv = *(const float4*)(cpb + (size_t)(n - 1) * H_ + ch);

        const float* pip = (const float*)&pi4;
        const float* pop = (const float*)&po4;
        const float* pgp = (const float*)&pg4;
        const float* pfp = (const float*)&pf4;
        const float* uip = (const float*)&ui4;
        const float* uop = (const float*)&uo4;
        const float* ugp = (const float*)&ug4;
        const float* ufp = (const float*)&uf4;
        const float* cpl = (const float*)&cpv;

        float4 hv, cv;
        float* hvp = (float*)&hv;
        float* cvp = (float*)&cv;
#pragma unroll
        for (int e = 0; e < 4; e++) {
            float pi = pip[e] + uip[e];
            float po = pop[e] + uop[e];
            float pg = pgp[e] + ugp[e];
            float pf = pfp[e] + ufp[e];
            float si = 1.0f / (1.0f + __expf(-pi));
            float so = 1.0f / (1.0f + __expf(-po));
            float sf = 1.0f / (1.0f + __expf(-pf));
            float tg = tanhf(pg);
            float c = sf * cpl[e] + si * tg;
            float h = so * tanhf(c);
            hvp[e] = h;
            cvp[e] = c;
        }
        *(float4*)(g_h0 + (size_t)n * H_ + ch) = hv;
        *(float4*)(cn + (size_t)n * H_ + ch) = cv;
        __half2 h01 = __floats2half2_rn(hvp[0], hvp[1]);
        __half2 h23 = __floats2half2_rn(hvp[2], hvp[3]);
        *(__half2*)(hhn + (size_t)n * H_ + ch)     = h01;
        *(__half2*)(hhn + (size_t)n * H_ + ch + 2) = h23;
    }
#undef LOAD_STAGE
}

// ===========================================================================
// Outputs
// ===========================================================================
__global__ void write_out(float* __restrict__ out) {
    int idx = blockIdx.x * blockDim.x + threadIdx.x;
    const int total = B_ * L_ * NOUT_;
    if (idx < total) {
        int j = idx & (NOUT_ - 1);
        int n = idx >> 8;
        out[idx] = g_h0[(size_t)n * H_ + (H_ - NOUT_) + j];
    }
    if (idx < B_ * 2 * H_) {
        int ch = idx % (2 * H_);
        int b  = idx / (2 * H_);
        int n  = b * L_ + (L_ - 1);
        float v = (ch < H_) ? g_h0[(size_t)n * H_ + ch]
                            : g_c0[(size_t)n * H_ + (ch - H_)];
        out[total + idx] = v;
    }
}

// ===========================================================================
extern "C" void kernel_launch(void* const* d_in, const int* in_sizes, int n_in,
                              void* d_out, int out_size) {
    const float* X        = (const float*)d_in[0];
    const float* z0       = (const float*)d_in[1];
    const float* inject_w = (const float*)d_in[2];
    const float* inject_b = (const float*)d_in[3];
    const float* conv_w   = (const float*)d_in[4];
    const float* conv_b   = (const float*)d_in[5];
    float* out = (float*)d_out;

    cudaFuncSetAttribute(gemm_fused<KI_, true>,
                         cudaFuncAttributeMaxDynamicSharedMemorySize, SMEM_BYTES);
    cudaFuncSetAttribute(gemm_fused<KC_, false>,
                         cudaFuncAttributeMaxDynamicSharedMemorySize, SMEM_BYTES);

    repack_conv2<<<(M4_ * KC_ + 255) / 256, 256>>>(conv_w);
    repack_inj2<<<(M4_ * KI_ + 255) / 256, 256>>>(inject_w, inject_b, conv_b);
    transpose_x<<<dim3(L_ / 32, NINP_ / 32, B_), dim3(32, 8)>>>(X);
    init_state<<<(H_ * N_ + 255) / 256, 256>>>(z0);

    gemm_fused<KI_, true><<<dim3(N_ / 128, M4_ / 128), 256, SMEM_BYTES>>>(z0, 0);

    for (int l = 0; l < NLAYER_; l++)
        gemm_fused<KC_, false><<<dim3(N_ / 128, M4_ / 128), 256, SMEM_BYTES>>>(z0, l & 1);

    write_out<<<(B_ * L_ * NOUT_ + 255) / 256, 256>>>(out);
}

// round 7
// speedup vs baseline: 7.1801x; 1.1757x over previous
#include <cuda_runtime.h>
#include <cuda_fp16.h>
#include <math.h>
#include <cstdint>

// Problem constants
#define B_    4
#define H_    768
#define L_    1024
#define N_    4096          // B_*L_
#define M4_   3072          // 4*H_
#define NINP_ 512
#define KC_   1536          // conv K  ([h(t-1); h(t)])
#define KI_   1024          // inject K ([x(t-1); x(t)])
#define NOUT_ 256
#define NLAYER_ 10

// Scratch (device globals; no allocation allowed)
__device__ float g_us[(size_t)N_ * M4_]; // us[n][m] plain order, biases folded
__device__ float g_h0[(size_t)N_ * H_];  // h fp32 (outputs)
__device__ float g_c0[(size_t)N_ * H_];
__device__ float g_c1[(size_t)N_ * H_];
__device__ __half g_hh0[(size_t)N_ * H_]; // h fp16 mirror (GEMM A input)
__device__ __half g_hh1[(size_t)N_ * H_];
__device__ __half g_Wc2[(size_t)M4_ * KC_]; // conv W fp16, gate-interleaved rows
__device__ __half g_Wi2[(size_t)M4_ * KI_]; // inject W fp16, plain rows
__device__ __half g_Xt[(size_t)N_ * NINP_]; // X fp16, time-major [n][i]
__device__ __half g_z0h[B_ * H_];           // z0 h-part fp16
__device__ float  g_bias[M4_];              // inject_b + conv_b

// ===========================================================================
// Helpers
// ===========================================================================
__device__ __forceinline__ uint32_t smem_u32(const void* p) {
    uint32_t a;
    asm("{ .reg .u64 t; cvta.to.shared.u64 t, %1; cvt.u32.u64 %0, t; }"
        : "=r"(a) : "l"(p));
    return a;
}
__device__ __forceinline__ void cp_async16(uint32_t dst, const void* src) {
    asm volatile("cp.async.cg.shared.global [%0], [%1], 16;" :: "r"(dst), "l"(src));
}
__device__ __forceinline__ void cp_async16_zero(uint32_t dst, const void* src) {
    asm volatile("cp.async.cg.shared.global [%0], [%1], 16, 0;" :: "r"(dst), "l"(src));
}
__device__ __forceinline__ void cp_commit() {
    asm volatile("cp.async.commit_group;");
}
template <int Npend>
__device__ __forceinline__ void cp_wait() {
    asm volatile("cp.async.wait_group %0;" :: "n"(Npend));
}
__device__ __forceinline__ void ldmatrix_x4(uint32_t* r, uint32_t addr) {
    asm volatile("ldmatrix.sync.aligned.m8n8.x4.shared.b16 {%0,%1,%2,%3}, [%4];"
        : "=r"(r[0]), "=r"(r[1]), "=r"(r[2]), "=r"(r[3]) : "r"(addr));
}
__device__ __forceinline__ void mma_f16(float& c0, float& c1, float& c2, float& c3,
                                        uint32_t a0, uint32_t a1, uint32_t a2, uint32_t a3,
                                        uint32_t b0, uint32_t b1) {
    asm volatile(
        "mma.sync.aligned.m16n8k16.row.col.f32.f16.f16.f32 "
        "{%0,%1,%2,%3}, {%4,%5,%6,%7}, {%8,%9}, {%0,%1,%2,%3};"
        : "+f"(c0), "+f"(c1), "+f"(c2), "+f"(c3)
        : "r"(a0), "r"(a1), "r"(a2), "r"(a3), "r"(b0), "r"(b1));
}

// ===========================================================================
// Repacks / transpose / init
// ===========================================================================
__global__ void repack_conv2(const float* __restrict__ conv_w) {
    int idx = blockIdx.x * blockDim.x + threadIdx.x;
    if (idx >= M4_ * KC_) return;
    int mp = idx / KC_;
    int k  = idx - mp * KC_;
    int y  = mp >> 7;
    int rr = mp & 127;
    int g  = rr >> 5;
    int cl = rr & 31;
    int m  = g * H_ + y * 32 + cl;
    int tap = (k >= H_) ? 1 : 0;
    int i = k - tap * H_;
    g_Wc2[idx] = __float2half_rn(conv_w[m * (H_ * 2) + i * 2 + tap]);
}

__global__ void repack_inj2(const float* __restrict__ inject_w,
                            const float* __restrict__ inject_b,
                            const float* __restrict__ conv_b) {
    int idx = blockIdx.x * blockDim.x + threadIdx.x;
    if (idx >= M4_ * KI_) return;
    int m = idx / KI_;
    int k = idx - m * KI_;
    int tap = (k >= NINP_) ? 1 : 0;
    int i = k - tap * NINP_;
    g_Wi2[idx] = __float2half_rn(inject_w[m * (NINP_ * 2) + i * 2 + tap]);
    if (k == 0) g_bias[m] = inject_b[m] + conv_b[m];
}

__global__ void transpose_x(const float* __restrict__ X) {
    __shared__ float tile[32][33];
    int b  = blockIdx.z;
    int i0 = blockIdx.y * 32;
    int t0 = blockIdx.x * 32;
    int tx = threadIdx.x, ty = threadIdx.y;
#pragma unroll
    for (int j = 0; j < 32; j += 8)
        tile[ty + j][tx] = X[(size_t)(b * NINP_ + i0 + ty + j) * L_ + t0 + tx];
    __syncthreads();
#pragma unroll
    for (int j = 0; j < 32; j += 8)
        g_Xt[(size_t)(b * L_ + t0 + ty + j) * NINP_ + i0 + tx] =
            __float2half_rn(tile[tx][ty + j]);
}

__global__ void init_state(const float* __restrict__ z0) {
    int idx = blockIdx.x * blockDim.x + threadIdx.x;
    if (idx < H_ * N_) { g_hh0[idx] = __half(0.0f); g_c0[idx] = 0.0f; }
    if (idx < B_ * H_) {
        int b = idx / H_, ch = idx - b * H_;
        g_z0h[idx] = __float2half_rn(z0[b * (2 * H_) + ch]);
    }
}

// ===========================================================================
// Fused GEMM (fp16 mma.sync + ldmatrix), 128(n)x128(m), BK=32, 3 stages,
// 2 CTAs/SM (smem 60 KB, regs capped at 128).
// ===========================================================================
#define BK      32
#define KS      40                       // padded row stride (halfs), 80B
#define STG_A   (128 * KS)               // halfs per A stage
#define STG_SZ  (2 * 128 * KS)           // halfs per stage (A+B)
#define NSTAGE  3
#define PS      132                      // pre_s row stride (floats)
#define SMEM_BYTES (NSTAGE * STG_SZ * 2) // 61440

template <int KTOT, bool INJECT>
__global__ __launch_bounds__(256, 2)
void gemm_fused(const float* __restrict__ z0, int rd) {
    extern __shared__ __half smh[];
    constexpr int KHALF = KTOT / 2;
    constexpr int NKT = KTOT / BK;

    const __half* __restrict__ Asrc = INJECT ? g_Xt : (rd ? g_hh1 : g_hh0);
    const __half* __restrict__ Bw   = INJECT ? g_Wi2 : g_Wc2;

    const int tid  = threadIdx.x;
    const int wid  = tid >> 5;
    const int lane = tid & 31;
    const int grp  = lane >> 2;
    const int qid  = lane & 3;
    const int n0   = blockIdx.x * 128;
    const int m0   = blockIdx.y * 128;

    const int wn = (wid >> 2) * 64;
    const int wm = (wid & 3) * 32;

    const uint32_t sbase = smem_u32(smh);
    const int lrow = lane & 15;
    const int lcol = (lane >> 4) << 3;

#define LOAD_STAGE(S, K0)                                                        \
    do {                                                                         \
        const int _k0 = (K0);                                                    \
        const uint32_t aoff = ((S) % NSTAGE) * STG_SZ;                           \
        const uint32_t boff = aoff + STG_A;                                      \
        _Pragma("unroll")                                                        \
        for (int j = 0; j < 2; j++) {                                            \
            int idx = tid + j * 256;         /* 0..511 */                        \
            int r  = idx >> 2;                                                   \
            int c8 = idx & 3;                                                    \
            int kk = _k0 + c8 * 8;                                               \
            {                                                                    \
                int n = n0 + r;                                                  \
                int t = n & (L_ - 1);                                            \
                int b = n >> 10;                                                 \
                uint32_t dst = sbase + (aoff + r * KS + c8 * 8) * 2;             \
                if (kk < KHALF) {                                                \
                    if (t == 0) {                                                \
                        if (INJECT) cp_async16_zero(dst, Asrc);                  \
                        else cp_async16(dst, g_z0h + b * H_ + kk);               \
                    } else {                                                     \
                        cp_async16(dst, Asrc + (size_t)(n - 1) * KHALF + kk);    \
                    }                                                            \
                } else {                                                         \
                    cp_async16(dst, Asrc + (size_t)n * KHALF + (kk - KHALF));    \
                }                                                                \
            }                                                                    \
            {                                                                    \
                uint32_t dst = sbase + (boff + r * KS + c8 * 8) * 2;             \
                cp_async16(dst, Bw + (size_t)(m0 + r) * KTOT + kk);              \
            }                                                                    \
        }                                                                        \
        cp_commit();                                                             \
    } while (0)

    // prologue
#pragma unroll
    for (int s = 0; s < NSTAGE - 1; s++) LOAD_STAGE(s, s * BK);

    float acc[4][4][4];
#pragma unroll
    for (int i = 0; i < 4; i++)
#pragma unroll
        for (int j = 0; j < 4; j++)
#pragma unroll
            for (int e = 0; e < 4; e++) acc[i][j][e] = 0.0f;

#pragma unroll 1
    for (int kt = 0; kt < NKT; kt++) {
        cp_wait<NSTAGE - 2>();
        __syncthreads();

        const int sf = kt + NSTAGE - 1;
        if (sf < NKT) LOAD_STAGE(sf, sf * BK);
        else cp_commit();

        const uint32_t a_base = sbase + (uint32_t)((kt % NSTAGE) * STG_SZ) * 2;
        const uint32_t b_base = a_base + STG_A * 2;

#pragma unroll
        for (int ks = 0; ks < BK; ks += 16) {
            uint32_t af[4][4];
            uint32_t bf[2][4];
#pragma unroll
            for (int fi = 0; fi < 4; fi++) {
                uint32_t addr = a_base +
                    (uint32_t)((wn + fi * 16 + lrow) * KS + ks + lcol) * 2;
                ldmatrix_x4(af[fi], addr);
            }
#pragma unroll
            for (int fh = 0; fh < 2; fh++) {
                uint32_t addr = b_base +
                    (uint32_t)((wm + fh * 16 + lrow) * KS + ks + lcol) * 2;
                ldmatrix_x4(bf[fh], addr);
            }
#pragma unroll
            for (int fi = 0; fi < 4; fi++) {
#pragma unroll
                for (int fh = 0; fh < 2; fh++) {
#pragma unroll
                    for (int s2 = 0; s2 < 2; s2++) {
                        int fj = fh * 2 + s2;
                        mma_f16(acc[fi][fj][0], acc[fi][fj][1],
                                acc[fi][fj][2], acc[fi][fj][3],
                                af[fi][0], af[fi][1], af[fi][2], af[fi][3],
                                bf[fh][s2], bf[fh][s2 + 2]);
                    }
                }
            }
        }
    }

    if (INJECT) {
#pragma unroll
        for (int fi = 0; fi < 4; fi++) {
#pragma unroll
            for (int fj = 0; fj < 4; fj++) {
                int n1 = n0 + wn + fi * 16 + grp;
                int m  = m0 + wm + fj * 8 + qid * 2;
                float b0 = g_bias[m], b1 = g_bias[m + 1];
                *(float2*)(g_us + (size_t)n1 * M4_ + m) =
                    make_float2(acc[fi][fj][0] + b0, acc[fi][fj][1] + b1);
                *(float2*)(g_us + (size_t)(n1 + 8) * M4_ + m) =
                    make_float2(acc[fi][fj][2] + b0, acc[fi][fj][3] + b1);
            }
        }
        return;
    }

    // ------------- fused gating epilogue, 2 passes of 64 n-rows -------------
    float* pre_s = (float*)smh;      // 64 x PS floats = 33.8 KB <= 60 KB
    const float* __restrict__ cpb = rd ? g_c1 : g_c0;
    float* __restrict__ cn = rd ? g_c0 : g_c1;
    __half* __restrict__ hhn = rd ? g_hh0 : g_hh1;
    const int chbase = blockIdx.y * 32;
    const int q  = tid & 7;
    const int nl = tid >> 3;

#pragma unroll
    for (int p = 0; p < 2; p++) {
        __syncthreads();             // smem free (mainloop or prev pass done)
        if ((wid >> 2) == p) {
#pragma unroll
            for (int fi = 0; fi < 4; fi++) {
#pragma unroll
                for (int fj = 0; fj < 4; fj++) {
                    int r0   = fi * 16 + grp;          // 0..63 within pass
                    int cidx = wm + fj * 8 + qid * 2;
                    *(float2*)&pre_s[r0 * PS + cidx] =
                        make_float2(acc[fi][fj][0], acc[fi][fj][1]);
                    *(float2*)&pre_s[(r0 + 8) * PS + cidx] =
                        make_float2(acc[fi][fj][2], acc[fi][fj][3]);
                }
            }
        }
        __syncthreads();

#pragma unroll
        for (int it = 0; it < 2; it++) {
            int row = nl + it * 32;          // 0..63
            int n = n0 + p * 64 + row;
            int t = n & (L_ - 1);
            int b = n >> 10;
            int ch = chbase + q * 4;

            float4 pi4 = *(const float4*)&pre_s[row * PS + 0 * 32 + q * 4];
            float4 po4 = *(const float4*)&pre_s[row * PS + 1 * 32 + q * 4];
            float4 pg4 = *(const float4*)&pre_s[row * PS + 2 * 32 + q * 4];
            float4 pf4 = *(const float4*)&pre_s[row * PS + 3 * 32 + q * 4];
            const size_t ub = (size_t)n * M4_;
            float4 ui4 = *(const float4*)(g_us + ub + 0 * H_ + ch);
            float4 uo4 = *(const float4*)(g_us + ub + 1 * H_ + ch);
            float4 ug4 = *(const float4*)(g_us + ub + 2 * H_ + ch);
            float4 uf4 = *(const float4*)(g_us + ub + 3 * H_ + ch);
            float4 cpv;
            if (t == 0) cpv = *(const float4*)(z0 + b * (2 * H_) + H_ + ch);
            else        cpv = *(const float4*)(cpb + (size_t)(n - 1) * H_ + ch);

            const float* pip = (const float*)&pi4;
            const float* pop = (const float*)&po4;
            const float* pgp = (const float*)&pg4;
            const float* pfp = (const float*)&pf4;
            const float* uip = (const float*)&ui4;
            const float* uop = (const float*)&uo4;
            const float* ugp = (const float*)&ug4;
            const float* ufp = (const float*)&uf4;
            const float* cpl = (const float*)&cpv;

            float4 hv, cv;
            float* hvp = (float*)&hv;
            float* cvp = (float*)&cv;
#pragma unroll
            for (int e = 0; e < 4; e++) {
                float pi = pip[e] + uip[e];
                float po = pop[e] + uop[e];
                float pg = pgp[e] + ugp[e];
                float pf = pfp[e] + ufp[e];
                float si = 1.0f / (1.0f + __expf(-pi));
                float so = 1.0f / (1.0f + __expf(-po));
                float sf = 1.0f / (1.0f + __expf(-pf));
                float tg = tanhf(pg);
                float c = sf * cpl[e] + si * tg;
                float h = so * tanhf(c);
                hvp[e] = h;
                cvp[e] = c;
            }
            *(float4*)(g_h0 + (size_t)n * H_ + ch) = hv;
            *(float4*)(cn + (size_t)n * H_ + ch) = cv;
            __half2 h01 = __floats2half2_rn(hvp[0], hvp[1]);
            __half2 h23 = __floats2half2_rn(hvp[2], hvp[3]);
            *(__half2*)(hhn + (size_t)n * H_ + ch)     = h01;
            *(__half2*)(hhn + (size_t)n * H_ + ch + 2) = h23;
        }
    }
#undef LOAD_STAGE
}

// ===========================================================================
// Outputs
// ===========================================================================
__global__ void write_out(float* __restrict__ out) {
    int idx = blockIdx.x * blockDim.x + threadIdx.x;
    const int total = B_ * L_ * NOUT_;
    if (idx < total) {
        int j = idx & (NOUT_ - 1);
        int n = idx >> 8;
        out[idx] = g_h0[(size_t)n * H_ + (H_ - NOUT_) + j];
    }
    if (idx < B_ * 2 * H_) {
        int ch = idx % (2 * H_);
        int b  = idx / (2 * H_);
        int n  = b * L_ + (L_ - 1);
        float v = (ch < H_) ? g_h0[(size_t)n * H_ + ch]
                            : g_c0[(size_t)n * H_ + (ch - H_)];
        out[total + idx] = v;
    }
}

// ===========================================================================
extern "C" void kernel_launch(void* const* d_in, const int* in_sizes, int n_in,
                              void* d_out, int out_size) {
    const float* X        = (const float*)d_in[0];
    const float* z0       = (const float*)d_in[1];
    const float* inject_w = (const float*)d_in[2];
    const float* inject_b = (const float*)d_in[3];
    const float* conv_w   = (const float*)d_in[4];
    const float* conv_b   = (const float*)d_in[5];
    float* out = (float*)d_out;

    cudaFuncSetAttribute(gemm_fused<KI_, true>,
                         cudaFuncAttributeMaxDynamicSharedMemorySize, SMEM_BYTES);
    cudaFuncSetAttribute(gemm_fused<KC_, false>,
                         cudaFuncAttributeMaxDynamicSharedMemorySize, SMEM_BYTES);

    repack_conv2<<<(M4_ * KC_ + 255) / 256, 256>>>(conv_w);
    repack_inj2<<<(M4_ * KI_ + 255) / 256, 256>>>(inject_w, inject_b, conv_b);
    transpose_x<<<dim3(L_ / 32, NINP_ / 32, B_), dim3(32, 8)>>>(X);
    init_state<<<(H_ * N_ + 255) / 256, 256>>>(z0);

    gemm_fused<KI_, true><<<dim3(N_ / 128, M4_ / 128), 256, SMEM_BYTES>>>(z0, 0);

    for (int l = 0; l < NLAYER_; l++)
        gemm_fused<KC_, false><<<dim3(N_ / 128, M4_ / 128), 256, SMEM_BYTES>>>(z0, l & 1);

    write_out<<<(B_ * L_ * NOUT_ + 255) / 256, 256>>>(out);
}

// round 8
// speedup vs baseline: 7.3986x; 1.0304x over previous
#include <cuda_runtime.h>
#include <cuda_fp16.h>
#include <math.h>
#include <cstdint>

// Problem constants
#define B_    4
#define H_    768
#define L_    1024
#define N_    4096          // B_*L_
#define M4_   3072          // 4*H_
#define NINP_ 512
#define KC_   1536          // conv K  ([h(t-1); h(t)])
#define KI_   1024          // inject K ([x(t-1); x(t)])
#define NOUT_ 256
#define NLAYER_ 10

// Scratch (device globals; no allocation allowed)
__device__ __half g_us2[(size_t)N_ * M4_]; // us[n][m] fp16, plain order, biases folded
__device__ float g_h0[(size_t)N_ * H_];    // h fp32 (last layer only)
__device__ float g_c0[(size_t)N_ * H_];
__device__ float g_c1[(size_t)N_ * H_];
__device__ __half g_hh0[(size_t)N_ * H_];  // h fp16 mirror (GEMM A input)
__device__ __half g_hh1[(size_t)N_ * H_];
__device__ __half g_Wc2[(size_t)M4_ * KC_]; // conv W fp16, gate-interleaved rows
__device__ __half g_Wi2[(size_t)M4_ * KI_]; // inject W fp16, plain rows
__device__ __half g_Xt[(size_t)N_ * NINP_]; // X fp16, time-major [n][i]
__device__ __half g_z0h[B_ * H_];           // z0 h-part fp16
__device__ float  g_bias[M4_];              // inject_b + conv_b

// ===========================================================================
// Helpers
// ===========================================================================
__device__ __forceinline__ uint32_t smem_u32(const void* p) {
    uint32_t a;
    asm("{ .reg .u64 t; cvta.to.shared.u64 t, %1; cvt.u32.u64 %0, t; }"
        : "=r"(a) : "l"(p));
    return a;
}
__device__ __forceinline__ void cp_async16(uint32_t dst, const void* src) {
    asm volatile("cp.async.cg.shared.global [%0], [%1], 16;" :: "r"(dst), "l"(src));
}
__device__ __forceinline__ void cp_async16_zero(uint32_t dst, const void* src) {
    asm volatile("cp.async.cg.shared.global [%0], [%1], 16, 0;" :: "r"(dst), "l"(src));
}
__device__ __forceinline__ void cp_commit() {
    asm volatile("cp.async.commit_group;");
}
template <int Npend>
__device__ __forceinline__ void cp_wait() {
    asm volatile("cp.async.wait_group %0;" :: "n"(Npend));
}
__device__ __forceinline__ void ldmatrix_x4(uint32_t* r, uint32_t addr) {
    asm volatile("ldmatrix.sync.aligned.m8n8.x4.shared.b16 {%0,%1,%2,%3}, [%4];"
        : "=r"(r[0]), "=r"(r[1]), "=r"(r[2]), "=r"(r[3]) : "r"(addr));
}
__device__ __forceinline__ void mma_f16(float& c0, float& c1, float& c2, float& c3,
                                        uint32_t a0, uint32_t a1, uint32_t a2, uint32_t a3,
                                        uint32_t b0, uint32_t b1) {
    asm volatile(
        "mma.sync.aligned.m16n8k16.row.col.f32.f16.f16.f32 "
        "{%0,%1,%2,%3}, {%4,%5,%6,%7}, {%8,%9}, {%0,%1,%2,%3};"
        : "+f"(c0), "+f"(c1), "+f"(c2), "+f"(c3)
        : "r"(a0), "r"(a1), "r"(a2), "r"(a3), "r"(b0), "r"(b1));
}
__device__ __forceinline__ float tanh_fast(float x) {
    float r;
    asm("tanh.approx.f32 %0, %1;" : "=f"(r) : "f"(x));
    return r;
}

// ===========================================================================
// Repacks / transpose / init
// ===========================================================================
__global__ void repack_conv2(const float* __restrict__ conv_w) {
    int idx = blockIdx.x * blockDim.x + threadIdx.x;
    if (idx >= M4_ * KC_) return;
    int mp = idx / KC_;
    int k  = idx - mp * KC_;
    int y  = mp >> 7;
    int rr = mp & 127;
    int g  = rr >> 5;
    int cl = rr & 31;
    int m  = g * H_ + y * 32 + cl;
    int tap = (k >= H_) ? 1 : 0;
    int i = k - tap * H_;
    g_Wc2[idx] = __float2half_rn(conv_w[m * (H_ * 2) + i * 2 + tap]);
}

__global__ void repack_inj2(const float* __restrict__ inject_w,
                            const float* __restrict__ inject_b,
                            const float* __restrict__ conv_b) {
    int idx = blockIdx.x * blockDim.x + threadIdx.x;
    if (idx >= M4_ * KI_) return;
    int m = idx / KI_;
    int k = idx - m * KI_;
    int tap = (k >= NINP_) ? 1 : 0;
    int i = k - tap * NINP_;
    g_Wi2[idx] = __float2half_rn(inject_w[m * (NINP_ * 2) + i * 2 + tap]);
    if (k == 0) g_bias[m] = inject_b[m] + conv_b[m];
}

__global__ void transpose_x(const float* __restrict__ X) {
    __shared__ float tile[32][33];
    int b  = blockIdx.z;
    int i0 = blockIdx.y * 32;
    int t0 = blockIdx.x * 32;
    int tx = threadIdx.x, ty = threadIdx.y;
#pragma unroll
    for (int j = 0; j < 32; j += 8)
        tile[ty + j][tx] = X[(size_t)(b * NINP_ + i0 + ty + j) * L_ + t0 + tx];
    __syncthreads();
#pragma unroll
    for (int j = 0; j < 32; j += 8)
        g_Xt[(size_t)(b * L_ + t0 + ty + j) * NINP_ + i0 + tx] =
            __float2half_rn(tile[tx][ty + j]);
}

__global__ void init_state(const float* __restrict__ z0) {
    int idx = blockIdx.x * blockDim.x + threadIdx.x;
    if (idx < H_ * N_) { g_hh0[idx] = __half(0.0f); g_c0[idx] = 0.0f; }
    if (idx < B_ * H_) {
        int b = idx / H_, ch = idx - b * H_;
        g_z0h[idx] = __float2half_rn(z0[b * (2 * H_) + ch]);
    }
}

// ===========================================================================
// Fused GEMM (fp16 mma.sync + ldmatrix), 128(n)x128(m), BK=32, 3 stages,
// 2 CTAs/SM. Layer epilogue stages us (fp16) through smem via cp.async.
// ===========================================================================
#define BK      32
#define KS      40                       // padded row stride (halfs), 80B
#define STG_A   (128 * KS)               // halfs per A stage
#define STG_SZ  (2 * 128 * KS)           // halfs per stage (A+B)
#define NSTAGE  3
#define SMEM_BYTES (NSTAGE * STG_SZ * 2) // 61440
// epilogue smem layout (per 64-row pass)
#define USS     160                      // us_s row stride in halfs (320B; 80 words)
#define PS      136                      // pre_s row stride in floats
#define PRE_OFF 5120                     // float offset of pre_s (byte 20480)

template <int KTOT, bool INJECT>
__global__ __launch_bounds__(256, 2)
void gemm_fused(const float* __restrict__ z0, int rd, int last) {
    extern __shared__ __half smh[];
    constexpr int KHALF = KTOT / 2;
    constexpr int NKT = KTOT / BK;

    const __half* __restrict__ Asrc = INJECT ? g_Xt : (rd ? g_hh1 : g_hh0);
    const __half* __restrict__ Bw   = INJECT ? g_Wi2 : g_Wc2;

    const int tid  = threadIdx.x;
    const int wid  = tid >> 5;
    const int lane = tid & 31;
    const int grp  = lane >> 2;
    const int qid  = lane & 3;
    const int n0   = blockIdx.x * 128;
    const int m0   = blockIdx.y * 128;

    const int wn = (wid >> 2) * 64;
    const int wm = (wid & 3) * 32;

    const uint32_t sbase = smem_u32(smh);
    const int lrow = lane & 15;
    const int lcol = (lane >> 4) << 3;

#define LOAD_STAGE(S, K0)                                                        \
    do {                                                                         \
        const int _k0 = (K0);                                                    \
        const uint32_t aoff = ((S) % NSTAGE) * STG_SZ;                           \
        const uint32_t boff = aoff + STG_A;                                      \
        _Pragma("unroll")                                                        \
        for (int j = 0; j < 2; j++) {                                            \
            int idx = tid + j * 256;         /* 0..511 */                        \
            int r  = idx >> 2;                                                   \
            int c8 = idx & 3;                                                    \
            int kk = _k0 + c8 * 8;                                               \
            {                                                                    \
                int n = n0 + r;                                                  \
                int t = n & (L_ - 1);                                            \
                int b = n >> 10;                                                 \
                uint32_t dst = sbase + (aoff + r * KS + c8 * 8) * 2;             \
                if (kk < KHALF) {                                                \
                    if (t == 0) {                                                \
                        if (INJECT) cp_async16_zero(dst, Asrc);                  \
                        else cp_async16(dst, g_z0h + b * H_ + kk);               \
                    } else {                                                     \
                        cp_async16(dst, Asrc + (size_t)(n - 1) * KHALF + kk);    \
                    }                                                            \
                } else {                                                         \
                    cp_async16(dst, Asrc + (size_t)n * KHALF + (kk - KHALF));    \
                }                                                                \
            }                                                                    \
            {                                                                    \
                uint32_t dst = sbase + (boff + r * KS + c8 * 8) * 2;             \
                cp_async16(dst, Bw + (size_t)(m0 + r) * KTOT + kk);              \
            }                                                                    \
        }                                                                        \
        cp_commit();                                                             \
    } while (0)

    // prologue
#pragma unroll
    for (int s = 0; s < NSTAGE - 1; s++) LOAD_STAGE(s, s * BK);

    float acc[4][4][4];
#pragma unroll
    for (int i = 0; i < 4; i++)
#pragma unroll
        for (int j = 0; j < 4; j++)
#pragma unroll
            for (int e = 0; e < 4; e++) acc[i][j][e] = 0.0f;

#pragma unroll 1
    for (int kt = 0; kt < NKT; kt++) {
        cp_wait<NSTAGE - 2>();
        __syncthreads();

        const int sf = kt + NSTAGE - 1;
        if (sf < NKT) LOAD_STAGE(sf, sf * BK);
        else cp_commit();

        const uint32_t a_base = sbase + (uint32_t)((kt % NSTAGE) * STG_SZ) * 2;
        const uint32_t b_base = a_base + STG_A * 2;

#pragma unroll
        for (int ks = 0; ks < BK; ks += 16) {
            uint32_t af[4][4];
            uint32_t bf[2][4];
#pragma unroll
            for (int fi = 0; fi < 4; fi++) {
                uint32_t addr = a_base +
                    (uint32_t)((wn + fi * 16 + lrow) * KS + ks + lcol) * 2;
                ldmatrix_x4(af[fi], addr);
            }
#pragma unroll
            for (int fh = 0; fh < 2; fh++) {
                uint32_t addr = b_base +
                    (uint32_t)((wm + fh * 16 + lrow) * KS + ks + lcol) * 2;
                ldmatrix_x4(bf[fh], addr);
            }
#pragma unroll
            for (int fi = 0; fi < 4; fi++) {
#pragma unroll
                for (int fh = 0; fh < 2; fh++) {
#pragma unroll
                    for (int s2 = 0; s2 < 2; s2++) {
                        int fj = fh * 2 + s2;
                        mma_f16(acc[fi][fj][0], acc[fi][fj][1],
                                acc[fi][fj][2], acc[fi][fj][3],
                                af[fi][0], af[fi][1], af[fi][2], af[fi][3],
                                bf[fh][s2], bf[fh][s2 + 2]);
                    }
                }
            }
        }
    }

    if (INJECT) {
        // store us = fp16(acc + bias), plain layout
#pragma unroll
        for (int fi = 0; fi < 4; fi++) {
#pragma unroll
            for (int fj = 0; fj < 4; fj++) {
                int n1 = n0 + wn + fi * 16 + grp;
                int m  = m0 + wm + fj * 8 + qid * 2;
                float b0 = g_bias[m], b1 = g_bias[m + 1];
                *(__half2*)(g_us2 + (size_t)n1 * M4_ + m) =
                    __floats2half2_rn(acc[fi][fj][0] + b0, acc[fi][fj][1] + b1);
                *(__half2*)(g_us2 + (size_t)(n1 + 8) * M4_ + m) =
                    __floats2half2_rn(acc[fi][fj][2] + b0, acc[fi][fj][3] + b1);
            }
        }
        return;
    }

    // ------------- fused gating epilogue, 2 passes of 64 n-rows -------------
    // smem per pass: us_s (fp16, 64 x USS) at 0, pre_s (fp32, 64 x PS) at PRE_OFF
    __half* us_s = smh;
    float*  pre_s = (float*)smh + PRE_OFF;
    const float* __restrict__ cpb = rd ? g_c1 : g_c0;
    float* __restrict__ cn = rd ? g_c0 : g_c1;
    __half* __restrict__ hhn = rd ? g_hh0 : g_hh1;
    const int chbase = blockIdx.y * 32;
    const int q  = tid & 7;
    const int nl = tid >> 3;

#pragma unroll
    for (int p = 0; p < 2; p++) {
        __syncthreads();             // smem free (mainloop or prev pass done)

        // stage us rows [p*64, p*64+64) : 1024 16B chunks, 4 per thread
#pragma unroll
        for (int j = 0; j < 4; j++) {
            int id = tid + j * 256;
            int row = id >> 4;               // 0..63
            int g   = (id >> 2) & 3;
            int c   = id & 3;
            int n = n0 + p * 64 + row;
            cp_async16(sbase + (uint32_t)(row * USS + g * 32 + c * 8) * 2,
                       g_us2 + (size_t)n * M4_ + g * H_ + chbase + c * 8);
        }
        cp_commit();

        // stage pre-activations for this pass's rows
        if ((wid >> 2) == p) {
#pragma unroll
            for (int fi = 0; fi < 4; fi++) {
#pragma unroll
                for (int fj = 0; fj < 4; fj++) {
                    int r0   = fi * 16 + grp;          // 0..63 within pass
                    int cidx = wm + fj * 8 + qid * 2;
                    *(float2*)&pre_s[r0 * PS + cidx] =
                        make_float2(acc[fi][fj][0], acc[fi][fj][1]);
                    *(float2*)&pre_s[(r0 + 8) * PS + cidx] =
                        make_float2(acc[fi][fj][2], acc[fi][fj][3]);
                }
            }
        }
        cp_wait<0>();
        __syncthreads();

#pragma unroll
        for (int it = 0; it < 2; it++) {
            int row = nl + it * 32;          // 0..63
            int n = n0 + p * 64 + row;
            int t = n & (L_ - 1);
            int b = n >> 10;
            int ch = chbase + q * 4;

            float4 pi4 = *(const float4*)&pre_s[row * PS + 0 * 32 + q * 4];
            float4 po4 = *(const float4*)&pre_s[row * PS + 1 * 32 + q * 4];
            float4 pg4 = *(const float4*)&pre_s[row * PS + 2 * 32 + q * 4];
            float4 pf4 = *(const float4*)&pre_s[row * PS + 3 * 32 + q * 4];

            const __half* ur = us_s + row * USS + q * 4;
            __half2 ui01 = *(const __half2*)(ur + 0 * 32);
            __half2 ui23 = *(const __half2*)(ur + 0 * 32 + 2);
            __half2 uo01 = *(const __half2*)(ur + 1 * 32);
            __half2 uo23 = *(const __half2*)(ur + 1 * 32 + 2);
            __half2 ug01 = *(const __half2*)(ur + 2 * 32);
            __half2 ug23 = *(const __half2*)(ur + 2 * 32 + 2);
            __half2 uf01 = *(const __half2*)(ur + 3 * 32);
            __half2 uf23 = *(const __half2*)(ur + 3 * 32 + 2);
            float2 uiA = __half22float2(ui01), uiB = __half22float2(ui23);
            float2 uoA = __half22float2(uo01), uoB = __half22float2(uo23);
            float2 ugA = __half22float2(ug01), ugB = __half22float2(ug23);
            float2 ufA = __half22float2(uf01), ufB = __half22float2(uf23);
            float ui[4] = {uiA.x, uiA.y, uiB.x, uiB.y};
            float uo[4] = {uoA.x, uoA.y, uoB.x, uoB.y};
            float ug[4] = {ugA.x, ugA.y, ugB.x, ugB.y};
            float uf[4] = {ufA.x, ufA.y, ufB.x, ufB.y};

            float4 cpv;
            if (t == 0) cpv = *(const float4*)(z0 + b * (2 * H_) + H_ + ch);
            else        cpv = *(const float4*)(cpb + (size_t)(n - 1) * H_ + ch);

            const float* pip = (const float*)&pi4;
            const float* pop = (const float*)&po4;
            const float* pgp = (const float*)&pg4;
            const float* pfp = (const float*)&pf4;
            const float* cpl = (const float*)&cpv;

            float4 hv, cv;
            float* hvp = (float*)&hv;
            float* cvp = (float*)&cv;
#pragma unroll
            for (int e = 0; e < 4; e++) {
                float pi = pip[e] + ui[e];
                float po = pop[e] + uo[e];
                float pg = pgp[e] + ug[e];
                float pf = pfp[e] + uf[e];
                float si = 1.0f / (1.0f + __expf(-pi));
                float so = 1.0f / (1.0f + __expf(-po));
                float sf = 1.0f / (1.0f + __expf(-pf));
                float tg = tanh_fast(pg);
                float c = sf * cpl[e] + si * tg;
                float h = so * tanh_fast(c);
                hvp[e] = h;
                cvp[e] = c;
            }
            *(float4*)(cn + (size_t)n * H_ + ch) = cv;
            if (last) {
                *(float4*)(g_h0 + (size_t)n * H_ + ch) = hv;
            } else {
                __half2 h01 = __floats2half2_rn(hvp[0], hvp[1]);
                __half2 h23 = __floats2half2_rn(hvp[2], hvp[3]);
                *(__half2*)(hhn + (size_t)n * H_ + ch)     = h01;
                *(__half2*)(hhn + (size_t)n * H_ + ch + 2) = h23;
            }
        }
    }
#undef LOAD_STAGE
}

// ===========================================================================
// Outputs
// ===========================================================================
__global__ void write_out(float* __restrict__ out) {
    int idx = blockIdx.x * blockDim.x + threadIdx.x;
    const int total = B_ * L_ * NOUT_;
    if (idx < total) {
        int j = idx & (NOUT_ - 1);
        int n = idx >> 8;
        out[idx] = g_h0[(size_t)n * H_ + (H_ - NOUT_) + j];
    }
    if (idx < B_ * 2 * H_) {
        int ch = idx % (2 * H_);
        int b  = idx / (2 * H_);
        int n  = b * L_ + (L_ - 1);
        float v = (ch < H_) ? g_h0[(size_t)n * H_ + ch]
                            : g_c0[(size_t)n * H_ + (ch - H_)];
        out[total + idx] = v;
    }
}

// ===========================================================================
extern "C" void kernel_launch(void* const* d_in, const int* in_sizes, int n_in,
                              void* d_out, int out_size) {
    const float* X        = (const float*)d_in[0];
    const float* z0       = (const float*)d_in[1];
    const float* inject_w = (const float*)d_in[2];
    const float* inject_b = (const float*)d_in[3];
    const float* conv_w   = (const float*)d_in[4];
    const float* conv_b   = (const float*)d_in[5];
    float* out = (float*)d_out;

    cudaFuncSetAttribute(gemm_fused<KI_, true>,
                         cudaFuncAttributeMaxDynamicSharedMemorySize, SMEM_BYTES);
    cudaFuncSetAttribute(gemm_fused<KC_, false>,
                         cudaFuncAttributeMaxDynamicSharedMemorySize, SMEM_BYTES);

    repack_conv2<<<(M4_ * KC_ + 255) / 256, 256>>>(conv_w);
    repack_inj2<<<(M4_ * KI_ + 255) / 256, 256>>>(inject_w, inject_b, conv_b);
    transpose_x<<<dim3(L_ / 32, NINP_ / 32, B_), dim3(32, 8)>>>(X);
    init_state<<<(H_ * N_ + 255) / 256, 256>>>(z0);

    gemm_fused<KI_, true><<<dim3(N_ / 128, M4_ / 128), 256, SMEM_BYTES>>>(z0, 0, 0);

    for (int l = 0; l < NLAYER_; l++)
        gemm_fused<KC_, false><<<dim3(N_ / 128, M4_ / 128), 256, SMEM_BYTES>>>(
            z0, l & 1, l == NLAYER_ - 1);

    write_out<<<(B_ * L_ * NOUT_ + 255) / 256, 256>>>(out);
}

// round 9
// speedup vs baseline: 8.1608x; 1.1030x over previous
#include <cuda_runtime.h>
#include <cuda_fp16.h>
#include <math.h>
#include <cstdint>

// Problem constants
#define B_    4
#define H_    768
#define L_    1024
#define N_    4096          // B_*L_
#define M4_   3072          // 4*H_
#define NINP_ 512
#define KC_   1536          // conv K  ([h(t-1); h(t)])
#define KI_   1024          // inject K ([x(t-1); x(t)])
#define NOUT_ 256
#define NLAYER_ 10

// Scratch (device globals; no allocation allowed)
__device__ __half g_us2[(size_t)N_ * M4_]; // us[n][m] fp16, plain order, biases folded
__device__ float g_c0[(size_t)N_ * H_];
__device__ float g_c1[(size_t)N_ * H_];
__device__ __half g_hh0[(size_t)N_ * H_];  // h fp16 mirror (GEMM A input)
__device__ __half g_hh1[(size_t)N_ * H_];
__device__ __half g_Wc2[(size_t)M4_ * KC_]; // conv W fp16, gate-interleaved rows
__device__ __half g_Wi2[(size_t)M4_ * KI_]; // inject W fp16, plain rows
__device__ __half g_Xt[(size_t)N_ * NINP_]; // X fp16, time-major [n][i]
__device__ __half g_z0h[B_ * H_];           // z0 h-part fp16
__device__ float  g_bias[M4_];              // inject_b + conv_b
__device__ float  g_pre0[B_ * M4_];         // layer-0 t==0 correction: W0 @ z0h

// ===========================================================================
// Helpers
// ===========================================================================
__device__ __forceinline__ uint32_t smem_u32(const void* p) {
    uint32_t a;
    asm("{ .reg .u64 t; cvta.to.shared.u64 t, %1; cvt.u32.u64 %0, t; }"
        : "=r"(a) : "l"(p));
    return a;
}
__device__ __forceinline__ void cp_async16(uint32_t dst, const void* src) {
    asm volatile("cp.async.cg.shared.global [%0], [%1], 16;" :: "r"(dst), "l"(src));
}
__device__ __forceinline__ void cp_async16_zero(uint32_t dst, const void* src) {
    asm volatile("cp.async.cg.shared.global [%0], [%1], 16, 0;" :: "r"(dst), "l"(src));
}
__device__ __forceinline__ void cp_commit() {
    asm volatile("cp.async.commit_group;");
}
template <int Npend>
__device__ __forceinline__ void cp_wait() {
    asm volatile("cp.async.wait_group %0;" :: "n"(Npend));
}
__device__ __forceinline__ void ldmatrix_x4(uint32_t* r, uint32_t addr) {
    asm volatile("ldmatrix.sync.aligned.m8n8.x4.shared.b16 {%0,%1,%2,%3}, [%4];"
        : "=r"(r[0]), "=r"(r[1]), "=r"(r[2]), "=r"(r[3]) : "r"(addr));
}
__device__ __forceinline__ void mma_f16(float& c0, float& c1, float& c2, float& c3,
                                        uint32_t a0, uint32_t a1, uint32_t a2, uint32_t a3,
                                        uint32_t b0, uint32_t b1) {
    asm volatile(
        "mma.sync.aligned.m16n8k16.row.col.f32.f16.f16.f32 "
        "{%0,%1,%2,%3}, {%4,%5,%6,%7}, {%8,%9}, {%0,%1,%2,%3};"
        : "+f"(c0), "+f"(c1), "+f"(c2), "+f"(c3)
        : "r"(a0), "r"(a1), "r"(a2), "r"(a3), "r"(b0), "r"(b1));
}
__device__ __forceinline__ float tanh_fast(float x) {
    float r;
    asm("tanh.approx.f32 %0, %1;" : "=f"(r) : "f"(x));
    return r;
}

// ===========================================================================
// Repacks / transpose / init
// ===========================================================================
__global__ void repack_conv2(const float* __restrict__ conv_w) {
    int idx = blockIdx.x * blockDim.x + threadIdx.x;
    if (idx >= M4_ * KC_) return;
    int mp = idx / KC_;
    int k  = idx - mp * KC_;
    int y  = mp >> 7;
    int rr = mp & 127;
    int g  = rr >> 5;
    int cl = rr & 31;
    int m  = g * H_ + y * 32 + cl;
    int tap = (k >= H_) ? 1 : 0;
    int i = k - tap * H_;
    g_Wc2[idx] = __float2half_rn(conv_w[m * (H_ * 2) + i * 2 + tap]);
}

__global__ void repack_inj2(const float* __restrict__ inject_w,
                            const float* __restrict__ inject_b,
                            const float* __restrict__ conv_b) {
    int idx = blockIdx.x * blockDim.x + threadIdx.x;
    if (idx >= M4_ * KI_) return;
    int m = idx / KI_;
    int k = idx - m * KI_;
    int tap = (k >= NINP_) ? 1 : 0;
    int i = k - tap * NINP_;
    g_Wi2[idx] = __float2half_rn(inject_w[m * (NINP_ * 2) + i * 2 + tap]);
    if (k == 0) g_bias[m] = inject_b[m] + conv_b[m];
}

__global__ void transpose_x(const float* __restrict__ X) {
    __shared__ float tile[32][33];
    int b  = blockIdx.z;
    int i0 = blockIdx.y * 32;
    int t0 = blockIdx.x * 32;
    int tx = threadIdx.x, ty = threadIdx.y;
#pragma unroll
    for (int j = 0; j < 32; j += 8)
        tile[ty + j][tx] = X[(size_t)(b * NINP_ + i0 + ty + j) * L_ + t0 + tx];
    __syncthreads();
#pragma unroll
    for (int j = 0; j < 32; j += 8)
        g_Xt[(size_t)(b * L_ + t0 + ty + j) * NINP_ + i0 + tx] =
            __float2half_rn(tile[tx][ty + j]);
}

__global__ void init_z0h(const float* __restrict__ z0) {
    int idx = blockIdx.x * blockDim.x + threadIdx.x;
    if (idx < B_ * H_) {
        int b = idx / H_, ch = idx - b * H_;
        g_z0h[idx] = __float2half_rn(z0[b * (2 * H_) + ch]);
    }
}

// fp32 GEMV: g_pre0[b][m] = sum_i conv_w[m][i][0] * z0h[b][i]  (one warp per dot)
__global__ void gemv_pre0(const float* __restrict__ conv_w,
                          const float* __restrict__ z0) {
    int w = (blockIdx.x * blockDim.x + threadIdx.x) >> 5;
    int lane = threadIdx.x & 31;
    if (w >= M4_ * B_) return;
    int m = w >> 2;
    int b = w & 3;
    float s = 0.0f;
    for (int i = lane; i < H_; i += 32)
        s += conv_w[(size_t)m * (2 * H_) + 2 * i] * z0[b * (2 * H_) + i];
#pragma unroll
    for (int o = 16; o; o >>= 1) s += __shfl_xor_sync(0xFFFFFFFFu, s, o);
    if (lane == 0) g_pre0[b * M4_ + m] = s;
}

// ===========================================================================
// Layer 0 (h_prev == 0): pre = us (+ W0·z0h at t==0); gate with c_prev
// (z0c at t==0, else 0). Writes g_hh1 (fp16) and g_c1.
// ===========================================================================
__global__ __launch_bounds__(256)
void layer0_gate(const float* __restrict__ z0) {
    int idx = blockIdx.x * blockDim.x + threadIdx.x;
    if (idx >= N_ * (H_ / 4)) return;
    int n  = idx / (H_ / 4);
    int ch = (idx - n * (H_ / 4)) * 4;
    int t = n & (L_ - 1);
    int b = n >> 10;

    const size_t ub = (size_t)n * M4_;
    float pi[4], po[4], pg[4], pf[4];
#pragma unroll
    for (int e = 0; e < 4; e += 2) {
        float2 vi = __half22float2(*(const __half2*)(g_us2 + ub + 0 * H_ + ch + e));
        float2 vo = __half22float2(*(const __half2*)(g_us2 + ub + 1 * H_ + ch + e));
        float2 vg = __half22float2(*(const __half2*)(g_us2 + ub + 2 * H_ + ch + e));
        float2 vf = __half22float2(*(const __half2*)(g_us2 + ub + 3 * H_ + ch + e));
        pi[e] = vi.x; pi[e + 1] = vi.y;
        po[e] = vo.x; po[e + 1] = vo.y;
        pg[e] = vg.x; pg[e + 1] = vg.y;
        pf[e] = vf.x; pf[e + 1] = vf.y;
    }
    float cprev[4] = {0.0f, 0.0f, 0.0f, 0.0f};
    if (t == 0) {
#pragma unroll
        for (int e = 0; e < 4; e++) {
            pi[e] += g_pre0[b * M4_ + 0 * H_ + ch + e];
            po[e] += g_pre0[b * M4_ + 1 * H_ + ch + e];
            pg[e] += g_pre0[b * M4_ + 2 * H_ + ch + e];
            pf[e] += g_pre0[b * M4_ + 3 * H_ + ch + e];
            cprev[e] = z0[b * (2 * H_) + H_ + ch + e];
        }
    }
    float4 cv;
    float* cvp = (float*)&cv;
    __half hh[4];
#pragma unroll
    for (int e = 0; e < 4; e++) {
        float si = 1.0f / (1.0f + __expf(-pi[e]));
        float so = 1.0f / (1.0f + __expf(-po[e]));
        float sf = 1.0f / (1.0f + __expf(-pf[e]));
        float tg = tanh_fast(pg[e]);
        float c = sf * cprev[e] + si * tg;
        float h = so * tanh_fast(c);
        cvp[e] = c;
        hh[e] = __float2half_rn(h);
    }
    *(float4*)(g_c1 + (size_t)n * H_ + ch) = cv;
    *(__half2*)(g_hh1 + (size_t)n * H_ + ch)     = __halves2half2(hh[0], hh[1]);
    *(__half2*)(g_hh1 + (size_t)n * H_ + ch + 2) = __halves2half2(hh[2], hh[3]);
}

// ===========================================================================
// Fused GEMM (fp16 mma.sync + ldmatrix), 128(n)x128(m), BK=32, 5 stages,
// 2 CTAs/SM. Layer epilogue stages us (fp16) through smem; last layer
// writes the harness output directly.
// ===========================================================================
#define BK      32
#define KS      40                       // padded row stride (halfs), 80B
#define STG_A   (128 * KS)               // halfs per A stage
#define STG_SZ  (2 * 128 * KS)           // halfs per stage (A+B)
#define NSTAGE  5
#define SMEM_BYTES (NSTAGE * STG_SZ * 2) // 102400
// epilogue smem layout (per 64-row pass)
#define USS     160                      // us_s row stride in halfs
#define PS      136                      // pre_s row stride in floats
#define PRE_OFF 5120                     // float offset of pre_s

template <int KTOT, bool INJECT>
__global__ __launch_bounds__(256, 2)
void gemm_fused(const float* __restrict__ z0, float* __restrict__ out,
                int rd, int last) {
    extern __shared__ __half smh[];
    constexpr int KHALF = KTOT / 2;
    constexpr int NKT = KTOT / BK;

    const __half* __restrict__ Asrc = INJECT ? g_Xt : (rd ? g_hh1 : g_hh0);
    const __half* __restrict__ Bw   = INJECT ? g_Wi2 : g_Wc2;

    const int tid  = threadIdx.x;
    const int wid  = tid >> 5;
    const int lane = tid & 31;
    const int grp  = lane >> 2;
    const int qid  = lane & 3;
    const int n0   = blockIdx.x * 128;
    const int m0   = blockIdx.y * 128;

    const int wn = (wid >> 2) * 64;
    const int wm = (wid & 3) * 32;

    const uint32_t sbase = smem_u32(smh);
    const int lrow = lane & 15;
    const int lcol = (lane >> 4) << 3;

#define LOAD_STAGE(S, K0)                                                        \
    do {                                                                         \
        const int _k0 = (K0);                                                    \
        const uint32_t aoff = ((S) % NSTAGE) * STG_SZ;                           \
        const uint32_t boff = aoff + STG_A;                                      \
        _Pragma("unroll")                                                        \
        for (int j = 0; j < 2; j++) {                                            \
            int idx = tid + j * 256;         /* 0..511 */                        \
            int r  = idx >> 2;                                                   \
            int c8 = idx & 3;                                                    \
            int kk = _k0 + c8 * 8;                                               \
            {                                                                    \
                int n = n0 + r;                                                  \
                int t = n & (L_ - 1);                                            \
                int b = n >> 10;                                                 \
                uint32_t dst = sbase + (aoff + r * KS + c8 * 8) * 2;             \
                if (kk < KHALF) {                                                \
                    if (t == 0) {                                                \
                        if (INJECT) cp_async16_zero(dst, Asrc);                  \
                        else cp_async16(dst, g_z0h + b * H_ + kk);               \
                    } else {                                                     \
                        cp_async16(dst, Asrc + (size_t)(n - 1) * KHALF + kk);    \
                    }                                                            \
                } else {                                                         \
                    cp_async16(dst, Asrc + (size_t)n * KHALF + (kk - KHALF));    \
                }                                                                \
            }                                                                    \
            {                                                                    \
                uint32_t dst = sbase + (boff + r * KS + c8 * 8) * 2;             \
                cp_async16(dst, Bw + (size_t)(m0 + r) * KTOT + kk);              \
            }                                                                    \
        }                                                                        \
        cp_commit();                                                             \
    } while (0)

    // prologue
#pragma unroll
    for (int s = 0; s < NSTAGE - 1; s++) LOAD_STAGE(s, s * BK);

    float acc[4][4][4];
#pragma unroll
    for (int i = 0; i < 4; i++)
#pragma unroll
        for (int j = 0; j < 4; j++)
#pragma unroll
            for (int e = 0; e < 4; e++) acc[i][j][e] = 0.0f;

#pragma unroll 1
    for (int kt = 0; kt < NKT; kt++) {
        cp_wait<NSTAGE - 2>();
        __syncthreads();

        const int sf = kt + NSTAGE - 1;
        if (sf < NKT) LOAD_STAGE(sf, sf * BK);
        else cp_commit();

        const uint32_t a_base = sbase + (uint32_t)((kt % NSTAGE) * STG_SZ) * 2;
        const uint32_t b_base = a_base + STG_A * 2;

#pragma unroll
        for (int ks = 0; ks < BK; ks += 16) {
            uint32_t af[4][4];
            uint32_t bf[2][4];
#pragma unroll
            for (int fi = 0; fi < 4; fi++) {
                uint32_t addr = a_base +
                    (uint32_t)((wn + fi * 16 + lrow) * KS + ks + lcol) * 2;
                ldmatrix_x4(af[fi], addr);
            }
#pragma unroll
            for (int fh = 0; fh < 2; fh++) {
                uint32_t addr = b_base +
                    (uint32_t)((wm + fh * 16 + lrow) * KS + ks + lcol) * 2;
                ldmatrix_x4(bf[fh], addr);
            }
#pragma unroll
            for (int fi = 0; fi < 4; fi++) {
#pragma unroll
                for (int fh = 0; fh < 2; fh++) {
#pragma unroll
                    for (int s2 = 0; s2 < 2; s2++) {
                        int fj = fh * 2 + s2;
                        mma_f16(acc[fi][fj][0], acc[fi][fj][1],
                                acc[fi][fj][2], acc[fi][fj][3],
                                af[fi][0], af[fi][1], af[fi][2], af[fi][3],
                                bf[fh][s2], bf[fh][s2 + 2]);
                    }
                }
            }
        }
    }

    if (INJECT) {
#pragma unroll
        for (int fi = 0; fi < 4; fi++) {
#pragma unroll
            for (int fj = 0; fj < 4; fj++) {
                int n1 = n0 + wn + fi * 16 + grp;
                int m  = m0 + wm + fj * 8 + qid * 2;
                float b0 = g_bias[m], b1 = g_bias[m + 1];
                *(__half2*)(g_us2 + (size_t)n1 * M4_ + m) =
                    __floats2half2_rn(acc[fi][fj][0] + b0, acc[fi][fj][1] + b1);
                *(__half2*)(g_us2 + (size_t)(n1 + 8) * M4_ + m) =
                    __floats2half2_rn(acc[fi][fj][2] + b0, acc[fi][fj][3] + b1);
            }
        }
        return;
    }

    // ------------- fused gating epilogue, 2 passes of 64 n-rows -------------
    __half* us_s = smh;
    float*  pre_s = (float*)smh + PRE_OFF;
    const float* __restrict__ cpb = rd ? g_c1 : g_c0;
    float* __restrict__ cn = rd ? g_c0 : g_c1;
    __half* __restrict__ hhn = rd ? g_hh0 : g_hh1;
    const int chbase = blockIdx.y * 32;
    const int q  = tid & 7;
    const int nl = tid >> 3;

#pragma unroll
    for (int p = 0; p < 2; p++) {
        __syncthreads();

        // stage us rows [p*64, p*64+64)
#pragma unroll
        for (int j = 0; j < 4; j++) {
            int id = tid + j * 256;
            int row = id >> 4;
            int g   = (id >> 2) & 3;
            int c   = id & 3;
            int n = n0 + p * 64 + row;
            cp_async16(sbase + (uint32_t)(row * USS + g * 32 + c * 8) * 2,
                       g_us2 + (size_t)n * M4_ + g * H_ + chbase + c * 8);
        }
        cp_commit();

        if ((wid >> 2) == p) {
#pragma unroll
            for (int fi = 0; fi < 4; fi++) {
#pragma unroll
                for (int fj = 0; fj < 4; fj++) {
                    int r0   = fi * 16 + grp;
                    int cidx = wm + fj * 8 + qid * 2;
                    *(float2*)&pre_s[r0 * PS + cidx] =
                        make_float2(acc[fi][fj][0], acc[fi][fj][1]);
                    *(float2*)&pre_s[(r0 + 8) * PS + cidx] =
                        make_float2(acc[fi][fj][2], acc[fi][fj][3]);
                }
            }
        }
        cp_wait<0>();
        __syncthreads();

#pragma unroll
        for (int it = 0; it < 2; it++) {
            int row = nl + it * 32;
            int n = n0 + p * 64 + row;
            int t = n & (L_ - 1);
            int b = n >> 10;
            int ch = chbase + q * 4;

            float4 pi4 = *(const float4*)&pre_s[row * PS + 0 * 32 + q * 4];
            float4 po4 = *(const float4*)&pre_s[row * PS + 1 * 32 + q * 4];
            float4 pg4 = *(const float4*)&pre_s[row * PS + 2 * 32 + q * 4];
            float4 pf4 = *(const float4*)&pre_s[row * PS + 3 * 32 + q * 4];

            const __half* ur = us_s + row * USS + q * 4;
            float2 uiA = __half22float2(*(const __half2*)(ur + 0 * 32));
            float2 uiB = __half22float2(*(const __half2*)(ur + 0 * 32 + 2));
            float2 uoA = __half22float2(*(const __half2*)(ur + 1 * 32));
            float2 uoB = __half22float2(*(const __half2*)(ur + 1 * 32 + 2));
            float2 ugA = __half22float2(*(const __half2*)(ur + 2 * 32));
            float2 ugB = __half22float2(*(const __half2*)(ur + 2 * 32 + 2));
            float2 ufA = __half22float2(*(const __half2*)(ur + 3 * 32));
            float2 ufB = __half22float2(*(const __half2*)(ur + 3 * 32 + 2));
            float ui[4] = {uiA.x, uiA.y, uiB.x, uiB.y};
            float uo[4] = {uoA.x, uoA.y, uoB.x, uoB.y};
            float ug[4] = {ugA.x, ugA.y, ugB.x, ugB.y};
            float uf[4] = {ufA.x, ufA.y, ufB.x, ufB.y};

            float4 cpv;
            if (t == 0) cpv = *(const float4*)(z0 + b * (2 * H_) + H_ + ch);
            else        cpv = *(const float4*)(cpb + (size_t)(n - 1) * H_ + ch);

            const float* pip = (const float*)&pi4;
            const float* pop = (const float*)&po4;
            const float* pgp = (const float*)&pg4;
            const float* pfp = (const float*)&pf4;
            const float* cpl = (const float*)&cpv;

            float4 hv, cv;
            float* hvp = (float*)&hv;
            float* cvp = (float*)&cv;
#pragma unroll
            for (int e = 0; e < 4; e++) {
                float pi = pip[e] + ui[e];
                float po = pop[e] + uo[e];
                float pg = pgp[e] + ug[e];
                float pf = pfp[e] + uf[e];
                float si = 1.0f / (1.0f + __expf(-pi));
                float so = 1.0f / (1.0f + __expf(-po));
                float sf = 1.0f / (1.0f + __expf(-pf));
                float tg = tanh_fast(pg);
                float c = sf * cpl[e] + si * tg;
                float h = so * tanh_fast(c);
                hvp[e] = h;
                cvp[e] = c;
            }
            if (last) {
                // out[b][t][j] = h for ch in [512, 768)
                if (chbase >= 512 + 0) {
                    *(float4*)(out + (size_t)n * NOUT_ + (ch - (H_ - NOUT_))) = hv;
                }
                if (t == L_ - 1) {
                    const size_t tot = (size_t)B_ * L_ * NOUT_;
                    *(float4*)(out + tot + b * (2 * H_) + ch)      = hv;
                    *(float4*)(out + tot + b * (2 * H_) + H_ + ch) = cv;
                }
            } else {
                *(float4*)(cn + (size_t)n * H_ + ch) = cv;
                __half2 h01 = __floats2half2_rn(hvp[0], hvp[1]);
                __half2 h23 = __floats2half2_rn(hvp[2], hvp[3]);
                *(__half2*)(hhn + (size_t)n * H_ + ch)     = h01;
                *(__half2*)(hhn + (size_t)n * H_ + ch + 2) = h23;
            }
        }
    }
#undef LOAD_STAGE
}

// ===========================================================================
extern "C" void kernel_launch(void* const* d_in, const int* in_sizes, int n_in,
                              void* d_out, int out_size) {
    const float* X        = (const float*)d_in[0];
    const float* z0       = (const float*)d_in[1];
    const float* inject_w = (const float*)d_in[2];
    const float* inject_b = (const float*)d_in[3];
    const float* conv_w   = (const float*)d_in[4];
    const float* conv_b   = (const float*)d_in[5];
    float* out = (float*)d_out;

    cudaFuncSetAttribute(gemm_fused<KI_, true>,
                         cudaFuncAttributeMaxDynamicSharedMemorySize, SMEM_BYTES);
    cudaFuncSetAttribute(gemm_fused<KC_, false>,
                         cudaFuncAttributeMaxDynamicSharedMemorySize, SMEM_BYTES);

    repack_conv2<<<(M4_ * KC_ + 255) / 256, 256>>>(conv_w);
    repack_inj2<<<(M4_ * KI_ + 255) / 256, 256>>>(inject_w, inject_b, conv_b);
    transpose_x<<<dim3(L_ / 32, NINP_ / 32, B_), dim3(32, 8)>>>(X);
    init_z0h<<<(B_ * H_ + 255) / 256, 256>>>(z0);
    gemv_pre0<<<(M4_ * B_ * 32 + 255) / 256, 256>>>(conv_w, z0);

    // inject GEMM -> us
    gemm_fused<KI_, true><<<dim3(N_ / 128, M4_ / 128), 256, SMEM_BYTES>>>(
        z0, out, 0, 0);

    // layer 0: h_prev == 0 -> elementwise gating (+ GEMV correction at t==0)
    layer0_gate<<<(N_ * (H_ / 4) + 255) / 256, 256>>>(z0);

    // layers 1..9
    for (int l = 1; l < NLAYER_; l++)
        gemm_fused<KC_, false><<<dim3(N_ / 128, M4_ / 128), 256, SMEM_BYTES>>>(
            z0, out, l & 1, l == NLAYER_ - 1);
}

// round 10
// speedup vs baseline: 9.1942x; 1.1266x over previous
#include <cuda_runtime.h>
#include <cuda_fp16.h>
#include <math.h>
#include <cstdint>

// Problem constants
#define B_    4
#define H_    768
#define L_    1024
#define N_    4096          // B_*L_
#define M4_   3072          // 4*H_
#define NINP_ 512
#define KC_   1536          // conv K  ([h(t-1); h(t)])
#define KI_   1024          // inject K ([x(t-1); x(t)])
#define NOUT_ 256
#define NLAYER_ 10

// Scratch (device globals; no allocation allowed)
__device__ __half g_us2[(size_t)N_ * M4_]; // us[n][m] fp16, plain order, biases folded
__device__ float g_c0[(size_t)N_ * H_];
__device__ float g_c1[(size_t)N_ * H_];
__device__ __half g_hh0[(size_t)N_ * H_];  // h fp16 mirror (GEMM A input)
__device__ __half g_hh1[(size_t)N_ * H_];
__device__ __half g_Wc2[(size_t)M4_ * KC_]; // conv W fp16, gate-interleaved rows
__device__ __half g_Wi2[(size_t)M4_ * KI_]; // inject W fp16, plain rows
__device__ __half g_Xt[(size_t)N_ * NINP_]; // X fp16, time-major [n][i]
__device__ __half g_z0h[B_ * H_];           // z0 h-part fp16
__device__ float  g_bias[M4_];              // inject_b + conv_b
__device__ float  g_pre0[B_ * M4_];         // layer-0 t==0 correction: W0 @ z0h

// ===========================================================================
// Helpers
// ===========================================================================
__device__ __forceinline__ uint32_t smem_u32(const void* p) {
    uint32_t a;
    asm("{ .reg .u64 t; cvta.to.shared.u64 t, %1; cvt.u32.u64 %0, t; }"
        : "=r"(a) : "l"(p));
    return a;
}
__device__ __forceinline__ void cp_async16(uint32_t dst, const void* src) {
    asm volatile("cp.async.cg.shared.global [%0], [%1], 16;" :: "r"(dst), "l"(src));
}
__device__ __forceinline__ void cp_async16_zero(uint32_t dst, const void* src) {
    asm volatile("cp.async.cg.shared.global [%0], [%1], 16, 0;" :: "r"(dst), "l"(src));
}
__device__ __forceinline__ void cp_commit() {
    asm volatile("cp.async.commit_group;");
}
template <int Npend>
__device__ __forceinline__ void cp_wait() {
    asm volatile("cp.async.wait_group %0;" :: "n"(Npend));
}
__device__ __forceinline__ void ldmatrix_x4(uint32_t* r, uint32_t addr) {
    asm volatile("ldmatrix.sync.aligned.m8n8.x4.shared.b16 {%0,%1,%2,%3}, [%4];"
        : "=r"(r[0]), "=r"(r[1]), "=r"(r[2]), "=r"(r[3]) : "r"(addr));
}
__device__ __forceinline__ void mma_f16(float& c0, float& c1, float& c2, float& c3,
                                        uint32_t a0, uint32_t a1, uint32_t a2, uint32_t a3,
                                        uint32_t b0, uint32_t b1) {
    asm volatile(
        "mma.sync.aligned.m16n8k16.row.col.f32.f16.f16.f32 "
        "{%0,%1,%2,%3}, {%4,%5,%6,%7}, {%8,%9}, {%0,%1,%2,%3};"
        : "+f"(c0), "+f"(c1), "+f"(c2), "+f"(c3)
        : "r"(a0), "r"(a1), "r"(a2), "r"(a3), "r"(b0), "r"(b1));
}
__device__ __forceinline__ float tanh_fast(float x) {
    float r;
    asm("tanh.approx.f32 %0, %1;" : "=f"(r) : "f"(x));
    return r;
}

// ===========================================================================
// Repacks / transpose / init
// ===========================================================================
__global__ void repack_conv2(const float* __restrict__ conv_w) {
    int idx = blockIdx.x * blockDim.x + threadIdx.x;
    if (idx >= M4_ * KC_) return;
    int mp = idx / KC_;
    int k  = idx - mp * KC_;
    int y  = mp >> 7;
    int rr = mp & 127;
    int g  = rr >> 5;
    int cl = rr & 31;
    int m  = g * H_ + y * 32 + cl;
    int tap = (k >= H_) ? 1 : 0;
    int i = k - tap * H_;
    g_Wc2[idx] = __float2half_rn(conv_w[m * (H_ * 2) + i * 2 + tap]);
}

__global__ void repack_inj2(const float* __restrict__ inject_w,
                            const float* __restrict__ inject_b,
                            const float* __restrict__ conv_b) {
    int idx = blockIdx.x * blockDim.x + threadIdx.x;
    if (idx >= M4_ * KI_) return;
    int m = idx / KI_;
    int k = idx - m * KI_;
    int tap = (k >= NINP_) ? 1 : 0;
    int i = k - tap * NINP_;
    g_Wi2[idx] = __float2half_rn(inject_w[m * (NINP_ * 2) + i * 2 + tap]);
    if (k == 0) g_bias[m] = inject_b[m] + conv_b[m];
}

__global__ void transpose_x(const float* __restrict__ X) {
    __shared__ float tile[32][33];
    int b  = blockIdx.z;
    int i0 = blockIdx.y * 32;
    int t0 = blockIdx.x * 32;
    int tx = threadIdx.x, ty = threadIdx.y;
#pragma unroll
    for (int j = 0; j < 32; j += 8)
        tile[ty + j][tx] = X[(size_t)(b * NINP_ + i0 + ty + j) * L_ + t0 + tx];
    __syncthreads();
#pragma unroll
    for (int j = 0; j < 32; j += 8)
        g_Xt[(size_t)(b * L_ + t0 + ty + j) * NINP_ + i0 + tx] =
            __float2half_rn(tile[tx][ty + j]);
}

__global__ void init_z0h(const float* __restrict__ z0) {
    int idx = blockIdx.x * blockDim.x + threadIdx.x;
    if (idx < B_ * H_) {
        int b = idx / H_, ch = idx - b * H_;
        g_z0h[idx] = __float2half_rn(z0[b * (2 * H_) + ch]);
    }
}

// fp32 GEMV: g_pre0[b][m] = sum_i conv_w[m][i][0] * z0h[b][i]
__global__ void gemv_pre0(const float* __restrict__ conv_w,
                          const float* __restrict__ z0) {
    int w = (blockIdx.x * blockDim.x + threadIdx.x) >> 5;
    int lane = threadIdx.x & 31;
    if (w >= M4_ * B_) return;
    int m = w >> 2;
    int b = w & 3;
    float s = 0.0f;
    for (int i = lane; i < H_; i += 32)
        s += conv_w[(size_t)m * (2 * H_) + 2 * i] * z0[b * (2 * H_) + i];
#pragma unroll
    for (int o = 16; o; o >>= 1) s += __shfl_xor_sync(0xFFFFFFFFu, s, o);
    if (lane == 0) g_pre0[b * M4_ + m] = s;
}

// ===========================================================================
// Layer 0 (h_prev == 0): pre = us (+ W0·z0h at t==0); gate with c_prev
// ===========================================================================
__global__ __launch_bounds__(256)
void layer0_gate(const float* __restrict__ z0) {
    int idx = blockIdx.x * blockDim.x + threadIdx.x;
    if (idx >= N_ * (H_ / 4)) return;
    int n  = idx / (H_ / 4);
    int ch = (idx - n * (H_ / 4)) * 4;
    int t = n & (L_ - 1);
    int b = n >> 10;

    const size_t ub = (size_t)n * M4_;
    float pi[4], po[4], pg[4], pf[4];
#pragma unroll
    for (int e = 0; e < 4; e += 2) {
        float2 vi = __half22float2(*(const __half2*)(g_us2 + ub + 0 * H_ + ch + e));
        float2 vo = __half22float2(*(const __half2*)(g_us2 + ub + 1 * H_ + ch + e));
        float2 vg = __half22float2(*(const __half2*)(g_us2 + ub + 2 * H_ + ch + e));
        float2 vf = __half22float2(*(const __half2*)(g_us2 + ub + 3 * H_ + ch + e));
        pi[e] = vi.x; pi[e + 1] = vi.y;
        po[e] = vo.x; po[e + 1] = vo.y;
        pg[e] = vg.x; pg[e + 1] = vg.y;
        pf[e] = vf.x; pf[e + 1] = vf.y;
    }
    float cprev[4] = {0.0f, 0.0f, 0.0f, 0.0f};
    if (t == 0) {
#pragma unroll
        for (int e = 0; e < 4; e++) {
            pi[e] += g_pre0[b * M4_ + 0 * H_ + ch + e];
            po[e] += g_pre0[b * M4_ + 1 * H_ + ch + e];
            pg[e] += g_pre0[b * M4_ + 2 * H_ + ch + e];
            pf[e] += g_pre0[b * M4_ + 3 * H_ + ch + e];
            cprev[e] = z0[b * (2 * H_) + H_ + ch + e];
        }
    }
    float4 cv;
    float* cvp = (float*)&cv;
    __half hh[4];
#pragma unroll
    for (int e = 0; e < 4; e++) {
        float si = 1.0f / (1.0f + __expf(-pi[e]));
        float so = 1.0f / (1.0f + __expf(-po[e]));
        float sf = 1.0f / (1.0f + __expf(-pf[e]));
        float tg = tanh_fast(pg[e]);
        float c = sf * cprev[e] + si * tg;
        float h = so * tanh_fast(c);
        cvp[e] = c;
        hh[e] = __float2half_rn(h);
    }
    *(float4*)(g_c1 + (size_t)n * H_ + ch) = cv;
    *(__half2*)(g_hh1 + (size_t)n * H_ + ch)     = __halves2half2(hh[0], hh[1]);
    *(__half2*)(g_hh1 + (size_t)n * H_ + ch + 2) = __halves2half2(hh[2], hh[3]);
}

// ===========================================================================
// Fused GEMM (fp16 mma.sync + ldmatrix), 128(n)x128(m), BK=64, 3 stages,
// 2 CTAs/SM (smem 108 KB x2 = 216 KB <= 228 KB).
// ===========================================================================
#define BK      64
#define KS      72                       // padded row stride (halfs), 144B
#define STG_A   (128 * KS)               // halfs per A stage
#define STG_SZ  (2 * 128 * KS)           // halfs per stage (A+B)
#define NSTAGE  3
#define SMEM_BYTES (NSTAGE * STG_SZ * 2) // 110592
// epilogue smem layout (per 64-row pass)
#define USS     160                      // us_s row stride in halfs
#define PS      136                      // pre_s row stride in floats
#define PRE_OFF 5120                     // float offset of pre_s

template <int KTOT, bool INJECT>
__global__ __launch_bounds__(256, 2)
void gemm_fused(const float* __restrict__ z0, float* __restrict__ out,
                int rd, int last) {
    extern __shared__ __half smh[];
    constexpr int KHALF = KTOT / 2;
    constexpr int NKT = KTOT / BK;

    const __half* __restrict__ Asrc = INJECT ? g_Xt : (rd ? g_hh1 : g_hh0);
    const __half* __restrict__ Bw   = INJECT ? g_Wi2 : g_Wc2;

    const int tid  = threadIdx.x;
    const int wid  = tid >> 5;
    const int lane = tid & 31;
    const int grp  = lane >> 2;
    const int qid  = lane & 3;
    const int n0   = blockIdx.x * 128;
    const int m0   = blockIdx.y * 128;

    const int wn = (wid >> 2) * 64;
    const int wm = (wid & 3) * 32;

    const uint32_t sbase = smem_u32(smh);
    const int lrow = lane & 15;
    const int lcol = (lane >> 4) << 3;

#define LOAD_STAGE(S, K0)                                                        \
    do {                                                                         \
        const int _k0 = (K0);                                                    \
        const uint32_t aoff = ((S) % NSTAGE) * STG_SZ;                           \
        const uint32_t boff = aoff + STG_A;                                      \
        _Pragma("unroll")                                                        \
        for (int j = 0; j < 4; j++) {                                            \
            int idx = tid + j * 256;         /* 0..1023 */                       \
            int r  = idx >> 3;                                                   \
            int c8 = idx & 7;                                                    \
            int kk = _k0 + c8 * 8;                                               \
            {                                                                    \
                int n = n0 + r;                                                  \
                int t = n & (L_ - 1);                                            \
                int b = n >> 10;                                                 \
                uint32_t dst = sbase + (aoff + r * KS + c8 * 8) * 2;             \
                if (kk < KHALF) {                                                \
                    if (t == 0) {                                                \
                        if (INJECT) cp_async16_zero(dst, Asrc);                  \
                        else cp_async16(dst, g_z0h + b * H_ + kk);               \
                    } else {                                                     \
                        cp_async16(dst, Asrc + (size_t)(n - 1) * KHALF + kk);    \
                    }                                                            \
                } else {                                                         \
                    cp_async16(dst, Asrc + (size_t)n * KHALF + (kk - KHALF));    \
                }                                                                \
            }                                                                    \
            {                                                                    \
                uint32_t dst = sbase + (boff + r * KS + c8 * 8) * 2;             \
                cp_async16(dst, Bw + (size_t)(m0 + r) * KTOT + kk);              \
            }                                                                    \
        }                                                                        \
        cp_commit();                                                             \
    } while (0)

    // prologue
#pragma unroll
    for (int s = 0; s < NSTAGE - 1; s++) LOAD_STAGE(s, s * BK);

    float acc[4][4][4];
#pragma unroll
    for (int i = 0; i < 4; i++)
#pragma unroll
        for (int j = 0; j < 4; j++)
#pragma unroll
            for (int e = 0; e < 4; e++) acc[i][j][e] = 0.0f;

#pragma unroll 1
    for (int kt = 0; kt < NKT; kt++) {
        cp_wait<NSTAGE - 2>();
        __syncthreads();

        const int sf = kt + NSTAGE - 1;
        if (sf < NKT) LOAD_STAGE(sf, sf * BK);
        else cp_commit();

        const uint32_t a_base = sbase + (uint32_t)((kt % NSTAGE) * STG_SZ) * 2;
        const uint32_t b_base = a_base + STG_A * 2;

#pragma unroll
        for (int ks = 0; ks < BK; ks += 16) {
            uint32_t af[4][4];
            uint32_t bf[2][4];
#pragma unroll
            for (int fi = 0; fi < 4; fi++) {
                uint32_t addr = a_base +
                    (uint32_t)((wn + fi * 16 + lrow) * KS + ks + lcol) * 2;
                ldmatrix_x4(af[fi], addr);
            }
#pragma unroll
            for (int fh = 0; fh < 2; fh++) {
                uint32_t addr = b_base +
                    (uint32_t)((wm + fh * 16 + lrow) * KS + ks + lcol) * 2;
                ldmatrix_x4(bf[fh], addr);
            }
#pragma unroll
            for (int fi = 0; fi < 4; fi++) {
#pragma unroll
                for (int fh = 0; fh < 2; fh++) {
#pragma unroll
                    for (int s2 = 0; s2 < 2; s2++) {
                        int fj = fh * 2 + s2;
                        mma_f16(acc[fi][fj][0], acc[fi][fj][1],
                                acc[fi][fj][2], acc[fi][fj][3],
                                af[fi][0], af[fi][1], af[fi][2], af[fi][3],
                                bf[fh][s2], bf[fh][s2 + 2]);
                    }
                }
            }
        }
    }

    if (INJECT) {
#pragma unroll
        for (int fi = 0; fi < 4; fi++) {
#pragma unroll
            for (int fj = 0; fj < 4; fj++) {
                int n1 = n0 + wn + fi * 16 + grp;
                int m  = m0 + wm + fj * 8 + qid * 2;
                float b0 = g_bias[m], b1 = g_bias[m + 1];
                *(__half2*)(g_us2 + (size_t)n1 * M4_ + m) =
                    __floats2half2_rn(acc[fi][fj][0] + b0, acc[fi][fj][1] + b1);
                *(__half2*)(g_us2 + (size_t)(n1 + 8) * M4_ + m) =
                    __floats2half2_rn(acc[fi][fj][2] + b0, acc[fi][fj][3] + b1);
            }
        }
        return;
    }

    // ------------- fused gating epilogue, 2 passes of 64 n-rows -------------
    __half* us_s = smh;
    float*  pre_s = (float*)smh + PRE_OFF;
    const float* __restrict__ cpb = rd ? g_c1 : g_c0;
    float* __restrict__ cn = rd ? g_c0 : g_c1;
    __half* __restrict__ hhn = rd ? g_hh0 : g_hh1;
    const int chbase = blockIdx.y * 32;
    const int q  = tid & 7;
    const int nl = tid >> 3;

#pragma unroll
    for (int p = 0; p < 2; p++) {
        __syncthreads();

        // stage us rows [p*64, p*64+64)
#pragma unroll
        for (int j = 0; j < 4; j++) {
            int id = tid + j * 256;
            int row = id >> 4;
            int g   = (id >> 2) & 3;
            int c   = id & 3;
            int n = n0 + p * 64 + row;
            cp_async16(sbase + (uint32_t)(row * USS + g * 32 + c * 8) * 2,
                       g_us2 + (size_t)n * M4_ + g * H_ + chbase + c * 8);
        }
        cp_commit();

        if ((wid >> 2) == p) {
#pragma unroll
            for (int fi = 0; fi < 4; fi++) {
#pragma unroll
                for (int fj = 0; fj < 4; fj++) {
                    int r0   = fi * 16 + grp;
                    int cidx = wm + fj * 8 + qid * 2;
                    *(float2*)&pre_s[r0 * PS + cidx] =
                        make_float2(acc[fi][fj][0], acc[fi][fj][1]);
                    *(float2*)&pre_s[(r0 + 8) * PS + cidx] =
                        make_float2(acc[fi][fj][2], acc[fi][fj][3]);
                }
            }
        }
        cp_wait<0>();
        __syncthreads();

#pragma unroll
        for (int it = 0; it < 2; it++) {
            int row = nl + it * 32;
            int n = n0 + p * 64 + row;
            int t = n & (L_ - 1);
            int b = n >> 10;
            int ch = chbase + q * 4;

            float4 pi4 = *(const float4*)&pre_s[row * PS + 0 * 32 + q * 4];
            float4 po4 = *(const float4*)&pre_s[row * PS + 1 * 32 + q * 4];
            float4 pg4 = *(const float4*)&pre_s[row * PS + 2 * 32 + q * 4];
            float4 pf4 = *(const float4*)&pre_s[row * PS + 3 * 32 + q * 4];

            const __half* ur = us_s + row * USS + q * 4;
            float2 uiA = __half22float2(*(const __half2*)(ur + 0 * 32));
            float2 uiB = __half22float2(*(const __half2*)(ur + 0 * 32 + 2));
            float2 uoA = __half22float2(*(const __half2*)(ur + 1 * 32));
            float2 uoB = __half22float2(*(const __half2*)(ur + 1 * 32 + 2));
            float2 ugA = __half22float2(*(const __half2*)(ur + 2 * 32));
            float2 ugB = __half22float2(*(const __half2*)(ur + 2 * 32 + 2));
            float2 ufA = __half22float2(*(const __half2*)(ur + 3 * 32));
            float2 ufB = __half22float2(*(const __half2*)(ur + 3 * 32 + 2));
            float ui[4] = {uiA.x, uiA.y, uiB.x, uiB.y};
            float uo[4] = {uoA.x, uoA.y, uoB.x, uoB.y};
            float ug[4] = {ugA.x, ugA.y, ugB.x, ugB.y};
            float uf[4] = {ufA.x, ufA.y, ufB.x, ufB.y};

            float4 cpv;
            if (t == 0) cpv = *(const float4*)(z0 + b * (2 * H_) + H_ + ch);
            else        cpv = *(const float4*)(cpb + (size_t)(n - 1) * H_ + ch);

            const float* pip = (const float*)&pi4;
            const float* pop = (const float*)&po4;
            const float* pgp = (const float*)&pg4;
            const float* pfp = (const float*)&pf4;
            const float* cpl = (const float*)&cpv;

            float4 hv, cv;
            float* hvp = (float*)&hv;
            float* cvp = (float*)&cv;
#pragma unroll
            for (int e = 0; e < 4; e++) {
                float pi = pip[e] + ui[e];
                float po = pop[e] + uo[e];
                float pg = pgp[e] + ug[e];
                float pf = pfp[e] + uf[e];
                float si = 1.0f / (1.0f + __expf(-pi));
                float so = 1.0f / (1.0f + __expf(-po));
                float sf = 1.0f / (1.0f + __expf(-pf));
                float tg = tanh_fast(pg);
                float c = sf * cpl[e] + si * tg;
                float h = so * tanh_fast(c);
                hvp[e] = h;
                cvp[e] = c;
            }
            if (last) {
                if (chbase >= H_ - NOUT_) {
                    *(float4*)(out + (size_t)n * NOUT_ + (ch - (H_ - NOUT_))) = hv;
                }
                if (t == L_ - 1) {
                    const size_t tot = (size_t)B_ * L_ * NOUT_;
                    *(float4*)(out + tot + b * (2 * H_) + ch)      = hv;
                    *(float4*)(out + tot + b * (2 * H_) + H_ + ch) = cv;
                }
            } else {
                *(float4*)(cn + (size_t)n * H_ + ch) = cv;
                __half2 h01 = __floats2half2_rn(hvp[0], hvp[1]);
                __half2 h23 = __floats2half2_rn(hvp[2], hvp[3]);
                *(__half2*)(hhn + (size_t)n * H_ + ch)     = h01;
                *(__half2*)(hhn + (size_t)n * H_ + ch + 2) = h23;
            }
        }
    }
#undef LOAD_STAGE
}

// ===========================================================================
extern "C" void kernel_launch(void* const* d_in, const int* in_sizes, int n_in,
                              void* d_out, int out_size) {
    const float* X        = (const float*)d_in[0];
    const float* z0       = (const float*)d_in[1];
    const float* inject_w = (const float*)d_in[2];
    const float* inject_b = (const float*)d_in[3];
    const float* conv_w   = (const float*)d_in[4];
    const float* conv_b   = (const float*)d_in[5];
    float* out = (float*)d_out;

    cudaFuncSetAttribute(gemm_fused<KI_, true>,
                         cudaFuncAttributeMaxDynamicSharedMemorySize, SMEM_BYTES);
    cudaFuncSetAttribute(gemm_fused<KC_, false>,
                         cudaFuncAttributeMaxDynamicSharedMemorySize, SMEM_BYTES);

    repack_conv2<<<(M4_ * KC_ + 255) / 256, 256>>>(conv_w);
    repack_inj2<<<(M4_ * KI_ + 255) / 256, 256>>>(inject_w, inject_b, conv_b);
    transpose_x<<<dim3(L_ / 32, NINP_ / 32, B_), dim3(32, 8)>>>(X);
    init_z0h<<<(B_ * H_ + 255) / 256, 256>>>(z0);
    gemv_pre0<<<(M4_ * B_ * 32 + 255) / 256, 256>>>(conv_w, z0);

    // inject GEMM -> us
    gemm_fused<KI_, true><<<dim3(N_ / 128, M4_ / 128), 256, SMEM_BYTES>>>(
        z0, out, 0, 0);

    // layer 0: h_prev == 0 -> elementwise gating (+ GEMV correction at t==0)
    layer0_gate<<<(N_ * (H_ / 4) + 255) / 256, 256>>>(z0);

    // layers 1..9
    for (int l = 1; l < NLAYER_; l++)
        gemm_fused<KC_, false><<<dim3(N_ / 128, M4_ / 128), 256, SMEM_BYTES>>>(
            z0, out, l & 1, l == NLAYER_ - 1);
}

// round 11
// speedup vs baseline: 9.2164x; 1.0024x over previous
#include <cuda_runtime.h>
#include <cuda_fp16.h>
#include <math.h>
#include <cstdint>

// Problem constants
#define B_    4
#define H_    768
#define L_    1024
#define N_    4096          // B_*L_
#define M4_   3072          // 4*H_
#define NINP_ 512
#define KC_   1536          // conv K  ([h(t-1); h(t)])
#define KI_   1024          // inject K ([x(t-1); x(t)])
#define NOUT_ 256
#define NLAYER_ 10

// Scratch (device globals; no allocation allowed)
// us layout: [n][mp], mp = y*128 + g*32 + cl  (gate-interleaved, y = ch/32)
__device__ __half g_us2[(size_t)N_ * M4_];
__device__ __half g_ch0[(size_t)N_ * H_];  // c fp16 inter-layer
__device__ __half g_ch1[(size_t)N_ * H_];
__device__ __half g_hh0[(size_t)N_ * H_];  // h fp16 (GEMM A input)
__device__ __half g_hh1[(size_t)N_ * H_];
__device__ __half g_Wc2[(size_t)M4_ * KC_]; // conv W fp16, gate-interleaved rows
__device__ __half g_Wi2[(size_t)M4_ * KI_]; // inject W fp16, gate-interleaved rows
__device__ __half g_Xt[(size_t)N_ * NINP_]; // X fp16, time-major [n][i]
__device__ __half g_z0h[B_ * H_];           // z0 h-part fp16
__device__ float  g_bias[M4_];              // inject_b + conv_b, interleaved index
__device__ float  g_pre0[B_ * M4_];         // layer-0 t==0 corr: W0 @ z0h, interleaved

// ===========================================================================
// Helpers
// ===========================================================================
__device__ __forceinline__ uint32_t smem_u32(const void* p) {
    uint32_t a;
    asm("{ .reg .u64 t; cvta.to.shared.u64 t, %1; cvt.u32.u64 %0, t; }"
        : "=r"(a) : "l"(p));
    return a;
}
__device__ __forceinline__ void cp_async16(uint32_t dst, const void* src) {
    asm volatile("cp.async.cg.shared.global [%0], [%1], 16;" :: "r"(dst), "l"(src));
}
__device__ __forceinline__ void cp_async16_zero(uint32_t dst, const void* src) {
    asm volatile("cp.async.cg.shared.global [%0], [%1], 16, 0;" :: "r"(dst), "l"(src));
}
__device__ __forceinline__ void cp_commit() {
    asm volatile("cp.async.commit_group;");
}
template <int Npend>
__device__ __forceinline__ void cp_wait() {
    asm volatile("cp.async.wait_group %0;" :: "n"(Npend));
}
__device__ __forceinline__ void ldmatrix_x4(uint32_t* r, uint32_t addr) {
    asm volatile("ldmatrix.sync.aligned.m8n8.x4.shared.b16 {%0,%1,%2,%3}, [%4];"
        : "=r"(r[0]), "=r"(r[1]), "=r"(r[2]), "=r"(r[3]) : "r"(addr));
}
__device__ __forceinline__ void mma_f16(float& c0, float& c1, float& c2, float& c3,
                                        uint32_t a0, uint32_t a1, uint32_t a2, uint32_t a3,
                                        uint32_t b0, uint32_t b1) {
    asm volatile(
        "mma.sync.aligned.m16n8k16.row.col.f32.f16.f16.f32 "
        "{%0,%1,%2,%3}, {%4,%5,%6,%7}, {%8,%9}, {%0,%1,%2,%3};"
        : "+f"(c0), "+f"(c1), "+f"(c2), "+f"(c3)
        : "r"(a0), "r"(a1), "r"(a2), "r"(a3), "r"(b0), "r"(b1));
}
__device__ __forceinline__ float tanh_fast(float x) {
    float r;
    asm("tanh.approx.f32 %0, %1;" : "=f"(r) : "f"(x));
    return r;
}

// ===========================================================================
// Repacks / transpose / init
// ===========================================================================
__global__ void repack_conv2(const float* __restrict__ conv_w) {
    int idx = blockIdx.x * blockDim.x + threadIdx.x;
    if (idx >= M4_ * KC_) return;
    int mp = idx / KC_;
    int k  = idx - mp * KC_;
    int y  = mp >> 7;
    int g  = (mp >> 5) & 3;
    int cl = mp & 31;
    int m  = g * H_ + y * 32 + cl;
    int tap = (k >= H_) ? 1 : 0;
    int i = k - tap * H_;
    g_Wc2[idx] = __float2half_rn(conv_w[m * (H_ * 2) + i * 2 + tap]);
}

__global__ void repack_inj2(const float* __restrict__ inject_w,
                            const float* __restrict__ inject_b,
                            const float* __restrict__ conv_b) {
    int idx = blockIdx.x * blockDim.x + threadIdx.x;
    if (idx >= M4_ * KI_) return;
    int mp = idx / KI_;
    int k  = idx - mp * KI_;
    int y  = mp >> 7;
    int g  = (mp >> 5) & 3;
    int cl = mp & 31;
    int m  = g * H_ + y * 32 + cl;
    int tap = (k >= NINP_) ? 1 : 0;
    int i = k - tap * NINP_;
    g_Wi2[idx] = __float2half_rn(inject_w[m * (NINP_ * 2) + i * 2 + tap]);
    if (k == 0) g_bias[mp] = inject_b[m] + conv_b[m];
}

__global__ void transpose_x(const float* __restrict__ X) {
    __shared__ float tile[32][33];
    int b  = blockIdx.z;
    int i0 = blockIdx.y * 32;
    int t0 = blockIdx.x * 32;
    int tx = threadIdx.x, ty = threadIdx.y;
#pragma unroll
    for (int j = 0; j < 32; j += 8)
        tile[ty + j][tx] = X[(size_t)(b * NINP_ + i0 + ty + j) * L_ + t0 + tx];
    __syncthreads();
#pragma unroll
    for (int j = 0; j < 32; j += 8)
        g_Xt[(size_t)(b * L_ + t0 + ty + j) * NINP_ + i0 + tx] =
            __float2half_rn(tile[tx][ty + j]);
}

__global__ void init_z0h(const float* __restrict__ z0) {
    int idx = blockIdx.x * blockDim.x + threadIdx.x;
    if (idx < B_ * H_) {
        int b = idx / H_, ch = idx - b * H_;
        g_z0h[idx] = __float2half_rn(z0[b * (2 * H_) + ch]);
    }
}

// fp32 GEMV: pre0[b][mp] = sum_i conv_w[m][i][0] * z0h[b][i]  (interleaved store)
__global__ void gemv_pre0(const float* __restrict__ conv_w,
                          const float* __restrict__ z0) {
    int w = (blockIdx.x * blockDim.x + threadIdx.x) >> 5;
    int lane = threadIdx.x & 31;
    if (w >= M4_ * B_) return;
    int m = w >> 2;
    int b = w & 3;
    float s = 0.0f;
    for (int i = lane; i < H_; i += 32)
        s += conv_w[(size_t)m * (2 * H_) + 2 * i] * z0[b * (2 * H_) + i];
#pragma unroll
    for (int o = 16; o; o >>= 1) s += __shfl_xor_sync(0xFFFFFFFFu, s, o);
    if (lane == 0) {
        int g = m / H_;
        int r = m - g * H_;
        int mp = (r >> 5) * 128 + g * 32 + (r & 31);
        g_pre0[b * M4_ + mp] = s;
    }
}

// ===========================================================================
// Fused GEMM (fp16 mma.sync + ldmatrix), 128(n)x128(m), BK=64, 3 stages,
// 2 CTAs/SM. INJECT: epilogue stores us fp16 AND does layer-0 gating.
// LAYER:  epilogue stages us from gmem, gates, writes h/c fp16 (or out).
// ===========================================================================
#define BK      64
#define KS      72                       // padded row stride (halfs), 144B
#define STG_A   (128 * KS)
#define STG_SZ  (2 * 128 * KS)
#define NSTAGE  3
#define SMEM_BYTES (NSTAGE * STG_SZ * 2) // 110592
// epilogue smem (per 64-row pass)
#define USS     136                      // us_s row stride in halfs (272B)
#define PS      136                      // pre_s row stride in floats
#define PRE_OFF 4352                     // float offset of pre_s (17408B)

template <int KTOT, bool INJECT>
__global__ __launch_bounds__(256, 2)
void gemm_fused(const float* __restrict__ z0, float* __restrict__ out,
                int rd, int last) {
    extern __shared__ __half smh[];
    constexpr int KHALF = KTOT / 2;
    constexpr int NKT = KTOT / BK;

    const __half* __restrict__ Asrc = INJECT ? g_Xt : (rd ? g_hh1 : g_hh0);
    const __half* __restrict__ Bw   = INJECT ? g_Wi2 : g_Wc2;

    const int tid  = threadIdx.x;
    const int wid  = tid >> 5;
    const int lane = tid & 31;
    const int grp  = lane >> 2;
    const int qid  = lane & 3;
    const int n0   = blockIdx.x * 128;
    const int m0   = blockIdx.y * 128;

    const int wn = (wid >> 2) * 64;
    const int wm = (wid & 3) * 32;

    const uint32_t sbase = smem_u32(smh);
    const int lrow = lane & 15;
    const int lcol = (lane >> 4) << 3;

#define LOAD_STAGE(S, K0)                                                        \
    do {                                                                         \
        const int _k0 = (K0);                                                    \
        const uint32_t aoff = ((S) % NSTAGE) * STG_SZ;                           \
        const uint32_t boff = aoff + STG_A;                                      \
        _Pragma("unroll")                                                        \
        for (int j = 0; j < 4; j++) {                                            \
            int idx = tid + j * 256;         /* 0..1023 */                       \
            int r  = idx >> 3;                                                   \
            int c8 = idx & 7;                                                    \
            int kk = _k0 + c8 * 8;                                               \
            {                                                                    \
                int n = n0 + r;                                                  \
                int t = n & (L_ - 1);                                            \
                int b = n >> 10;                                                 \
                uint32_t dst = sbase + (aoff + r * KS + c8 * 8) * 2;             \
                if (kk < KHALF) {                                                \
                    if (t == 0) {                                                \
                        if (INJECT) cp_async16_zero(dst, Asrc);                  \
                        else cp_async16(dst, g_z0h + b * H_ + kk);               \
                    } else {                                                     \
                        cp_async16(dst, Asrc + (size_t)(n - 1) * KHALF + kk);    \
                    }                                                            \
                } else {                                                         \
                    cp_async16(dst, Asrc + (size_t)n * KHALF + (kk - KHALF));    \
                }                                                                \
            }                                                                    \
            {                                                                    \
                uint32_t dst = sbase + (boff + r * KS + c8 * 8) * 2;             \
                cp_async16(dst, Bw + (size_t)(m0 + r) * KTOT + kk);              \
            }                                                                    \
        }                                                                        \
        cp_commit();                                                             \
    } while (0)

    // prologue
#pragma unroll
    for (int s = 0; s < NSTAGE - 1; s++) LOAD_STAGE(s, s * BK);

    float acc[4][4][4];
#pragma unroll
    for (int i = 0; i < 4; i++)
#pragma unroll
        for (int j = 0; j < 4; j++)
#pragma unroll
            for (int e = 0; e < 4; e++) acc[i][j][e] = 0.0f;

#pragma unroll 1
    for (int kt = 0; kt < NKT; kt++) {
        cp_wait<NSTAGE - 2>();
        __syncthreads();

        const int sf = kt + NSTAGE - 1;
        if (sf < NKT) LOAD_STAGE(sf, sf * BK);
        else cp_commit();

        const uint32_t a_base = sbase + (uint32_t)((kt % NSTAGE) * STG_SZ) * 2;
        const uint32_t b_base = a_base + STG_A * 2;

#pragma unroll
        for (int ks = 0; ks < BK; ks += 16) {
            uint32_t af[4][4];
            uint32_t bf[2][4];
#pragma unroll
            for (int fi = 0; fi < 4; fi++) {
                uint32_t addr = a_base +
                    (uint32_t)((wn + fi * 16 + lrow) * KS + ks + lcol) * 2;
                ldmatrix_x4(af[fi], addr);
            }
#pragma unroll
            for (int fh = 0; fh < 2; fh++) {
                uint32_t addr = b_base +
                    (uint32_t)((wm + fh * 16 + lrow) * KS + ks + lcol) * 2;
                ldmatrix_x4(bf[fh], addr);
            }
#pragma unroll
            for (int fi = 0; fi < 4; fi++) {
#pragma unroll
                for (int fh = 0; fh < 2; fh++) {
#pragma unroll
                    for (int s2 = 0; s2 < 2; s2++) {
                        int fj = fh * 2 + s2;
                        mma_f16(acc[fi][fj][0], acc[fi][fj][1],
                                acc[fi][fj][2], acc[fi][fj][3],
                                af[fi][0], af[fi][1], af[fi][2], af[fi][3],
                                bf[fh][s2], bf[fh][s2 + 2]);
                    }
                }
            }
        }
    }

    // ---------------- epilogue ----------------
    __half* us_s  = smh;
    float*  pre_s = (float*)smh + PRE_OFF;
    const int chbase = blockIdx.y * 32;
    const int q  = tid & 7;
    const int nl = tid >> 3;

    if (INJECT) {
        // add bias into acc, store us fp16 (interleaved layout: col = mp - m0)
#pragma unroll
        for (int fi = 0; fi < 4; fi++) {
#pragma unroll
            for (int fj = 0; fj < 4; fj++) {
                int n1  = n0 + wn + fi * 16 + grp;
                int col = wm + fj * 8 + qid * 2;
                float b0 = g_bias[m0 + col], b1 = g_bias[m0 + col + 1];
                acc[fi][fj][0] += b0; acc[fi][fj][1] += b1;
                acc[fi][fj][2] += b0; acc[fi][fj][3] += b1;
                *(__half2*)(g_us2 + (size_t)n1 * M4_ + m0 + col) =
                    __floats2half2_rn(acc[fi][fj][0], acc[fi][fj][1]);
                *(__half2*)(g_us2 + (size_t)(n1 + 8) * M4_ + m0 + col) =
                    __floats2half2_rn(acc[fi][fj][2], acc[fi][fj][3]);
            }
        }
        // layer-0 gating fused: pre = us (+ pre0 at t==0); c_prev = z0c at t==0 else 0
#pragma unroll
        for (int p = 0; p < 2; p++) {
            __syncthreads();
            if ((wid >> 2) == p) {
#pragma unroll
                for (int fi = 0; fi < 4; fi++) {
#pragma unroll
                    for (int fj = 0; fj < 4; fj++) {
                        int r0   = fi * 16 + grp;
                        int cidx = wm + fj * 8 + qid * 2;
                        *(float2*)&pre_s[r0 * PS + cidx] =
                            make_float2(acc[fi][fj][0], acc[fi][fj][1]);
                        *(float2*)&pre_s[(r0 + 8) * PS + cidx] =
                            make_float2(acc[fi][fj][2], acc[fi][fj][3]);
                    }
                }
            }
            __syncthreads();
#pragma unroll
            for (int it = 0; it < 2; it++) {
                int row = nl + it * 32;
                int n = n0 + p * 64 + row;
                int t = n & (L_ - 1);
                int b = n >> 10;
                int ch = chbase + q * 4;

                float pi[4], po[4], pg[4], pf[4], cprev[4];
#pragma unroll
                for (int e = 0; e < 4; e++) {
                    pi[e] = pre_s[row * PS + 0 * 32 + q * 4 + e];
                    po[e] = pre_s[row * PS + 1 * 32 + q * 4 + e];
                    pg[e] = pre_s[row * PS + 2 * 32 + q * 4 + e];
                    pf[e] = pre_s[row * PS + 3 * 32 + q * 4 + e];
                    cprev[e] = 0.0f;
                }
                if (t == 0) {
#pragma unroll
                    for (int e = 0; e < 4; e++) {
                        pi[e] += g_pre0[b * M4_ + m0 + 0 * 32 + q * 4 + e];
                        po[e] += g_pre0[b * M4_ + m0 + 1 * 32 + q * 4 + e];
                        pg[e] += g_pre0[b * M4_ + m0 + 2 * 32 + q * 4 + e];
                        pf[e] += g_pre0[b * M4_ + m0 + 3 * 32 + q * 4 + e];
                        cprev[e] = z0[b * (2 * H_) + H_ + ch + e];
                    }
                }
                __half hh[4], cc[4];
#pragma unroll
                for (int e = 0; e < 4; e++) {
                    float si = 1.0f / (1.0f + __expf(-pi[e]));
                    float so = 1.0f / (1.0f + __expf(-po[e]));
                    float sf = 1.0f / (1.0f + __expf(-pf[e]));
                    float tg = tanh_fast(pg[e]);
                    float c = sf * cprev[e] + si * tg;
                    float h = so * tanh_fast(c);
                    hh[e] = __float2half_rn(h);
                    cc[e] = __float2half_rn(c);
                }
                *(__half2*)(g_hh1 + (size_t)n * H_ + ch)     = __halves2half2(hh[0], hh[1]);
                *(__half2*)(g_hh1 + (size_t)n * H_ + ch + 2) = __halves2half2(hh[2], hh[3]);
                *(__half2*)(g_ch1 + (size_t)n * H_ + ch)     = __halves2half2(cc[0], cc[1]);
                *(__half2*)(g_ch1 + (size_t)n * H_ + ch + 2) = __halves2half2(cc[2], cc[3]);
            }
        }
        return;
    }

    // ---- layer epilogue: 2 passes of 64 n-rows ----
    const __half* __restrict__ cpb = rd ? g_ch1 : g_ch0;
    __half* __restrict__ cn  = rd ? g_ch0 : g_ch1;
    __half* __restrict__ hhn = rd ? g_hh0 : g_hh1;

#pragma unroll
    for (int p = 0; p < 2; p++) {
        __syncthreads();

        // stage us rows [p*64, p*64+64): contiguous 256B per row
#pragma unroll
        for (int j = 0; j < 4; j++) {
            int id = tid + j * 256;
            int row = id >> 4;
            int c   = id & 15;
            int n = n0 + p * 64 + row;
            cp_async16(sbase + (uint32_t)(row * USS + c * 8) * 2,
                       g_us2 + (size_t)n * M4_ + m0 + c * 8);
        }
        cp_commit();

        if ((wid >> 2) == p) {
#pragma unroll
            for (int fi = 0; fi < 4; fi++) {
#pragma unroll
                for (int fj = 0; fj < 4; fj++) {
                    int r0   = fi * 16 + grp;
                    int cidx = wm + fj * 8 + qid * 2;
                    *(float2*)&pre_s[r0 * PS + cidx] =
                        make_float2(acc[fi][fj][0], acc[fi][fj][1]);
                    *(float2*)&pre_s[(r0 + 8) * PS + cidx] =
                        make_float2(acc[fi][fj][2], acc[fi][fj][3]);
                }
            }
        }
        cp_wait<0>();
        __syncthreads();

#pragma unroll
        for (int it = 0; it < 2; it++) {
            int row = nl + it * 32;
            int n = n0 + p * 64 + row;
            int t = n & (L_ - 1);
            int b = n >> 10;
            int ch = chbase + q * 4;

            float4 pi4 = *(const float4*)&pre_s[row * PS + 0 * 32 + q * 4];
            float4 po4 = *(const float4*)&pre_s[row * PS + 1 * 32 + q * 4];
            float4 pg4 = *(const float4*)&pre_s[row * PS + 2 * 32 + q * 4];
            float4 pf4 = *(const float4*)&pre_s[row * PS + 3 * 32 + q * 4];

            const __half* ur = us_s + row * USS + q * 4;
            float2 uiA = __half22float2(*(const __half2*)(ur + 0 * 32));
            float2 uiB = __half22float2(*(const __half2*)(ur + 0 * 32 + 2));
            float2 uoA = __half22float2(*(const __half2*)(ur + 1 * 32));
            float2 uoB = __half22float2(*(const __half2*)(ur + 1 * 32 + 2));
            float2 ugA = __half22float2(*(const __half2*)(ur + 2 * 32));
            float2 ugB = __half22float2(*(const __half2*)(ur + 2 * 32 + 2));
            float2 ufA = __half22float2(*(const __half2*)(ur + 3 * 32));
            float2 ufB = __half22float2(*(const __half2*)(ur + 3 * 32 + 2));
            float ui[4] = {uiA.x, uiA.y, uiB.x, uiB.y};
            float uo[4] = {uoA.x, uoA.y, uoB.x, uoB.y};
            float ug[4] = {ugA.x, ugA.y, ugB.x, ugB.y};
            float uf[4] = {ufA.x, ufA.y, ufB.x, ufB.y};

            float cpl[4];
            if (t == 0) {
                float4 zc = *(const float4*)(z0 + b * (2 * H_) + H_ + ch);
                cpl[0] = zc.x; cpl[1] = zc.y; cpl[2] = zc.z; cpl[3] = zc.w;
            } else {
                float2 cA = __half22float2(*(const __half2*)(cpb + (size_t)(n - 1) * H_ + ch));
                float2 cB = __half22float2(*(const __half2*)(cpb + (size_t)(n - 1) * H_ + ch + 2));
                cpl[0] = cA.x; cpl[1] = cA.y; cpl[2] = cB.x; cpl[3] = cB.y;
            }

            const float* pip = (const float*)&pi4;
            const float* pop = (const float*)&po4;
            const float* pgp = (const float*)&pg4;
            const float* pfp = (const float*)&pf4;

            float4 hv, cv;
            float* hvp = (float*)&hv;
            float* cvp = (float*)&cv;
#pragma unroll
            for (int e = 0; e < 4; e++) {
                float pi = pip[e] + ui[e];
                float po = pop[e] + uo[e];
                float pg = pgp[e] + ug[e];
                float pf = pfp[e] + uf[e];
                float si = 1.0f / (1.0f + __expf(-pi));
                float so = 1.0f / (1.0f + __expf(-po));
                float sf = 1.0f / (1.0f + __expf(-pf));
                float tg = tanh_fast(pg);
                float c = sf * cpl[e] + si * tg;
                float h = so * tanh_fast(c);
                hvp[e] = h;
                cvp[e] = c;
            }
            if (last) {
                if (chbase >= H_ - NOUT_) {
                    *(float4*)(out + (size_t)n * NOUT_ + (ch - (H_ - NOUT_))) = hv;
                }
                if (t == L_ - 1) {
                    const size_t tot = (size_t)B_ * L_ * NOUT_;
                    *(float4*)(out + tot + b * (2 * H_) + ch)      = hv;
                    *(float4*)(out + tot + b * (2 * H_) + H_ + ch) = cv;
                }
            } else {
                __half2 h01 = __floats2half2_rn(hvp[0], hvp[1]);
                __half2 h23 = __floats2half2_rn(hvp[2], hvp[3]);
                __half2 c01 = __floats2half2_rn(cvp[0], cvp[1]);
                __half2 c23 = __floats2half2_rn(cvp[2], cvp[3]);
                *(__half2*)(hhn + (size_t)n * H_ + ch)     = h01;
                *(__half2*)(hhn + (size_t)n * H_ + ch + 2) = h23;
                *(__half2*)(cn + (size_t)n * H_ + ch)      = c01;
                *(__half2*)(cn + (size_t)n * H_ + ch + 2)  = c23;
            }
        }
    }
#undef LOAD_STAGE
}

// ===========================================================================
extern "C" void kernel_launch(void* const* d_in, const int* in_sizes, int n_in,
                              void* d_out, int out_size) {
    const float* X        = (const float*)d_in[0];
    const float* z0       = (const float*)d_in[1];
    const float* inject_w = (const float*)d_in[2];
    const float* inject_b = (const float*)d_in[3];
    const float* conv_w   = (const float*)d_in[4];
    const float* conv_b   = (const float*)d_in[5];
    float* out = (float*)d_out;

    cudaFuncSetAttribute(gemm_fused<KI_, true>,
                         cudaFuncAttributeMaxDynamicSharedMemorySize, SMEM_BYTES);
    cudaFuncSetAttribute(gemm_fused<KC_, false>,
                         cudaFuncAttributeMaxDynamicSharedMemorySize, SMEM_BYTES);

    repack_conv2<<<(M4_ * KC_ + 255) / 256, 256>>>(conv_w);
    repack_inj2<<<(M4_ * KI_ + 255) / 256, 256>>>(inject_w, inject_b, conv_b);
    transpose_x<<<dim3(L_ / 32, NINP_ / 32, B_), dim3(32, 8)>>>(X);
    init_z0h<<<(B_ * H_ + 255) / 256, 256>>>(z0);
    gemv_pre0<<<(M4_ * B_ * 32 + 255) / 256, 256>>>(conv_w, z0);

    // inject GEMM -> us (fp16, interleaved) + fused layer-0 gating -> hh1/ch1
    gemm_fused<KI_, true><<<dim3(N_ / 128, M4_ / 128), 256, SMEM_BYTES>>>(
        z0, out, 0, 0);

    // layers 1..9
    for (int l = 1; l < NLAYER_; l++)
        gemm_fused<KC_, false><<<dim3(N_ / 128, M4_ / 128), 256, SMEM_BYTES>>>(
            z0, out, l & 1, l == NLAYER_ - 1);
}

// round 12
// speedup vs baseline: 9.3060x; 1.0097x over previous
#include <cuda_runtime.h>
#include <cuda_fp16.h>
#include <math.h>
#include <cstdint>

// Problem constants
#define B_    4
#define H_    768
#define L_    1024
#define N_    4096          // B_*L_
#define M4_   3072          // 4*H_
#define NINP_ 512
#define KC_   1536          // conv K  ([h(t-1); h(t)])
#define KI_   1024          // inject K ([x(t-1); x(t)])
#define NOUT_ 256
#define NLAYER_ 10

// Scratch (device globals; no allocation allowed)
// us layout: [n][mp], mp = y*128 + g*32 + cl  (gate-interleaved, y = ch/32)
__device__ __half g_us2[(size_t)N_ * M4_];
__device__ __half g_ch0[(size_t)N_ * H_];  // c fp16 inter-layer
__device__ __half g_ch1[(size_t)N_ * H_];
__device__ __half g_hh0[(size_t)N_ * H_];  // h fp16 (GEMM A input)
__device__ __half g_hh1[(size_t)N_ * H_];
__device__ __half g_Wc2[(size_t)M4_ * KC_]; // conv W fp16, gate-interleaved rows
__device__ __half g_Wi2[(size_t)M4_ * KI_]; // inject W fp16, gate-interleaved rows
__device__ __half g_Xt[(size_t)N_ * NINP_]; // X fp16, time-major [n][i]
__device__ __half g_z0h[B_ * H_];           // z0 h-part fp16
__device__ float  g_bias[M4_];              // inject_b + conv_b, interleaved index
__device__ float  g_pre0[B_ * M4_];         // layer-0 t==0 corr: W0 @ z0h, interleaved

// ===========================================================================
// Helpers
// ===========================================================================
__device__ __forceinline__ uint32_t smem_u32(const void* p) {
    uint32_t a;
    asm("{ .reg .u64 t; cvta.to.shared.u64 t, %1; cvt.u32.u64 %0, t; }"
        : "=r"(a) : "l"(p));
    return a;
}
__device__ __forceinline__ void cp_async16(uint32_t dst, const void* src) {
    asm volatile("cp.async.cg.shared.global [%0], [%1], 16;" :: "r"(dst), "l"(src));
}
__device__ __forceinline__ void cp_async16_zero(uint32_t dst, const void* src) {
    asm volatile("cp.async.cg.shared.global [%0], [%1], 16, 0;" :: "r"(dst), "l"(src));
}
__device__ __forceinline__ void cp_commit() {
    asm volatile("cp.async.commit_group;");
}
template <int Npend>
__device__ __forceinline__ void cp_wait() {
    asm volatile("cp.async.wait_group %0;" :: "n"(Npend));
}
__device__ __forceinline__ void ldmatrix_x4(uint32_t* r, uint32_t addr) {
    asm volatile("ldmatrix.sync.aligned.m8n8.x4.shared.b16 {%0,%1,%2,%3}, [%4];"
        : "=r"(r[0]), "=r"(r[1]), "=r"(r[2]), "=r"(r[3]) : "r"(addr));
}
__device__ __forceinline__ void mma_f16(float& c0, float& c1, float& c2, float& c3,
                                        uint32_t a0, uint32_t a1, uint32_t a2, uint32_t a3,
                                        uint32_t b0, uint32_t b1) {
    asm volatile(
        "mma.sync.aligned.m16n8k16.row.col.f32.f16.f16.f32 "
        "{%0,%1,%2,%3}, {%4,%5,%6,%7}, {%8,%9}, {%0,%1,%2,%3};"
        : "+f"(c0), "+f"(c1), "+f"(c2), "+f"(c3)
        : "r"(a0), "r"(a1), "r"(a2), "r"(a3), "r"(b0), "r"(b1));
}
__device__ __forceinline__ float tanh_fast(float x) {
    float r;
    asm("tanh.approx.f32 %0, %1;" : "=f"(r) : "f"(x));
    return r;
}
__device__ __forceinline__ void griddep_wait() {
    asm volatile("griddepcontrol.wait;" ::: "memory");
}

// ===========================================================================
// Repacks / transpose / init
// ===========================================================================
__global__ void repack_conv2(const float* __restrict__ conv_w) {
    int idx = blockIdx.x * blockDim.x + threadIdx.x;
    if (idx >= M4_ * KC_) return;
    int mp = idx / KC_;
    int k  = idx - mp * KC_;
    int y  = mp >> 7;
    int g  = (mp >> 5) & 3;
    int cl = mp & 31;
    int m  = g * H_ + y * 32 + cl;
    int tap = (k >= H_) ? 1 : 0;
    int i = k - tap * H_;
    g_Wc2[idx] = __float2half_rn(conv_w[m * (H_ * 2) + i * 2 + tap]);
}

__global__ void repack_inj2(const float* __restrict__ inject_w,
                            const float* __restrict__ inject_b,
                            const float* __restrict__ conv_b) {
    int idx = blockIdx.x * blockDim.x + threadIdx.x;
    if (idx >= M4_ * KI_) return;
    int mp = idx / KI_;
    int k  = idx - mp * KI_;
    int y  = mp >> 7;
    int g  = (mp >> 5) & 3;
    int cl = mp & 31;
    int m  = g * H_ + y * 32 + cl;
    int tap = (k >= NINP_) ? 1 : 0;
    int i = k - tap * NINP_;
    g_Wi2[idx] = __float2half_rn(inject_w[m * (NINP_ * 2) + i * 2 + tap]);
    if (k == 0) g_bias[mp] = inject_b[m] + conv_b[m];
}

__global__ void transpose_x(const float* __restrict__ X) {
    __shared__ float tile[32][33];
    int b  = blockIdx.z;
    int i0 = blockIdx.y * 32;
    int t0 = blockIdx.x * 32;
    int tx = threadIdx.x, ty = threadIdx.y;
#pragma unroll
    for (int j = 0; j < 32; j += 8)
        tile[ty + j][tx] = X[(size_t)(b * NINP_ + i0 + ty + j) * L_ + t0 + tx];
    __syncthreads();
#pragma unroll
    for (int j = 0; j < 32; j += 8)
        g_Xt[(size_t)(b * L_ + t0 + ty + j) * NINP_ + i0 + tx] =
            __float2half_rn(tile[tx][ty + j]);
}

__global__ void init_z0h(const float* __restrict__ z0) {
    int idx = blockIdx.x * blockDim.x + threadIdx.x;
    if (idx < B_ * H_) {
        int b = idx / H_, ch = idx - b * H_;
        g_z0h[idx] = __float2half_rn(z0[b * (2 * H_) + ch]);
    }
}

// fp32 GEMV: pre0[b][mp] = sum_i conv_w[m][i][0] * z0h[b][i]  (interleaved store)
__global__ void gemv_pre0(const float* __restrict__ conv_w,
                          const float* __restrict__ z0) {
    int w = (blockIdx.x * blockDim.x + threadIdx.x) >> 5;
    int lane = threadIdx.x & 31;
    if (w >= M4_ * B_) return;
    int m = w >> 2;
    int b = w & 3;
    float s = 0.0f;
    for (int i = lane; i < H_; i += 32)
        s += conv_w[(size_t)m * (2 * H_) + 2 * i] * z0[b * (2 * H_) + i];
#pragma unroll
    for (int o = 16; o; o >>= 1) s += __shfl_xor_sync(0xFFFFFFFFu, s, o);
    if (lane == 0) {
        int g = m / H_;
        int r = m - g * H_;
        int mp = (r >> 5) * 128 + g * 32 + (r & 31);
        g_pre0[b * M4_ + mp] = s;
    }
}

// ===========================================================================
// Fused GEMM (fp16 mma.sync + ldmatrix), 128(n)x128(m), BK=64, 3 stages,
// 2 CTAs/SM, PDL: weight prologue before griddepcontrol.wait.
// ===========================================================================
#define BK      64
#define KS      72                       // padded row stride (halfs), 144B
#define STG_A   (128 * KS)
#define STG_SZ  (2 * 128 * KS)
#define NSTAGE  3
#define SMEM_BYTES (NSTAGE * STG_SZ * 2) // 110592
// epilogue smem (per 64-row pass)
#define USS     136                      // us_s row stride in halfs
#define PS      136                      // pre_s row stride in floats
#define PRE_OFF 4352                     // float offset of pre_s

template <int KTOT, bool INJECT>
__global__ __launch_bounds__(256, 2)
void gemm_fused(const float* __restrict__ z0, float* __restrict__ out,
                int rd, int last) {
    extern __shared__ __half smh[];
    constexpr int KHALF = KTOT / 2;
    constexpr int NKT = KTOT / BK;

    const __half* __restrict__ Asrc = INJECT ? g_Xt : (rd ? g_hh1 : g_hh0);
    const __half* __restrict__ Bw   = INJECT ? g_Wi2 : g_Wc2;

    const int tid  = threadIdx.x;
    const int wid  = tid >> 5;
    const int lane = tid & 31;
    const int grp  = lane >> 2;
    const int qid  = lane & 3;
    const int n0   = blockIdx.x * 128;
    const int m0   = blockIdx.y * 128;

    const int wn = (wid >> 2) * 64;
    const int wm = (wid & 3) * 32;

    const uint32_t sbase = smem_u32(smh);
    const int lrow = lane & 15;
    const int lcol = (lane >> 4) << 3;

#define LOAD_STAGE_B(S, K0)                                                      \
    do {                                                                         \
        const int _k0 = (K0);                                                    \
        const uint32_t boff = ((S) % NSTAGE) * STG_SZ + STG_A;                   \
        _Pragma("unroll")                                                        \
        for (int j = 0; j < 4; j++) {                                            \
            int idx = tid + j * 256;                                             \
            int r  = idx >> 3;                                                   \
            int c8 = idx & 7;                                                    \
            int kk = _k0 + c8 * 8;                                               \
            uint32_t dst = sbase + (boff + r * KS + c8 * 8) * 2;                 \
            cp_async16(dst, Bw + (size_t)(m0 + r) * KTOT + kk);                  \
        }                                                                        \
        cp_commit();                                                             \
    } while (0)

#define LOAD_STAGE_A(S, K0)                                                      \
    do {                                                                         \
        const int _k0 = (K0);                                                    \
        const uint32_t aoff = ((S) % NSTAGE) * STG_SZ;                           \
        _Pragma("unroll")                                                        \
        for (int j = 0; j < 4; j++) {                                            \
            int idx = tid + j * 256;                                             \
            int r  = idx >> 3;                                                   \
            int c8 = idx & 7;                                                    \
            int kk = _k0 + c8 * 8;                                               \
            int n = n0 + r;                                                      \
            int t = n & (L_ - 1);                                                \
            int b = n >> 10;                                                     \
            uint32_t dst = sbase + (aoff + r * KS + c8 * 8) * 2;                 \
            if (kk < KHALF) {                                                    \
                if (t == 0) {                                                    \
                    if (INJECT) cp_async16_zero(dst, Asrc);                      \
                    else cp_async16(dst, g_z0h + b * H_ + kk);                   \
                } else {                                                         \
                    cp_async16(dst, Asrc + (size_t)(n - 1) * KHALF + kk);        \
                }                                                                \
            } else {                                                             \
                cp_async16(dst, Asrc + (size_t)n * KHALF + (kk - KHALF));        \
            }                                                                    \
        }                                                                        \
        cp_commit();                                                             \
    } while (0)

#define LOAD_STAGE(S, K0)                                                        \
    do {                                                                         \
        const int _k0 = (K0);                                                    \
        const uint32_t aoff = ((S) % NSTAGE) * STG_SZ;                           \
        const uint32_t boff = aoff + STG_A;                                      \
        _Pragma("unroll")                                                        \
        for (int j = 0; j < 4; j++) {                                            \
            int idx = tid + j * 256;                                             \
            int r  = idx >> 3;                                                   \
            int c8 = idx & 7;                                                    \
            int kk = _k0 + c8 * 8;                                               \
            {                                                                    \
                int n = n0 + r;                                                  \
                int t = n & (L_ - 1);                                            \
                int b = n >> 10;                                                 \
                uint32_t dst = sbase + (aoff + r * KS + c8 * 8) * 2;             \
                if (kk < KHALF) {                                                \
                    if (t == 0) {                                                \
                        if (INJECT) cp_async16_zero(dst, Asrc);                  \
                        else cp_async16(dst, g_z0h + b * H_ + kk);               \
                    } else {                                                     \
                        cp_async16(dst, Asrc + (size_t)(n - 1) * KHALF + kk);    \
                    }                                                            \
                } else {                                                         \
                    cp_async16(dst, Asrc + (size_t)n * KHALF + (kk - KHALF));    \
                }                                                                \
            }                                                                    \
            {                                                                    \
                uint32_t dst = sbase + (boff + r * KS + c8 * 8) * 2;             \
                cp_async16(dst, Bw + (size_t)(m0 + r) * KTOT + kk);              \
            }                                                                    \
        }                                                                        \
        cp_commit();                                                             \
    } while (0)

    // prologue: weights first (independent of predecessor kernel), then wait,
    // then the h/x-dependent A tiles.
    LOAD_STAGE_B(0, 0);
    LOAD_STAGE_B(1, BK);
    griddep_wait();
    LOAD_STAGE_A(0, 0);
    LOAD_STAGE_A(1, BK);

    float acc[4][4][4];
#pragma unroll
    for (int i = 0; i < 4; i++)
#pragma unroll
        for (int j = 0; j < 4; j++)
#pragma unroll
            for (int e = 0; e < 4; e++) acc[i][j][e] = 0.0f;

#pragma unroll 1
    for (int kt = 0; kt < NKT; kt++) {
        cp_wait<NSTAGE - 2>();
        __syncthreads();

        const int sf = kt + NSTAGE - 1;
        if (sf < NKT) LOAD_STAGE(sf, sf * BK);
        else cp_commit();

        const uint32_t a_base = sbase + (uint32_t)((kt % NSTAGE) * STG_SZ) * 2;
        const uint32_t b_base = a_base + STG_A * 2;

#pragma unroll
        for (int ks = 0; ks < BK; ks += 16) {
            uint32_t af[4][4];
            uint32_t bf[2][4];
#pragma unroll
            for (int fi = 0; fi < 4; fi++) {
                uint32_t addr = a_base +
                    (uint32_t)((wn + fi * 16 + lrow) * KS + ks + lcol) * 2;
                ldmatrix_x4(af[fi], addr);
            }
#pragma unroll
            for (int fh = 0; fh < 2; fh++) {
                uint32_t addr = b_base +
                    (uint32_t)((wm + fh * 16 + lrow) * KS + ks + lcol) * 2;
                ldmatrix_x4(bf[fh], addr);
            }
#pragma unroll
            for (int fi = 0; fi < 4; fi++) {
#pragma unroll
                for (int fh = 0; fh < 2; fh++) {
#pragma unroll
                    for (int s2 = 0; s2 < 2; s2++) {
                        int fj = fh * 2 + s2;
                        mma_f16(acc[fi][fj][0], acc[fi][fj][1],
                                acc[fi][fj][2], acc[fi][fj][3],
                                af[fi][0], af[fi][1], af[fi][2], af[fi][3],
                                bf[fh][s2], bf[fh][s2 + 2]);
                    }
                }
            }
        }
    }

    // ---------------- epilogue ----------------
    __half* us_s  = smh;
    float*  pre_s = (float*)smh + PRE_OFF;
    const int chbase = blockIdx.y * 32;
    const int q  = tid & 7;
    const int nl = tid >> 3;

    if (INJECT) {
#pragma unroll
        for (int fi = 0; fi < 4; fi++) {
#pragma unroll
            for (int fj = 0; fj < 4; fj++) {
                int n1  = n0 + wn + fi * 16 + grp;
                int col = wm + fj * 8 + qid * 2;
                float b0 = g_bias[m0 + col], b1 = g_bias[m0 + col + 1];
                acc[fi][fj][0] += b0; acc[fi][fj][1] += b1;
                acc[fi][fj][2] += b0; acc[fi][fj][3] += b1;
                *(__half2*)(g_us2 + (size_t)n1 * M4_ + m0 + col) =
                    __floats2half2_rn(acc[fi][fj][0], acc[fi][fj][1]);
                *(__half2*)(g_us2 + (size_t)(n1 + 8) * M4_ + m0 + col) =
                    __floats2half2_rn(acc[fi][fj][2], acc[fi][fj][3]);
            }
        }
        // fused layer-0 gating
#pragma unroll
        for (int p = 0; p < 2; p++) {
            __syncthreads();
            if ((wid >> 2) == p) {
#pragma unroll
                for (int fi = 0; fi < 4; fi++) {
#pragma unroll
                    for (int fj = 0; fj < 4; fj++) {
                        int r0   = fi * 16 + grp;
                        int cidx = wm + fj * 8 + qid * 2;
                        *(float2*)&pre_s[r0 * PS + cidx] =
                            make_float2(acc[fi][fj][0], acc[fi][fj][1]);
                        *(float2*)&pre_s[(r0 + 8) * PS + cidx] =
                            make_float2(acc[fi][fj][2], acc[fi][fj][3]);
                    }
                }
            }
            __syncthreads();
#pragma unroll
            for (int it = 0; it < 2; it++) {
                int row = nl + it * 32;
                int n = n0 + p * 64 + row;
                int t = n & (L_ - 1);
                int b = n >> 10;
                int ch = chbase + q * 4;

                float pi[4], po[4], pg[4], pf[4], cprev[4];
#pragma unroll
                for (int e = 0; e < 4; e++) {
                    pi[e] = pre_s[row * PS + 0 * 32 + q * 4 + e];
                    po[e] = pre_s[row * PS + 1 * 32 + q * 4 + e];
                    pg[e] = pre_s[row * PS + 2 * 32 + q * 4 + e];
                    pf[e] = pre_s[row * PS + 3 * 32 + q * 4 + e];
                    cprev[e] = 0.0f;
                }
                if (t == 0) {
#pragma unroll
                    for (int e = 0; e < 4; e++) {
                        pi[e] += g_pre0[b * M4_ + m0 + 0 * 32 + q * 4 + e];
                        po[e] += g_pre0[b * M4_ + m0 + 1 * 32 + q * 4 + e];
                        pg[e] += g_pre0[b * M4_ + m0 + 2 * 32 + q * 4 + e];
                        pf[e] += g_pre0[b * M4_ + m0 + 3 * 32 + q * 4 + e];
                        cprev[e] = z0[b * (2 * H_) + H_ + ch + e];
                    }
                }
                __half hh[4], cc[4];
#pragma unroll
                for (int e = 0; e < 4; e++) {
                    float si = 1.0f / (1.0f + __expf(-pi[e]));
                    float so = 1.0f / (1.0f + __expf(-po[e]));
                    float sf = 1.0f / (1.0f + __expf(-pf[e]));
                    float tg = tanh_fast(pg[e]);
                    float c = sf * cprev[e] + si * tg;
                    float h = so * tanh_fast(c);
                    hh[e] = __float2half_rn(h);
                    cc[e] = __float2half_rn(c);
                }
                *(__half2*)(g_hh1 + (size_t)n * H_ + ch)     = __halves2half2(hh[0], hh[1]);
                *(__half2*)(g_hh1 + (size_t)n * H_ + ch + 2) = __halves2half2(hh[2], hh[3]);
                *(__half2*)(g_ch1 + (size_t)n * H_ + ch)     = __halves2half2(cc[0], cc[1]);
                *(__half2*)(g_ch1 + (size_t)n * H_ + ch + 2) = __halves2half2(cc[2], cc[3]);
            }
        }
        return;
    }

    // ---- layer epilogue: 2 passes of 64 n-rows ----
    const __half* __restrict__ cpb = rd ? g_ch1 : g_ch0;
    __half* __restrict__ cn  = rd ? g_ch0 : g_ch1;
    __half* __restrict__ hhn = rd ? g_hh0 : g_hh1;

#pragma unroll
    for (int p = 0; p < 2; p++) {
        __syncthreads();

#pragma unroll
        for (int j = 0; j < 4; j++) {
            int id = tid + j * 256;
            int row = id >> 4;
            int c   = id & 15;
            int n = n0 + p * 64 + row;
            cp_async16(sbase + (uint32_t)(row * USS + c * 8) * 2,
                       g_us2 + (size_t)n * M4_ + m0 + c * 8);
        }
        cp_commit();

        if ((wid >> 2) == p) {
#pragma unroll
            for (int fi = 0; fi < 4; fi++) {
#pragma unroll
                for (int fj = 0; fj < 4; fj++) {
                    int r0   = fi * 16 + grp;
                    int cidx = wm + fj * 8 + qid * 2;
                    *(float2*)&pre_s[r0 * PS + cidx] =
                        make_float2(acc[fi][fj][0], acc[fi][fj][1]);
                    *(float2*)&pre_s[(r0 + 8) * PS + cidx] =
                        make_float2(acc[fi][fj][2], acc[fi][fj][3]);
                }
            }
        }
        cp_wait<0>();
        __syncthreads();

#pragma unroll
        for (int it = 0; it < 2; it++) {
            int row = nl + it * 32;
            int n = n0 + p * 64 + row;
            int t = n & (L_ - 1);
            int b = n >> 10;
            int ch = chbase + q * 4;

            float4 pi4 = *(const float4*)&pre_s[row * PS + 0 * 32 + q * 4];
            float4 po4 = *(const float4*)&pre_s[row * PS + 1 * 32 + q * 4];
            float4 pg4 = *(const float4*)&pre_s[row * PS + 2 * 32 + q * 4];
            float4 pf4 = *(const float4*)&pre_s[row * PS + 3 * 32 + q * 4];

            const __half* ur = us_s + row * USS + q * 4;
            float2 uiA = __half22float2(*(const __half2*)(ur + 0 * 32));
            float2 uiB = __half22float2(*(const __half2*)(ur + 0 * 32 + 2));
            float2 uoA = __half22float2(*(const __half2*)(ur + 1 * 32));
            float2 uoB = __half22float2(*(const __half2*)(ur + 1 * 32 + 2));
            float2 ugA = __half22float2(*(const __half2*)(ur + 2 * 32));
            float2 ugB = __half22float2(*(const __half2*)(ur + 2 * 32 + 2));
            float2 ufA = __half22float2(*(const __half2*)(ur + 3 * 32));
            float2 ufB = __half22float2(*(const __half2*)(ur + 3 * 32 + 2));
            float ui[4] = {uiA.x, uiA.y, uiB.x, uiB.y};
            float uo[4] = {uoA.x, uoA.y, uoB.x, uoB.y};
            float ug[4] = {ugA.x, ugA.y, ugB.x, ugB.y};
            float uf[4] = {ufA.x, ufA.y, ufB.x, ufB.y};

            float cpl[4];
            if (t == 0) {
                float4 zc = *(const float4*)(z0 + b * (2 * H_) + H_ + ch);
                cpl[0] = zc.x; cpl[1] = zc.y; cpl[2] = zc.z; cpl[3] = zc.w;
            } else {
                float2 cA = __half22float2(*(const __half2*)(cpb + (size_t)(n - 1) * H_ + ch));
                float2 cB = __half22float2(*(const __half2*)(cpb + (size_t)(n - 1) * H_ + ch + 2));
                cpl[0] = cA.x; cpl[1] = cA.y; cpl[2] = cB.x; cpl[3] = cB.y;
            }

            const float* pip = (const float*)&pi4;
            const float* pop = (const float*)&po4;
            const float* pgp = (const float*)&pg4;
            const float* pfp = (const float*)&pf4;

            float4 hv, cv;
            float* hvp = (float*)&hv;
            float* cvp = (float*)&cv;
#pragma unroll
            for (int e = 0; e < 4; e++) {
                float pi = pip[e] + ui[e];
                float po = pop[e] + uo[e];
                float pg = pgp[e] + ug[e];
                float pf = pfp[e] + uf[e];
                float si = 1.0f / (1.0f + __expf(-pi));
                float so = 1.0f / (1.0f + __expf(-po));
                float sf = 1.0f / (1.0f + __expf(-pf));
                float tg = tanh_fast(pg);
                float c = sf * cpl[e] + si * tg;
                float h = so * tanh_fast(c);
                hvp[e] = h;
                cvp[e] = c;
            }
            if (last) {
                if (chbase >= H_ - NOUT_) {
                    *(float4*)(out + (size_t)n * NOUT_ + (ch - (H_ - NOUT_))) = hv;
                }
                if (t == L_ - 1) {
                    const size_t tot = (size_t)B_ * L_ * NOUT_;
                    *(float4*)(out + tot + b * (2 * H_) + ch)      = hv;
                    *(float4*)(out + tot + b * (2 * H_) + H_ + ch) = cv;
                }
            } else {
                __half2 h01 = __floats2half2_rn(hvp[0], hvp[1]);
                __half2 h23 = __floats2half2_rn(hvp[2], hvp[3]);
                __half2 c01 = __floats2half2_rn(cvp[0], cvp[1]);
                __half2 c23 = __floats2half2_rn(cvp[2], cvp[3]);
                *(__half2*)(hhn + (size_t)n * H_ + ch)     = h01;
                *(__half2*)(hhn + (size_t)n * H_ + ch + 2) = h23;
                *(__half2*)(cn + (size_t)n * H_ + ch)      = c01;
                *(__half2*)(cn + (size_t)n * H_ + ch + 2)  = c23;
            }
        }
    }
#undef LOAD_STAGE
#undef LOAD_STAGE_A
#undef LOAD_STAGE_B
}

// ===========================================================================
// Host-side PDL launch with plain-launch fallback
// ===========================================================================
template <int KTOT, bool INJECT>
static void launch_gemm_pdl(const float* z0, float* out, int rd, int last) {
    cudaLaunchConfig_t cfg = {};
    cfg.gridDim = dim3(N_ / 128, M4_ / 128);
    cfg.blockDim = dim3(256);
    cfg.dynamicSmemBytes = SMEM_BYTES;
    cfg.stream = 0;
    cudaLaunchAttribute attr[1];
    attr[0].id = cudaLaunchAttributeProgrammaticStreamSerialization;
    attr[0].val.programmaticStreamSerializationAllowed = 1;
    cfg.attrs = attr;
    cfg.numAttrs = 1;
    cudaError_t e = cudaLaunchKernelEx(&cfg, gemm_fused<KTOT, INJECT>,
                                       z0, out, rd, last);
    if (e != cudaSuccess) {
        cudaGetLastError();  // clear
        gemm_fused<KTOT, INJECT>
            <<<dim3(N_ / 128, M4_ / 128), 256, SMEM_BYTES>>>(z0, out, rd, last);
    }
}

// ===========================================================================
extern "C" void kernel_launch(void* const* d_in, const int* in_sizes, int n_in,
                              void* d_out, int out_size) {
    const float* X        = (const float*)d_in[0];
    const float* z0       = (const float*)d_in[1];
    const float* inject_w = (const float*)d_in[2];
    const float* inject_b = (const float*)d_in[3];
    const float* conv_w   = (const float*)d_in[4];
    const float* conv_b   = (const float*)d_in[5];
    float* out = (float*)d_out;

    cudaFuncSetAttribute(gemm_fused<KI_, true>,
                         cudaFuncAttributeMaxDynamicSharedMemorySize, SMEM_BYTES);
    cudaFuncSetAttribute(gemm_fused<KC_, false>,
                         cudaFuncAttributeMaxDynamicSharedMemorySize, SMEM_BYTES);

    repack_conv2<<<(M4_ * KC_ + 255) / 256, 256>>>(conv_w);
    repack_inj2<<<(M4_ * KI_ + 255) / 256, 256>>>(inject_w, inject_b, conv_b);
    transpose_x<<<dim3(L_ / 32, NINP_ / 32, B_), dim3(32, 8)>>>(X);
    init_z0h<<<(B_ * H_ + 255) / 256, 256>>>(z0);
    gemv_pre0<<<(M4_ * B_ * 32 + 255) / 256, 256>>>(conv_w, z0);

    // inject GEMM -> us (fp16, interleaved) + fused layer-0 gating -> hh1/ch1
    launch_gemm_pdl<KI_, true>(z0, out, 0, 0);

    // layers 1..9
    for (int l = 1; l < NLAYER_; l++)
        launch_gemm_pdl<KC_, false>(z0, out, l & 1, l == NLAYER_ - 1);
}

// round 13
// speedup vs baseline: 9.3227x; 1.0018x over previous
#include <cuda_runtime.h>
#include <cuda_fp16.h>
#include <math.h>
#include <cstdint>

// Problem constants
#define B_    4
#define H_    768
#define L_    1024
#define N_    4096          // B_*L_
#define M4_   3072          // 4*H_
#define NINP_ 512
#define KC_   1536          // conv K  ([h(t-1); h(t)])
#define KI_   1024          // inject K ([x(t-1); x(t)])
#define NOUT_ 256
#define NLAYER_ 10

// Scratch (device globals; no allocation allowed)
// us layout: [n][mp], mp = y*128 + g*32 + cl  (gate-interleaved, y = ch/32)
__device__ __half g_us2[(size_t)N_ * M4_];
__device__ __half g_ch0[(size_t)N_ * H_];  // c fp16 inter-layer
__device__ __half g_ch1[(size_t)N_ * H_];
__device__ __half g_hh0[(size_t)N_ * H_];  // h fp16 (GEMM A input)
__device__ __half g_hh1[(size_t)N_ * H_];
__device__ __half g_Wc2[(size_t)M4_ * KC_]; // conv W fp16, gate-interleaved rows
__device__ __half g_Wi2[(size_t)M4_ * KI_]; // inject W fp16, gate-interleaved rows
__device__ __half g_Xt[(size_t)N_ * NINP_]; // X fp16, time-major [n][i]
__device__ __half g_z0h[B_ * H_];           // z0 h-part fp16
__device__ float  g_bias[M4_];              // inject_b + conv_b, interleaved index
__device__ float  g_pre0[B_ * M4_];         // layer-0 t==0 corr: W0 @ z0h, interleaved

// ===========================================================================
// Helpers
// ===========================================================================
__device__ __forceinline__ uint32_t smem_u32(const void* p) {
    uint32_t a;
    asm("{ .reg .u64 t; cvta.to.shared.u64 t, %1; cvt.u32.u64 %0, t; }"
        : "=r"(a) : "l"(p));
    return a;
}
__device__ __forceinline__ void cp_async16(uint32_t dst, const void* src) {
    asm volatile("cp.async.cg.shared.global [%0], [%1], 16;" :: "r"(dst), "l"(src));
}
__device__ __forceinline__ void cp_async16_zero(uint32_t dst, const void* src) {
    asm volatile("cp.async.cg.shared.global [%0], [%1], 16, 0;" :: "r"(dst), "l"(src));
}
__device__ __forceinline__ void cp_commit() {
    asm volatile("cp.async.commit_group;");
}
template <int Npend>
__device__ __forceinline__ void cp_wait() {
    asm volatile("cp.async.wait_group %0;" :: "n"(Npend));
}
__device__ __forceinline__ void ldmatrix_x4(uint32_t* r, uint32_t addr) {
    asm volatile("ldmatrix.sync.aligned.m8n8.x4.shared.b16 {%0,%1,%2,%3}, [%4];"
        : "=r"(r[0]), "=r"(r[1]), "=r"(r[2]), "=r"(r[3]) : "r"(addr));
}
__device__ __forceinline__ void mma_f16(float& c0, float& c1, float& c2, float& c3,
                                        uint32_t a0, uint32_t a1, uint32_t a2, uint32_t a3,
                                        uint32_t b0, uint32_t b1) {
    asm volatile(
        "mma.sync.aligned.m16n8k16.row.col.f32.f16.f16.f32 "
        "{%0,%1,%2,%3}, {%4,%5,%6,%7}, {%8,%9}, {%0,%1,%2,%3};"
        : "+f"(c0), "+f"(c1), "+f"(c2), "+f"(c3)
        : "r"(a0), "r"(a1), "r"(a2), "r"(a3), "r"(b0), "r"(b1));
}
__device__ __forceinline__ float tanh_fast(float x) {
    float r;
    asm("tanh.approx.f32 %0, %1;" : "=f"(r) : "f"(x));
    return r;
}
__device__ __forceinline__ void griddep_wait() {
    asm volatile("griddepcontrol.wait;" ::: "memory");
}
__device__ __forceinline__ void griddep_launch_dependents() {
    asm volatile("griddepcontrol.launch_dependents;" ::: "memory");
}

// ===========================================================================
// Repacks / transpose / init
// ===========================================================================
__global__ void repack_conv2(const float* __restrict__ conv_w) {
    int idx = blockIdx.x * blockDim.x + threadIdx.x;
    if (idx >= M4_ * KC_) return;
    int mp = idx / KC_;
    int k  = idx - mp * KC_;
    int y  = mp >> 7;
    int g  = (mp >> 5) & 3;
    int cl = mp & 31;
    int m  = g * H_ + y * 32 + cl;
    int tap = (k >= H_) ? 1 : 0;
    int i = k - tap * H_;
    g_Wc2[idx] = __float2half_rn(conv_w[m * (H_ * 2) + i * 2 + tap]);
}

__global__ void repack_inj2(const float* __restrict__ inject_w,
                            const float* __restrict__ inject_b,
                            const float* __restrict__ conv_b) {
    int idx = blockIdx.x * blockDim.x + threadIdx.x;
    if (idx >= M4_ * KI_) return;
    int mp = idx / KI_;
    int k  = idx - mp * KI_;
    int y  = mp >> 7;
    int g  = (mp >> 5) & 3;
    int cl = mp & 31;
    int m  = g * H_ + y * 32 + cl;
    int tap = (k >= NINP_) ? 1 : 0;
    int i = k - tap * NINP_;
    g_Wi2[idx] = __float2half_rn(inject_w[m * (NINP_ * 2) + i * 2 + tap]);
    if (k == 0) g_bias[mp] = inject_b[m] + conv_b[m];
}

__global__ void transpose_x(const float* __restrict__ X) {
    __shared__ float tile[32][33];
    int b  = blockIdx.z;
    int i0 = blockIdx.y * 32;
    int t0 = blockIdx.x * 32;
    int tx = threadIdx.x, ty = threadIdx.y;
#pragma unroll
    for (int j = 0; j < 32; j += 8)
        tile[ty + j][tx] = X[(size_t)(b * NINP_ + i0 + ty + j) * L_ + t0 + tx];
    __syncthreads();
#pragma unroll
    for (int j = 0; j < 32; j += 8)
        g_Xt[(size_t)(b * L_ + t0 + ty + j) * NINP_ + i0 + tx] =
            __float2half_rn(tile[tx][ty + j]);
}

__global__ void init_z0h(const float* __restrict__ z0) {
    int idx = blockIdx.x * blockDim.x + threadIdx.x;
    if (idx < B_ * H_) {
        int b = idx / H_, ch = idx - b * H_;
        g_z0h[idx] = __float2half_rn(z0[b * (2 * H_) + ch]);
    }
}

// fp32 GEMV: pre0[b][mp] = sum_i conv_w[m][i][0] * z0h[b][i]  (interleaved store)
__global__ void gemv_pre0(const float* __restrict__ conv_w,
                          const float* __restrict__ z0) {
    int w = (blockIdx.x * blockDim.x + threadIdx.x) >> 5;
    int lane = threadIdx.x & 31;
    if (w >= M4_ * B_) return;
    int m = w >> 2;
    int b = w & 3;
    float s = 0.0f;
    for (int i = lane; i < H_; i += 32)
        s += conv_w[(size_t)m * (2 * H_) + 2 * i] * z0[b * (2 * H_) + i];
#pragma unroll
    for (int o = 16; o; o >>= 1) s += __shfl_xor_sync(0xFFFFFFFFu, s, o);
    if (lane == 0) {
        int g = m / H_;
        int r = m - g * H_;
        int mp = (r >> 5) * 128 + g * 32 + (r & 31);
        g_pre0[b * M4_ + mp] = s;
    }
}

// ===========================================================================
// Fused GEMM (fp16 mma.sync + ldmatrix), 128(n)x128(m), BK=64, 3 stages,
// 2 CTAs/SM, full PDL: weight prologue before griddepcontrol.wait,
// launch_dependents fired right after the mainloop.
// ===========================================================================
#define BK      64
#define KS      72                       // padded row stride (halfs), 144B
#define STG_A   (128 * KS)
#define STG_SZ  (2 * 128 * KS)
#define NSTAGE  3
#define SMEM_BYTES (NSTAGE * STG_SZ * 2) // 110592
// epilogue smem (per 64-row pass)
#define USS     136                      // us_s row stride in halfs
#define PS      136                      // pre_s row stride in floats
#define PRE_OFF 4352                     // float offset of pre_s

template <int KTOT, bool INJECT>
__global__ __launch_bounds__(256, 2)
void gemm_fused(const float* __restrict__ z0, float* __restrict__ out,
                int rd, int last) {
    extern __shared__ __half smh[];
    constexpr int KHALF = KTOT / 2;
    constexpr int NKT = KTOT / BK;

    const __half* __restrict__ Asrc = INJECT ? g_Xt : (rd ? g_hh1 : g_hh0);
    const __half* __restrict__ Bw   = INJECT ? g_Wi2 : g_Wc2;

    const int tid  = threadIdx.x;
    const int wid  = tid >> 5;
    const int lane = tid & 31;
    const int grp  = lane >> 2;
    const int qid  = lane & 3;
    const int n0   = blockIdx.x * 128;
    const int m0   = blockIdx.y * 128;

    const int wn = (wid >> 2) * 64;
    const int wm = (wid & 3) * 32;

    const uint32_t sbase = smem_u32(smh);
    const int lrow = lane & 15;
    const int lcol = (lane >> 4) << 3;

#define LOAD_STAGE_B(S, K0)                                                      \
    do {                                                                         \
        const int _k0 = (K0);                                                    \
        const uint32_t boff = ((S) % NSTAGE) * STG_SZ + STG_A;                   \
        _Pragma("unroll")                                                        \
        for (int j = 0; j < 4; j++) {                                            \
            int idx = tid + j * 256;                                             \
            int r  = idx >> 3;                                                   \
            int c8 = idx & 7;                                                    \
            int kk = _k0 + c8 * 8;                                               \
            uint32_t dst = sbase + (boff + r * KS + c8 * 8) * 2;                 \
            cp_async16(dst, Bw + (size_t)(m0 + r) * KTOT + kk);                  \
        }                                                                        \
        cp_commit();                                                             \
    } while (0)

#define LOAD_STAGE_A(S, K0)                                                      \
    do {                                                                         \
        const int _k0 = (K0);                                                    \
        const uint32_t aoff = ((S) % NSTAGE) * STG_SZ;                           \
        _Pragma("unroll")                                                        \
        for (int j = 0; j < 4; j++) {                                            \
            int idx = tid + j * 256;                                             \
            int r  = idx >> 3;                                                   \
            int c8 = idx & 7;                                                    \
            int kk = _k0 + c8 * 8;                                               \
            int n = n0 + r;                                                      \
            int t = n & (L_ - 1);                                                \
            int b = n >> 10;                                                     \
            uint32_t dst = sbase + (aoff + r * KS + c8 * 8) * 2;                 \
            if (kk < KHALF) {                                                    \
                if (t == 0) {                                                    \
                    if (INJECT) cp_async16_zero(dst, Asrc);                      \
                    else cp_async16(dst, g_z0h + b * H_ + kk);                   \
                } else {                                                         \
                    cp_async16(dst, Asrc + (size_t)(n - 1) * KHALF + kk);        \
                }                                                                \
            } else {                                                             \
                cp_async16(dst, Asrc + (size_t)n * KHALF + (kk - KHALF));        \
            }                                                                    \
        }                                                                        \
        cp_commit();                                                             \
    } while (0)

#define LOAD_STAGE(S, K0)                                                        \
    do {                                                                         \
        const int _k0 = (K0);                                                    \
        const uint32_t aoff = ((S) % NSTAGE) * STG_SZ;                           \
        const uint32_t boff = aoff + STG_A;                                      \
        _Pragma("unroll")                                                        \
        for (int j = 0; j < 4; j++) {                                            \
            int idx = tid + j * 256;                                             \
            int r  = idx >> 3;                                                   \
            int c8 = idx & 7;                                                    \
            int kk = _k0 + c8 * 8;                                               \
            {                                                                    \
                int n = n0 + r;                                                  \
                int t = n & (L_ - 1);                                            \
                int b = n >> 10;                                                 \
                uint32_t dst = sbase + (aoff + r * KS + c8 * 8) * 2;             \
                if (kk < KHALF) {                                                \
                    if (t == 0) {                                                \
                        if (INJECT) cp_async16_zero(dst, Asrc);                  \
                        else cp_async16(dst, g_z0h + b * H_ + kk);               \
                    } else {                                                     \
                        cp_async16(dst, Asrc + (size_t)(n - 1) * KHALF + kk);    \
                    }                                                            \
                } else {                                                         \
                    cp_async16(dst, Asrc + (size_t)n * KHALF + (kk - KHALF));    \
                }                                                                \
            }                                                                    \
            {                                                                    \
                uint32_t dst = sbase + (boff + r * KS + c8 * 8) * 2;             \
                cp_async16(dst, Bw + (size_t)(m0 + r) * KTOT + kk);              \
            }                                                                    \
        }                                                                        \
        cp_commit();                                                             \
    } while (0)

    // prologue: weights first (independent of predecessor kernel), then wait,
    // then the h/x-dependent A tiles.
    LOAD_STAGE_B(0, 0);
    LOAD_STAGE_B(1, BK);
    griddep_wait();
    LOAD_STAGE_A(0, 0);
    LOAD_STAGE_A(1, BK);

    float acc[4][4][4];
#pragma unroll
    for (int i = 0; i < 4; i++)
#pragma unroll
        for (int j = 0; j < 4; j++)
#pragma unroll
            for (int e = 0; e < 4; e++) acc[i][j][e] = 0.0f;

#pragma unroll 1
    for (int kt = 0; kt < NKT; kt++) {
        cp_wait<NSTAGE - 2>();
        __syncthreads();

        const int sf = kt + NSTAGE - 1;
        if (sf < NKT) LOAD_STAGE(sf, sf * BK);
        else cp_commit();

        const uint32_t a_base = sbase + (uint32_t)((kt % NSTAGE) * STG_SZ) * 2;
        const uint32_t b_base = a_base + STG_A * 2;

#pragma unroll
        for (int ks = 0; ks < BK; ks += 16) {
            uint32_t af[4][4];
            uint32_t bf[2][4];
#pragma unroll
            for (int fi = 0; fi < 4; fi++) {
                uint32_t addr = a_base +
                    (uint32_t)((wn + fi * 16 + lrow) * KS + ks + lcol) * 2;
                ldmatrix_x4(af[fi], addr);
            }
#pragma unroll
            for (int fh = 0; fh < 2; fh++) {
                uint32_t addr = b_base +
                    (uint32_t)((wm + fh * 16 + lrow) * KS + ks + lcol) * 2;
                ldmatrix_x4(bf[fh], addr);
            }
#pragma unroll
            for (int fi = 0; fi < 4; fi++) {
#pragma unroll
                for (int fh = 0; fh < 2; fh++) {
#pragma unroll
                    for (int s2 = 0; s2 < 2; s2++) {
                        int fj = fh * 2 + s2;
                        mma_f16(acc[fi][fj][0], acc[fi][fj][1],
                                acc[fi][fj][2], acc[fi][fj][3],
                                af[fi][0], af[fi][1], af[fi][2], af[fi][3],
                                bf[fh][s2], bf[fh][s2 + 2]);
                    }
                }
            }
        }
    }

    // Fire the PDL trigger: mainloop done, successor may launch and prefetch
    // its weight tiles while this kernel runs its epilogue.
    griddep_launch_dependents();

    // ---------------- epilogue ----------------
    __half* us_s  = smh;
    float*  pre_s = (float*)smh + PRE_OFF;
    const int chbase = blockIdx.y * 32;
    const int q  = tid & 7;
    const int nl = tid >> 3;

    if (INJECT) {
#pragma unroll
        for (int fi = 0; fi < 4; fi++) {
#pragma unroll
            for (int fj = 0; fj < 4; fj++) {
                int n1  = n0 + wn + fi * 16 + grp;
                int col = wm + fj * 8 + qid * 2;
                float b0 = g_bias[m0 + col], b1 = g_bias[m0 + col + 1];
                acc[fi][fj][0] += b0; acc[fi][fj][1] += b1;
                acc[fi][fj][2] += b0; acc[fi][fj][3] += b1;
                *(__half2*)(g_us2 + (size_t)n1 * M4_ + m0 + col) =
                    __floats2half2_rn(acc[fi][fj][0], acc[fi][fj][1]);
                *(__half2*)(g_us2 + (size_t)(n1 + 8) * M4_ + m0 + col) =
                    __floats2half2_rn(acc[fi][fj][2], acc[fi][fj][3]);
            }
        }
        // fused layer-0 gating
#pragma unroll
        for (int p = 0; p < 2; p++) {
            __syncthreads();
            if ((wid >> 2) == p) {
#pragma unroll
                for (int fi = 0; fi < 4; fi++) {
#pragma unroll
                    for (int fj = 0; fj < 4; fj++) {
                        int r0   = fi * 16 + grp;
                        int cidx = wm + fj * 8 + qid * 2;
                        *(float2*)&pre_s[r0 * PS + cidx] =
                            make_float2(acc[fi][fj][0], acc[fi][fj][1]);
                        *(float2*)&pre_s[(r0 + 8) * PS + cidx] =
                            make_float2(acc[fi][fj][2], acc[fi][fj][3]);
                    }
                }
            }
            __syncthreads();
#pragma unroll
            for (int it = 0; it < 2; it++) {
                int row = nl + it * 32;
                int n = n0 + p * 64 + row;
                int t = n & (L_ - 1);
                int b = n >> 10;
                int ch = chbase + q * 4;

                float pi[4], po[4], pg[4], pf[4], cprev[4];
#pragma unroll
                for (int e = 0; e < 4; e++) {
                    pi[e] = pre_s[row * PS + 0 * 32 + q * 4 + e];
                    po[e] = pre_s[row * PS + 1 * 32 + q * 4 + e];
                    pg[e] = pre_s[row * PS + 2 * 32 + q * 4 + e];
                    pf[e] = pre_s[row * PS + 3 * 32 + q * 4 + e];
                    cprev[e] = 0.0f;
                }
                if (t == 0) {
#pragma unroll
                    for (int e = 0; e < 4; e++) {
                        pi[e] += g_pre0[b * M4_ + m0 + 0 * 32 + q * 4 + e];
                        po[e] += g_pre0[b * M4_ + m0 + 1 * 32 + q * 4 + e];
                        pg[e] += g_pre0[b * M4_ + m0 + 2 * 32 + q * 4 + e];
                        pf[e] += g_pre0[b * M4_ + m0 + 3 * 32 + q * 4 + e];
                        cprev[e] = z0[b * (2 * H_) + H_ + ch + e];
                    }
                }
                __half hh[4], cc[4];
#pragma unroll
                for (int e = 0; e < 4; e++) {
                    float si = 1.0f / (1.0f + __expf(-pi[e]));
                    float so = 1.0f / (1.0f + __expf(-po[e]));
                    float sf = 1.0f / (1.0f + __expf(-pf[e]));
                    float tg = tanh_fast(pg[e]);
                    float c = sf * cprev[e] + si * tg;
                    float h = so * tanh_fast(c);
                    hh[e] = __float2half_rn(h);
                    cc[e] = __float2half_rn(c);
                }
                *(__half2*)(g_hh1 + (size_t)n * H_ + ch)     = __halves2half2(hh[0], hh[1]);
                *(__half2*)(g_hh1 + (size_t)n * H_ + ch + 2) = __halves2half2(hh[2], hh[3]);
                *(__half2*)(g_ch1 + (size_t)n * H_ + ch)     = __halves2half2(cc[0], cc[1]);
                *(__half2*)(g_ch1 + (size_t)n * H_ + ch + 2) = __halves2half2(cc[2], cc[3]);
            }
        }
        return;
    }

    // ---- layer epilogue: 2 passes of 64 n-rows ----
    const __half* __restrict__ cpb = rd ? g_ch1 : g_ch0;
    __half* __restrict__ cn  = rd ? g_ch0 : g_ch1;
    __half* __restrict__ hhn = rd ? g_hh0 : g_hh1;

#pragma unroll
    for (int p = 0; p < 2; p++) {
        __syncthreads();

#pragma unroll
        for (int j = 0; j < 4; j++) {
            int id = tid + j * 256;
            int row = id >> 4;
            int c   = id & 15;
            int n = n0 + p * 64 + row;
            cp_async16(sbase + (uint32_t)(row * USS + c * 8) * 2,
                       g_us2 + (size_t)n * M4_ + m0 + c * 8);
        }
        cp_commit();

        if ((wid >> 2) == p) {
#pragma unroll
            for (int fi = 0; fi < 4; fi++) {
#pragma unroll
                for (int fj = 0; fj < 4; fj++) {
                    int r0   = fi * 16 + grp;
                    int cidx = wm + fj * 8 + qid * 2;
                    *(float2*)&pre_s[r0 * PS + cidx] =
                        make_float2(acc[fi][fj][0], acc[fi][fj][1]);
                    *(float2*)&pre_s[(r0 + 8) * PS + cidx] =
                        make_float2(acc[fi][fj][2], acc[fi][fj][3]);
                }
            }
        }
        cp_wait<0>();
        __syncthreads();

#pragma unroll
        for (int it = 0; it < 2; it++) {
            int row = nl + it * 32;
            int n = n0 + p * 64 + row;
            int t = n & (L_ - 1);
            int b = n >> 10;
            int ch = chbase + q * 4;

            float4 pi4 = *(const float4*)&pre_s[row * PS + 0 * 32 + q * 4];
            float4 po4 = *(const float4*)&pre_s[row * PS + 1 * 32 + q * 4];
            float4 pg4 = *(const float4*)&pre_s[row * PS + 2 * 32 + q * 4];
            float4 pf4 = *(const float4*)&pre_s[row * PS + 3 * 32 + q * 4];

            const __half* ur = us_s + row * USS + q * 4;
            float2 uiA = __half22float2(*(const __half2*)(ur + 0 * 32));
            float2 uiB = __half22float2(*(const __half2*)(ur + 0 * 32 + 2));
            float2 uoA = __half22float2(*(const __half2*)(ur + 1 * 32));
            float2 uoB = __half22float2(*(const __half2*)(ur + 1 * 32 + 2));
            float2 ugA = __half22float2(*(const __half2*)(ur + 2 * 32));
            float2 ugB = __half22float2(*(const __half2*)(ur + 2 * 32 + 2));
            float2 ufA = __half22float2(*(const __half2*)(ur + 3 * 32));
            float2 ufB = __half22float2(*(const __half2*)(ur + 3 * 32 + 2));
            float ui[4] = {uiA.x, uiA.y, uiB.x, uiB.y};
            float uo[4] = {uoA.x, uoA.y, uoB.x, uoB.y};
            float ug[4] = {ugA.x, ugA.y, ugB.x, ugB.y};
            float uf[4] = {ufA.x, ufA.y, ufB.x, ufB.y};

            float cpl[4];
            if (t == 0) {
                float4 zc = *(const float4*)(z0 + b * (2 * H_) + H_ + ch);
                cpl[0] = zc.x; cpl[1] = zc.y; cpl[2] = zc.z; cpl[3] = zc.w;
            } else {
                float2 cA = __half22float2(*(const __half2*)(cpb + (size_t)(n - 1) * H_ + ch));
                float2 cB = __half22float2(*(const __half2*)(cpb + (size_t)(n - 1) * H_ + ch + 2));
                cpl[0] = cA.x; cpl[1] = cA.y; cpl[2] = cB.x; cpl[3] = cB.y;
            }

            const float* pip = (const float*)&pi4;
            const float* pop = (const float*)&po4;
            const float* pgp = (const float*)&pg4;
            const float* pfp = (const float*)&pf4;

            float4 hv, cv;
            float* hvp = (float*)&hv;
            float* cvp = (float*)&cv;
#pragma unroll
            for (int e = 0; e < 4; e++) {
                float pi = pip[e] + ui[e];
                float po = pop[e] + uo[e];
                float pg = pgp[e] + ug[e];
                float pf = pfp[e] + uf[e];
                float si = 1.0f / (1.0f + __expf(-pi));
                float so = 1.0f / (1.0f + __expf(-po));
                float sf = 1.0f / (1.0f + __expf(-pf));
                float tg = tanh_fast(pg);
                float c = sf * cpl[e] + si * tg;
                float h = so * tanh_fast(c);
                hvp[e] = h;
                cvp[e] = c;
            }
            if (last) {
                if (chbase >= H_ - NOUT_) {
                    *(float4*)(out + (size_t)n * NOUT_ + (ch - (H_ - NOUT_))) = hv;
                }
                if (t == L_ - 1) {
                    const size_t tot = (size_t)B_ * L_ * NOUT_;
                    *(float4*)(out + tot + b * (2 * H_) + ch)      = hv;
                    *(float4*)(out + tot + b * (2 * H_) + H_ + ch) = cv;
                }
            } else {
                __half2 h01 = __floats2half2_rn(hvp[0], hvp[1]);
                __half2 h23 = __floats2half2_rn(hvp[2], hvp[3]);
                __half2 c01 = __floats2half2_rn(cvp[0], cvp[1]);
                __half2 c23 = __floats2half2_rn(cvp[2], cvp[3]);
                *(__half2*)(hhn + (size_t)n * H_ + ch)     = h01;
                *(__half2*)(hhn + (size_t)n * H_ + ch + 2) = h23;
                *(__half2*)(cn + (size_t)n * H_ + ch)      = c01;
                *(__half2*)(cn + (size_t)n * H_ + ch + 2)  = c23;
            }
        }
    }
#undef LOAD_STAGE
#undef LOAD_STAGE_A
#undef LOAD_STAGE_B
}

// ===========================================================================
// Host-side PDL launch with plain-launch fallback
// ===========================================================================
template <int KTOT, bool INJECT>
static void launch_gemm_pdl(const float* z0, float* out, int rd, int last) {
    cudaLaunchConfig_t cfg = {};
    cfg.gridDim = dim3(N_ / 128, M4_ / 128);
    cfg.blockDim = dim3(256);
    cfg.dynamicSmemBytes = SMEM_BYTES;
    cfg.stream = 0;
    cudaLaunchAttribute attr[1];
    attr[0].id = cudaLaunchAttributeProgrammaticStreamSerialization;
    attr[0].val.programmaticStreamSerializationAllowed = 1;
    cfg.attrs = attr;
    cfg.numAttrs = 1;
    cudaError_t e = cudaLaunchKernelEx(&cfg, gemm_fused<KTOT, INJECT>,
                                       z0, out, rd, last);
    if (e != cudaSuccess) {
        cudaGetLastError();  // clear
        gemm_fused<KTOT, INJECT>
            <<<dim3(N_ / 128, M4_ / 128), 256, SMEM_BYTES>>>(z0, out, rd, last);
    }
}

// ===========================================================================
extern "C" void kernel_launch(void* const* d_in, const int* in_sizes, int n_in,
                              void* d_out, int out_size) {
    const float* X        = (const float*)d_in[0];
    const float* z0       = (const float*)d_in[1];
    const float* inject_w = (const float*)d_in[2];
    const float* inject_b = (const float*)d_in[3];
    const float* conv_w   = (const float*)d_in[4];
    const float* conv_b   = (const float*)d_in[5];
    float* out = (float*)d_out;

    cudaFuncSetAttribute(gemm_fused<KI_, true>,
                         cudaFuncAttributeMaxDynamicSharedMemorySize, SMEM_BYTES);
    cudaFuncSetAttribute(gemm_fused<KC_, false>,
                         cudaFuncAttributeMaxDynamicSharedMemorySize, SMEM_BYTES);

    repack_conv2<<<(M4_ * KC_ + 255) / 256, 256>>>(conv_w);
    repack_inj2<<<(M4_ * KI_ + 255) / 256, 256>>>(inject_w, inject_b, conv_b);
    transpose_x<<<dim3(L_ / 32, NINP_ / 32, B_), dim3(32, 8)>>>(X);
    init_z0h<<<(B_ * H_ + 255) / 256, 256>>>(z0);
    gemv_pre0<<<(M4_ * B_ * 32 + 255) / 256, 256>>>(conv_w, z0);

    // inject GEMM -> us (fp16, interleaved) + fused layer-0 gating -> hh1/ch1
    launch_gemm_pdl<KI_, true>(z0, out, 0, 0);

    // layers 1..9
    for (int l = 1; l < NLAYER_; l++)
        launch_gemm_pdl<KC_, false>(z0, out, l & 1, l == NLAYER_ - 1);
}

// round 14
// speedup vs baseline: 10.2049x; 1.0946x over previous
#include <cuda_runtime.h>
#include <cuda_fp16.h>
#include <math.h>
#include <cstdint>

// Problem constants
#define B_    4
#define H_    768
#define L_    1024
#define N_    4096          // B_*L_
#define M4_   3072          // 4*H_
#define NINP_ 512
#define KC_   1536          // conv K  ([h(t-1); h(t)])
#define KI_   1024          // inject K ([x(t-1); x(t)])
#define NOUT_ 256
#define NLAYER_ 10

#define NBLK_N 32           // n-tiles per layer
#define NBLK_M 24           // m-tiles per layer
#define ITEMS_PER_LAYER (NBLK_N * NBLK_M)     // 768
#define TOTAL_ITEMS (NLAYER_ * ITEMS_PER_LAYER) // 7680
#define GRID_PERSIST 296    // 2 CTAs/SM x 148 SMs

// Scratch (device globals; no allocation allowed)
// us layout: [n][mp], mp = y*128 + g*32 + cl  (gate-interleaved, y = ch/32)
__device__ __half g_us2[(size_t)N_ * M4_];
__device__ __half g_ch0[(size_t)N_ * H_];  // c fp16 inter-layer
__device__ __half g_ch1[(size_t)N_ * H_];
__device__ __half g_hh0[(size_t)N_ * H_];  // h fp16 (GEMM A input)
__device__ __half g_hh1[(size_t)N_ * H_];
__device__ __half g_Wc2[(size_t)M4_ * KC_]; // conv W fp16, gate-interleaved rows
__device__ __half g_Wi2[(size_t)M4_ * KI_]; // inject W fp16, gate-interleaved rows
__device__ __half g_Xt[(size_t)N_ * NINP_]; // X fp16, time-major [n][i]
__device__ __half g_z0h[B_ * H_];           // z0 h-part fp16
__device__ float  g_bias[M4_];              // inject_b + conv_b, interleaved index
__device__ float  g_pre0[B_ * M4_];         // layer-0 t==0 corr: W0 @ z0h, interleaved
__device__ unsigned g_ticket;               // work-item ticket
__device__ int    g_cnt[NLAYER_][NBLK_N];   // per-(layer,nblock) completion counts

// ===========================================================================
// Helpers
// ===========================================================================
__device__ __forceinline__ uint32_t smem_u32(const void* p) {
    uint32_t a;
    asm("{ .reg .u64 t; cvta.to.shared.u64 t, %1; cvt.u32.u64 %0, t; }"
        : "=r"(a) : "l"(p));
    return a;
}
__device__ __forceinline__ void cp_async16(uint32_t dst, const void* src) {
    asm volatile("cp.async.cg.shared.global [%0], [%1], 16;" :: "r"(dst), "l"(src));
}
__device__ __forceinline__ void cp_async16_zero(uint32_t dst, const void* src) {
    asm volatile("cp.async.cg.shared.global [%0], [%1], 16, 0;" :: "r"(dst), "l"(src));
}
__device__ __forceinline__ void cp_commit() {
    asm volatile("cp.async.commit_group;");
}
template <int Npend>
__device__ __forceinline__ void cp_wait() {
    asm volatile("cp.async.wait_group %0;" :: "n"(Npend));
}
__device__ __forceinline__ void ldmatrix_x4(uint32_t* r, uint32_t addr) {
    asm volatile("ldmatrix.sync.aligned.m8n8.x4.shared.b16 {%0,%1,%2,%3}, [%4];"
        : "=r"(r[0]), "=r"(r[1]), "=r"(r[2]), "=r"(r[3]) : "r"(addr));
}
__device__ __forceinline__ void mma_f16(float& c0, float& c1, float& c2, float& c3,
                                        uint32_t a0, uint32_t a1, uint32_t a2, uint32_t a3,
                                        uint32_t b0, uint32_t b1) {
    asm volatile(
        "mma.sync.aligned.m16n8k16.row.col.f32.f16.f16.f32 "
        "{%0,%1,%2,%3}, {%4,%5,%6,%7}, {%8,%9}, {%0,%1,%2,%3};"
        : "+f"(c0), "+f"(c1), "+f"(c2), "+f"(c3)
        : "r"(a0), "r"(a1), "r"(a2), "r"(a3), "r"(b0), "r"(b1));
}
__device__ __forceinline__ float tanh_fast(float x) {
    float r;
    asm("tanh.approx.f32 %0, %1;" : "=f"(r) : "f"(x));
    return r;
}
__device__ __forceinline__ int ld_acquire(const int* p) {
    int v;
    asm volatile("ld.acquire.gpu.global.s32 %0, [%1];" : "=r"(v) : "l"(p) : "memory");
    return v;
}

// ===========================================================================
// Repacks / transpose / init
// ===========================================================================
__global__ void repack_conv2(const float* __restrict__ conv_w) {
    int idx = blockIdx.x * blockDim.x + threadIdx.x;
    if (idx >= M4_ * KC_) return;
    int mp = idx / KC_;
    int k  = idx - mp * KC_;
    int y  = mp >> 7;
    int g  = (mp >> 5) & 3;
    int cl = mp & 31;
    int m  = g * H_ + y * 32 + cl;
    int tap = (k >= H_) ? 1 : 0;
    int i = k - tap * H_;
    g_Wc2[idx] = __float2half_rn(conv_w[m * (H_ * 2) + i * 2 + tap]);
}

__global__ void repack_inj2(const float* __restrict__ inject_w,
                            const float* __restrict__ inject_b,
                            const float* __restrict__ conv_b) {
    int idx = blockIdx.x * blockDim.x + threadIdx.x;
    if (idx >= M4_ * KI_) return;
    int mp = idx / KI_;
    int k  = idx - mp * KI_;
    int y  = mp >> 7;
    int g  = (mp >> 5) & 3;
    int cl = mp & 31;
    int m  = g * H_ + y * 32 + cl;
    int tap = (k >= NINP_) ? 1 : 0;
    int i = k - tap * NINP_;
    g_Wi2[idx] = __float2half_rn(inject_w[m * (NINP_ * 2) + i * 2 + tap]);
    if (k == 0) g_bias[mp] = inject_b[m] + conv_b[m];
}

__global__ void transpose_x(const float* __restrict__ X) {
    __shared__ float tile[32][33];
    int b  = blockIdx.z;
    int i0 = blockIdx.y * 32;
    int t0 = blockIdx.x * 32;
    int tx = threadIdx.x, ty = threadIdx.y;
#pragma unroll
    for (int j = 0; j < 32; j += 8)
        tile[ty + j][tx] = X[(size_t)(b * NINP_ + i0 + ty + j) * L_ + t0 + tx];
    __syncthreads();
#pragma unroll
    for (int j = 0; j < 32; j += 8)
        g_Xt[(size_t)(b * L_ + t0 + ty + j) * NINP_ + i0 + tx] =
            __float2half_rn(tile[tx][ty + j]);
}

__global__ void init_z0h(const float* __restrict__ z0) {
    int idx = blockIdx.x * blockDim.x + threadIdx.x;
    if (idx < B_ * H_) {
        int b = idx / H_, ch = idx - b * H_;
        g_z0h[idx] = __float2half_rn(z0[b * (2 * H_) + ch]);
    }
    // zero the sync state for this launch (deterministic across graph replays)
    if (idx == 0) g_ticket = 0;
    if (idx < NLAYER_ * NBLK_N) ((int*)g_cnt)[idx] = 0;
}

// fp32 GEMV: pre0[b][mp] = sum_i conv_w[m][i][0] * z0h[b][i]  (interleaved store)
__global__ void gemv_pre0(const float* __restrict__ conv_w,
                          const float* __restrict__ z0) {
    int w = (blockIdx.x * blockDim.x + threadIdx.x) >> 5;
    int lane = threadIdx.x & 31;
    if (w >= M4_ * B_) return;
    int m = w >> 2;
    int b = w & 3;
    float s = 0.0f;
    for (int i = lane; i < H_; i += 32)
        s += conv_w[(size_t)m * (2 * H_) + 2 * i] * z0[b * (2 * H_) + i];
#pragma unroll
    for (int o = 16; o; o >>= 1) s += __shfl_xor_sync(0xFFFFFFFFu, s, o);
    if (lane == 0) {
        int g = m / H_;
        int r = m - g * H_;
        int mp = (r >> 5) * 128 + g * 32 + (r & 31);
        g_pre0[b * M4_ + mp] = s;
    }
}

// ===========================================================================
// Persistent mega-kernel: all layers (inject = layer 0) in one launch.
// Work item w -> (l, iblk, mblk). Fine-grained dataflow sync via g_cnt.
// ===========================================================================
#define BK      64
#define KS      72                       // padded row stride (halfs), 144B
#define STG_A   (128 * KS)
#define STG_SZ  (2 * 128 * KS)
#define NSTAGE  3
#define SMEM_BYTES (NSTAGE * STG_SZ * 2) // 110592
#define USS     136                      // us_s row stride in halfs
#define PS      136                      // pre_s row stride in floats
#define PRE_OFF 4352                     // float offset of pre_s

__global__ __launch_bounds__(256, 2)
void gemm_mega(const float* __restrict__ z0, float* __restrict__ out) {
    extern __shared__ __half smh[];
    __shared__ unsigned sm_w;

    const int tid  = threadIdx.x;
    const int wid  = tid >> 5;
    const int lane = tid & 31;
    const int grp  = lane >> 2;
    const int qid  = lane & 3;
    const int wn = (wid >> 2) * 64;
    const int wm = (wid & 3) * 32;
    const uint32_t sbase = smem_u32(smh);
    const int lrow = lane & 15;
    const int lcol = (lane >> 4) << 3;
    const int q  = tid & 7;
    const int nl = tid >> 3;

    for (;;) {
        if (tid == 0) sm_w = atomicAdd(&g_ticket, 1u);
        __syncthreads();
        const unsigned w = sm_w;
        if (w >= TOTAL_ITEMS) return;

        const int l    = w / ITEMS_PER_LAYER;
        const int r_   = w - l * ITEMS_PER_LAYER;
        const int iblk = r_ / NBLK_M;
        const int mblk = r_ - iblk * NBLK_M;
        const int n0 = iblk * 128;
        const int m0 = mblk * 128;
        const bool inj  = (l == 0);
        const bool last = (l == NLAYER_ - 1);
        const int  rd   = l & 1;

        const __half* __restrict__ Asrc = inj ? g_Xt : (rd ? g_hh1 : g_hh0);
        const __half* __restrict__ Bw   = inj ? g_Wi2 : g_Wc2;
        const int KTOT  = inj ? KI_ : KC_;
        const int KHALF = inj ? NINP_ : H_;
        const int NKT   = KTOT / BK;

#define LOAD_STAGE_B(S, K0)                                                      \
    do {                                                                         \
        const int _k0 = (K0);                                                    \
        const uint32_t boff = ((S) % NSTAGE) * STG_SZ + STG_A;                   \
        _Pragma("unroll")                                                        \
        for (int j = 0; j < 4; j++) {                                            \
            int idx = tid + j * 256;                                             \
            int r  = idx >> 3;                                                   \
            int c8 = idx & 7;                                                    \
            int kk = _k0 + c8 * 8;                                               \
            uint32_t dst = sbase + (boff + r * KS + c8 * 8) * 2;                 \
            cp_async16(dst, Bw + (size_t)(m0 + r) * KTOT + kk);                  \
        }                                                                        \
        cp_commit();                                                             \
    } while (0)

#define LOAD_STAGE_A(S, K0)                                                      \
    do {                                                                         \
        const int _k0 = (K0);                                                    \
        const uint32_t aoff = ((S) % NSTAGE) * STG_SZ;                           \
        _Pragma("unroll")                                                        \
        for (int j = 0; j < 4; j++) {                                            \
            int idx = tid + j * 256;                                             \
            int r  = idx >> 3;                                                   \
            int c8 = idx & 7;                                                    \
            int kk = _k0 + c8 * 8;                                               \
            int n = n0 + r;                                                      \
            int t = n & (L_ - 1);                                                \
            int b = n >> 10;                                                     \
            uint32_t dst = sbase + (aoff + r * KS + c8 * 8) * 2;                 \
            if (kk < KHALF) {                                                    \
                if (t == 0) {                                                    \
                    if (inj) cp_async16_zero(dst, Asrc);                         \
                    else cp_async16(dst, g_z0h + b * H_ + kk);                   \
                } else {                                                         \
                    cp_async16(dst, Asrc + (size_t)(n - 1) * KHALF + kk);        \
                }                                                                \
            } else {                                                             \
                cp_async16(dst, Asrc + (size_t)n * KHALF + (kk - KHALF));        \
            }                                                                    \
        }                                                                        \
        cp_commit();                                                             \
    } while (0)

#define LOAD_STAGE_AB(S, K0)                                                     \
    do {                                                                         \
        const int _k0 = (K0);                                                    \
        const uint32_t aoff = ((S) % NSTAGE) * STG_SZ;                           \
        const uint32_t boff = aoff + STG_A;                                      \
        _Pragma("unroll")                                                        \
        for (int j = 0; j < 4; j++) {                                            \
            int idx = tid + j * 256;                                             \
            int r  = idx >> 3;                                                   \
            int c8 = idx & 7;                                                    \
            int kk = _k0 + c8 * 8;                                               \
            {                                                                    \
                int n = n0 + r;                                                  \
                int t = n & (L_ - 1);                                            \
                int b = n >> 10;                                                 \
                uint32_t dst = sbase + (aoff + r * KS + c8 * 8) * 2;             \
                if (kk < KHALF) {                                                \
                    if (t == 0) {                                                \
                        if (inj) cp_async16_zero(dst, Asrc);                     \
                        else cp_async16(dst, g_z0h + b * H_ + kk);               \
                    } else {                                                     \
                        cp_async16(dst, Asrc + (size_t)(n - 1) * KHALF + kk);    \
                    }                                                            \
                } else {                                                         \
                    cp_async16(dst, Asrc + (size_t)n * KHALF + (kk - KHALF));    \
                }                                                                \
            }                                                                    \
            {                                                                    \
                uint32_t dst = sbase + (boff + r * KS + c8 * 8) * 2;             \
                cp_async16(dst, Bw + (size_t)(m0 + r) * KTOT + kk);              \
            }                                                                    \
        }                                                                        \
        cp_commit();                                                             \
    } while (0)

        // prefetch weight stages (no data dependency), then wait for producers
        LOAD_STAGE_B(0, 0);
        LOAD_STAGE_B(1, BK);
        if (tid == 0 && l > 0) {
            int lo = (iblk > 0) ? iblk - 1 : 0;
            int hi = (iblk < NBLK_N - 1) ? iblk + 1 : NBLK_N - 1;
            for (int ii = lo; ii <= hi; ii++)
                while (ld_acquire(&g_cnt[l - 1][ii]) < NBLK_M) __nanosleep(64);
        }
        __syncthreads();
        LOAD_STAGE_A(0, 0);
        LOAD_STAGE_A(1, BK);

        float acc[4][4][4];
#pragma unroll
        for (int i = 0; i < 4; i++)
#pragma unroll
            for (int j = 0; j < 4; j++)
#pragma unroll
                for (int e = 0; e < 4; e++) acc[i][j][e] = 0.0f;

#pragma unroll 1
        for (int kt = 0; kt < NKT; kt++) {
            cp_wait<NSTAGE - 2>();
            __syncthreads();

            const int sf = kt + NSTAGE - 1;
            if (sf < NKT) LOAD_STAGE_AB(sf, sf * BK);
            else cp_commit();

            const uint32_t a_base = sbase + (uint32_t)((kt % NSTAGE) * STG_SZ) * 2;
            const uint32_t b_base = a_base + STG_A * 2;

#pragma unroll
            for (int ks = 0; ks < BK; ks += 16) {
                uint32_t af[4][4];
                uint32_t bf[2][4];
#pragma unroll
                for (int fi = 0; fi < 4; fi++) {
                    uint32_t addr = a_base +
                        (uint32_t)((wn + fi * 16 + lrow) * KS + ks + lcol) * 2;
                    ldmatrix_x4(af[fi], addr);
                }
#pragma unroll
                for (int fh = 0; fh < 2; fh++) {
                    uint32_t addr = b_base +
                        (uint32_t)((wm + fh * 16 + lrow) * KS + ks + lcol) * 2;
                    ldmatrix_x4(bf[fh], addr);
                }
#pragma unroll
                for (int fi = 0; fi < 4; fi++) {
#pragma unroll
                    for (int fh = 0; fh < 2; fh++) {
#pragma unroll
                        for (int s2 = 0; s2 < 2; s2++) {
                            int fj = fh * 2 + s2;
                            mma_f16(acc[fi][fj][0], acc[fi][fj][1],
                                    acc[fi][fj][2], acc[fi][fj][3],
                                    af[fi][0], af[fi][1], af[fi][2], af[fi][3],
                                    bf[fh][s2], bf[fh][s2 + 2]);
                        }
                    }
                }
            }
        }

        // ---------------- epilogue ----------------
        __half* us_s  = smh;
        float*  pre_s = (float*)smh + PRE_OFF;
        const int chbase = mblk * 32;

        if (inj) {
#pragma unroll
            for (int fi = 0; fi < 4; fi++) {
#pragma unroll
                for (int fj = 0; fj < 4; fj++) {
                    int n1  = n0 + wn + fi * 16 + grp;
                    int col = wm + fj * 8 + qid * 2;
                    float b0 = g_bias[m0 + col], b1 = g_bias[m0 + col + 1];
                    acc[fi][fj][0] += b0; acc[fi][fj][1] += b1;
                    acc[fi][fj][2] += b0; acc[fi][fj][3] += b1;
                    *(__half2*)(g_us2 + (size_t)n1 * M4_ + m0 + col) =
                        __floats2half2_rn(acc[fi][fj][0], acc[fi][fj][1]);
                    *(__half2*)(g_us2 + (size_t)(n1 + 8) * M4_ + m0 + col) =
                        __floats2half2_rn(acc[fi][fj][2], acc[fi][fj][3]);
                }
            }
#pragma unroll
            for (int p = 0; p < 2; p++) {
                __syncthreads();
                if ((wid >> 2) == p) {
#pragma unroll
                    for (int fi = 0; fi < 4; fi++) {
#pragma unroll
                        for (int fj = 0; fj < 4; fj++) {
                            int r0   = fi * 16 + grp;
                            int cidx = wm + fj * 8 + qid * 2;
                            *(float2*)&pre_s[r0 * PS + cidx] =
                                make_float2(acc[fi][fj][0], acc[fi][fj][1]);
                            *(float2*)&pre_s[(r0 + 8) * PS + cidx] =
                                make_float2(acc[fi][fj][2], acc[fi][fj][3]);
                        }
                    }
                }
                __syncthreads();
#pragma unroll
                for (int it = 0; it < 2; it++) {
                    int row = nl + it * 32;
                    int n = n0 + p * 64 + row;
                    int t = n & (L_ - 1);
                    int b = n >> 10;
                    int ch = chbase + q * 4;

                    float pi[4], po[4], pg[4], pf[4], cprev[4];
#pragma unroll
                    for (int e = 0; e < 4; e++) {
                        pi[e] = pre_s[row * PS + 0 * 32 + q * 4 + e];
                        po[e] = pre_s[row * PS + 1 * 32 + q * 4 + e];
                        pg[e] = pre_s[row * PS + 2 * 32 + q * 4 + e];
                        pf[e] = pre_s[row * PS + 3 * 32 + q * 4 + e];
                        cprev[e] = 0.0f;
                    }
                    if (t == 0) {
#pragma unroll
                        for (int e = 0; e < 4; e++) {
                            pi[e] += g_pre0[b * M4_ + m0 + 0 * 32 + q * 4 + e];
                            po[e] += g_pre0[b * M4_ + m0 + 1 * 32 + q * 4 + e];
                            pg[e] += g_pre0[b * M4_ + m0 + 2 * 32 + q * 4 + e];
                            pf[e] += g_pre0[b * M4_ + m0 + 3 * 32 + q * 4 + e];
                            cprev[e] = z0[b * (2 * H_) + H_ + ch + e];
                        }
                    }
                    __half hh[4], cc[4];
#pragma unroll
                    for (int e = 0; e < 4; e++) {
                        float si = 1.0f / (1.0f + __expf(-pi[e]));
                        float so = 1.0f / (1.0f + __expf(-po[e]));
                        float sf = 1.0f / (1.0f + __expf(-pf[e]));
                        float tg = tanh_fast(pg[e]);
                        float c = sf * cprev[e] + si * tg;
                        float h = so * tanh_fast(c);
                        hh[e] = __float2half_rn(h);
                        cc[e] = __float2half_rn(c);
                    }
                    *(__half2*)(g_hh1 + (size_t)n * H_ + ch)     = __halves2half2(hh[0], hh[1]);
                    *(__half2*)(g_hh1 + (size_t)n * H_ + ch + 2) = __halves2half2(hh[2], hh[3]);
                    *(__half2*)(g_ch1 + (size_t)n * H_ + ch)     = __halves2half2(cc[0], cc[1]);
                    *(__half2*)(g_ch1 + (size_t)n * H_ + ch + 2) = __halves2half2(cc[2], cc[3]);
                }
            }
        } else {
            const __half* __restrict__ cpb = rd ? g_ch1 : g_ch0;
            __half* __restrict__ cn  = rd ? g_ch0 : g_ch1;
            __half* __restrict__ hhn = rd ? g_hh0 : g_hh1;

#pragma unroll
            for (int p = 0; p < 2; p++) {
                __syncthreads();
#pragma unroll
                for (int j = 0; j < 4; j++) {
                    int id = tid + j * 256;
                    int row = id >> 4;
                    int c   = id & 15;
                    int n = n0 + p * 64 + row;
                    cp_async16(sbase + (uint32_t)(row * USS + c * 8) * 2,
                               g_us2 + (size_t)n * M4_ + m0 + c * 8);
                }
                cp_commit();

                if ((wid >> 2) == p) {
#pragma unroll
                    for (int fi = 0; fi < 4; fi++) {
#pragma unroll
                        for (int fj = 0; fj < 4; fj++) {
                            int r0   = fi * 16 + grp;
                            int cidx = wm + fj * 8 + qid * 2;
                            *(float2*)&pre_s[r0 * PS + cidx] =
                                make_float2(acc[fi][fj][0], acc[fi][fj][1]);
                            *(float2*)&pre_s[(r0 + 8) * PS + cidx] =
                                make_float2(acc[fi][fj][2], acc[fi][fj][3]);
                        }
                    }
                }
                cp_wait<0>();
                __syncthreads();

#pragma unroll
                for (int it = 0; it < 2; it++) {
                    int row = nl + it * 32;
                    int n = n0 + p * 64 + row;
                    int t = n & (L_ - 1);
                    int b = n >> 10;
                    int ch = chbase + q * 4;

                    float4 pi4 = *(const float4*)&pre_s[row * PS + 0 * 32 + q * 4];
                    float4 po4 = *(const float4*)&pre_s[row * PS + 1 * 32 + q * 4];
                    float4 pg4 = *(const float4*)&pre_s[row * PS + 2 * 32 + q * 4];
                    float4 pf4 = *(const float4*)&pre_s[row * PS + 3 * 32 + q * 4];

                    const __half* ur = us_s + row * USS + q * 4;
                    float2 uiA = __half22float2(*(const __half2*)(ur + 0 * 32));
                    float2 uiB = __half22float2(*(const __half2*)(ur + 0 * 32 + 2));
                    float2 uoA = __half22float2(*(const __half2*)(ur + 1 * 32));
                    float2 uoB = __half22float2(*(const __half2*)(ur + 1 * 32 + 2));
                    float2 ugA = __half22float2(*(const __half2*)(ur + 2 * 32));
                    float2 ugB = __half22float2(*(const __half2*)(ur + 2 * 32 + 2));
                    float2 ufA = __half22float2(*(const __half2*)(ur + 3 * 32));
                    float2 ufB = __half22float2(*(const __half2*)(ur + 3 * 32 + 2));
                    float ui[4] = {uiA.x, uiA.y, uiB.x, uiB.y};
                    float uo[4] = {uoA.x, uoA.y, uoB.x, uoB.y};
                    float ug[4] = {ugA.x, ugA.y, ugB.x, ugB.y};
                    float uf[4] = {ufA.x, ufA.y, ufB.x, ufB.y};

                    float cpl[4];
                    if (t == 0) {
                        float4 zc = *(const float4*)(z0 + b * (2 * H_) + H_ + ch);
                        cpl[0] = zc.x; cpl[1] = zc.y; cpl[2] = zc.z; cpl[3] = zc.w;
                    } else {
                        float2 cA = __half22float2(*(const __half2*)(cpb + (size_t)(n - 1) * H_ + ch));
                        float2 cB = __half22float2(*(const __half2*)(cpb + (size_t)(n - 1) * H_ + ch + 2));
                        cpl[0] = cA.x; cpl[1] = cA.y; cpl[2] = cB.x; cpl[3] = cB.y;
                    }

                    const float* pip = (const float*)&pi4;
                    const float* pop = (const float*)&po4;
                    const float* pgp = (const float*)&pg4;
                    const float* pfp = (const float*)&pf4;

                    float4 hv, cv;
                    float* hvp = (float*)&hv;
                    float* cvp = (float*)&cv;
#pragma unroll
                    for (int e = 0; e < 4; e++) {
                        float pi = pip[e] + ui[e];
                        float po = pop[e] + uo[e];
                        float pg = pgp[e] + ug[e];
                        float pf = pfp[e] + uf[e];
                        float si = 1.0f / (1.0f + __expf(-pi));
                        float so = 1.0f / (1.0f + __expf(-po));
                        float sf = 1.0f / (1.0f + __expf(-pf));
                        float tg = tanh_fast(pg);
                        float c = sf * cpl[e] + si * tg;
                        float h = so * tanh_fast(c);
                        hvp[e] = h;
                        cvp[e] = c;
                    }
                    if (last) {
                        if (chbase >= H_ - NOUT_) {
                            *(float4*)(out + (size_t)n * NOUT_ + (ch - (H_ - NOUT_))) = hv;
                        }
                        if (t == L_ - 1) {
                            const size_t tot = (size_t)B_ * L_ * NOUT_;
                            *(float4*)(out + tot + b * (2 * H_) + ch)      = hv;
                            *(float4*)(out + tot + b * (2 * H_) + H_ + ch) = cv;
                        }
                    } else {
                        __half2 h01 = __floats2half2_rn(hvp[0], hvp[1]);
                        __half2 h23 = __floats2half2_rn(hvp[2], hvp[3]);
                        __half2 c01 = __floats2half2_rn(cvp[0], cvp[1]);
                        __half2 c23 = __floats2half2_rn(cvp[2], cvp[3]);
                        *(__half2*)(hhn + (size_t)n * H_ + ch)     = h01;
                        *(__half2*)(hhn + (size_t)n * H_ + ch + 2) = h23;
                        *(__half2*)(cn + (size_t)n * H_ + ch)      = c01;
                        *(__half2*)(cn + (size_t)n * H_ + ch + 2)  = c23;
                    }
                }
            }
        }

        // publish completion: all threads' writes -> bar -> fence -> count
        __syncthreads();
        if (tid == 0) {
            __threadfence();
            atomicAdd(&g_cnt[l][iblk], 1);
        }
#undef LOAD_STAGE_AB
#undef LOAD_STAGE_A
#undef LOAD_STAGE_B
    }
}

// ===========================================================================
extern "C" void kernel_launch(void* const* d_in, const int* in_sizes, int n_in,
                              void* d_out, int out_size) {
    const float* X        = (const float*)d_in[0];
    const float* z0       = (const float*)d_in[1];
    const float* inject_w = (const float*)d_in[2];
    const float* inject_b = (const float*)d_in[3];
    const float* conv_w   = (const float*)d_in[4];
    const float* conv_b   = (const float*)d_in[5];
    float* out = (float*)d_out;

    cudaFuncSetAttribute(gemm_mega,
                         cudaFuncAttributeMaxDynamicSharedMemorySize, SMEM_BYTES);

    repack_conv2<<<(M4_ * KC_ + 255) / 256, 256>>>(conv_w);
    repack_inj2<<<(M4_ * KI_ + 255) / 256, 256>>>(inject_w, inject_b, conv_b);
    transpose_x<<<dim3(L_ / 32, NINP_ / 32, B_), dim3(32, 8)>>>(X);
    init_z0h<<<(B_ * H_ + 255) / 256, 256>>>(z0);
    gemv_pre0<<<(M4_ * B_ * 32 + 255) / 256, 256>>>(conv_w, z0);

    gemm_mega<<<GRID_PERSIST, 256, SMEM_BYTES>>>(z0, out);
}